// round 3
// baseline (speedup 1.0000x reference)
#include <cuda_runtime.h>
#include <math.h>

// Problem constants (fixed by setup_inputs)
#define BB 2
#define NN 8192
#define CC 13

// Stage constants
// Ns:      8192, 2048, 512, 128, 32
// D:       64, 128, 256, 512, 512
// NSAMPLE: 36, 24, 24, 24, 24  (minus self -> 35, 23, 23, 23, 23)
// KNEIGH:  1, 4, 16, 64, 256

// ---------------- device scratch (no allocations allowed) ----------------
__device__ double   g_ce_sum[6];    // [0]=output CE sum, [1..5]=pred1..5 CE sums
__device__ double   g_bl_sum[5];    // boundary loss sums per stage
__device__ unsigned g_bl_cnt[5];    // boundary point counts per stage
__device__ int      g_hard[21824];  // hard labels; offsets 0,16384,20480,21504,21760

__global__ void zero_kernel() {
    int t = threadIdx.x;
    if (t < 6) g_ce_sum[t] = 0.0;
    if (t < 5) { g_bl_sum[t] = 0.0; g_bl_cnt[t] = 0u; }
}

// ---------------- cross entropy: one thread per row ----------------
__global__ void ce_kernel(const float* __restrict__ logits,
                          const int* __restrict__ labels,
                          const int* __restrict__ gidx,  // null -> labels[r] directly
                          int Ni, int slot) {
    int r = blockIdx.x * blockDim.x + threadIdx.x;
    int total = BB * Ni;
    if (r >= total) return;
    int b = r / Ni;
    int lab = gidx ? labels[b * NN + gidx[r]] : labels[r];
    const float* row = logits + (size_t)r * CC;
    float v[CC];
#pragma unroll
    for (int c = 0; c < CC; ++c) v[c] = row[c];
    float m = v[0];
#pragma unroll
    for (int c = 1; c < CC; ++c) m = fmaxf(m, v[c]);
    float s = 0.f;
#pragma unroll
    for (int c = 0; c < CC; ++c) s += expf(v[c] - m);
    float l = (m + logf(s)) - v[lab];
    atomicAdd(&g_ce_sum[slot], (double)l);
}

// ---------------- stage 0 hard labels: nearest full-res point is self ----------------
__global__ void hard_copy(const int* __restrict__ labels) {
    int r = blockIdx.x * blockDim.x + threadIdx.x;
    if (r < BB * NN) g_hard[r] = labels[r];
}

// ---------------- hard labels for stages 1..4 ----------------
// For each stage point: k nearest of the 8192 full-res points (expanded d2 formula),
// then argmax of label counts (first-index tie-break, matching jnp.argmax).
template <int K>
__global__ void hard_knn(const float* __restrict__ xyz_full,   // [B, NN, 3]
                         const float* __restrict__ coord,      // [B, Ni, 3]
                         const int* __restrict__ labels,       // [B, NN]
                         int Ni, int hard_off) {
    __shared__ float4 s[1024];
    int b = blockIdx.y;
    int qi = blockIdx.x * blockDim.x + threadIdx.x;
    bool active = qi < Ni;
    float qx = 0, qy = 0, qz = 0, q2 = 0;
    if (active) {
        const float* q = coord + ((size_t)b * Ni + qi) * 3;
        qx = q[0]; qy = q[1]; qz = q[2];
        q2 = qx * qx + qy * qy + qz * qz;
    }
    float kd[K]; int ki[K];
    for (int j = 0; j < K; ++j) { kd[j] = 3.0e38f; ki[j] = 0; }

    for (int t0 = 0; t0 < NN; t0 += 1024) {
        for (int t = threadIdx.x; t < 1024; t += blockDim.x) {
            const float* p = xyz_full + ((size_t)b * NN + t0 + t) * 3;
            float x = p[0], y = p[1], z = p[2];
            s[t] = make_float4(x, y, z, x * x + y * y + z * z);
        }
        __syncthreads();
        if (active) {
            for (int t = 0; t < 1024; ++t) {
                float4 c = s[t];
                float d2 = q2 - 2.f * (qx * c.x + qy * c.y + qz * c.z) + c.w;
                if (d2 < kd[K - 1]) {  // strict: keeps earlier index on ties (top_k semantics)
                    int j = K - 1;
                    while (j > 0 && kd[j - 1] > d2) { kd[j] = kd[j - 1]; ki[j] = ki[j - 1]; --j; }
                    kd[j] = d2; ki[j] = t0 + t;
                }
            }
        }
        __syncthreads();
    }
    if (active) {
        int cnt[CC];
#pragma unroll
        for (int c = 0; c < CC; ++c) cnt[c] = 0;
        for (int j = 0; j < K; ++j) cnt[labels[b * NN + ki[j]]]++;
        int best = 0, bc = cnt[0];
#pragma unroll
        for (int c = 1; c < CC; ++c) if (cnt[c] > bc) { bc = cnt[c]; best = c; }
        g_hard[hard_off + b * Ni + qi] = best;
    }
}

// ---------------- boundary loss per stage ----------------
// Per query: (ns-1)-NN within the stage's own coords (self excluded), then
// contrastive loss over feature-space distances, masked accumulation.
template <int NS1>
__global__ void stage_loss(const float* __restrict__ coord,   // [B, Ni, 3]
                           const float* __restrict__ feat,    // [B, Ni, D]
                           int Ni, int D, int hard_off, int stage) {
    __shared__ float4 s[1024];
    int b = blockIdx.y;
    int qi = blockIdx.x * blockDim.x + threadIdx.x;
    bool active = qi < Ni;
    float qx = 0, qy = 0, qz = 0, q2 = 0;
    if (active) {
        const float* q = coord + ((size_t)b * Ni + qi) * 3;
        qx = q[0]; qy = q[1]; qz = q[2];
        q2 = qx * qx + qy * qy + qz * qz;
    }
    float kd[NS1]; int ki[NS1];
    for (int j = 0; j < NS1; ++j) { kd[j] = 3.0e38f; ki[j] = 0; }

    for (int t0 = 0; t0 < Ni; t0 += 1024) {
        int tl = min(1024, Ni - t0);
        for (int t = threadIdx.x; t < tl; t += blockDim.x) {
            const float* p = coord + ((size_t)b * Ni + t0 + t) * 3;
            float x = p[0], y = p[1], z = p[2];
            s[t] = make_float4(x, y, z, x * x + y * y + z * z);
        }
        __syncthreads();
        if (active) {
            for (int t = 0; t < tl; ++t) {
                int gi = t0 + t;
                if (gi == qi) continue;  // reference drops self (top-1)
                float4 c = s[t];
                float d2 = q2 - 2.f * (qx * c.x + qy * c.y + qz * c.z) + c.w;
                if (d2 < kd[NS1 - 1]) {
                    int j = NS1 - 1;
                    while (j > 0 && kd[j - 1] > d2) { kd[j] = kd[j - 1]; ki[j] = ki[j - 1]; --j; }
                    kd[j] = d2; ki[j] = gi;
                }
            }
        }
        __syncthreads();
    }
    if (!active) return;

    const float4* fq = (const float4*)(feat + ((size_t)b * Ni + qi) * (size_t)D);
    int myh = g_hard[hard_off + b * Ni + qi];
    int D4 = D >> 2;
    float fdist[NS1];
    bool  msk[NS1];
    float dmin = 3.0e38f;
    int cnt = 0;
    for (int j = 0; j < NS1; ++j) {
        const float4* fn = (const float4*)(feat + ((size_t)b * Ni + ki[j]) * (size_t)D);
        float ss = 0.f;
        for (int d = 0; d < D4; ++d) {
            float4 a = fq[d], bb = fn[d];
            float dx = a.x - bb.x, dy = a.y - bb.y, dz = a.z - bb.z, dw = a.w - bb.w;
            ss += dx * dx + dy * dy + dz * dz + dw * dw;
        }
        float dist = sqrtf(ss + 1e-6f);
        fdist[j] = dist;
        bool mm = (g_hard[hard_off + b * Ni + ki[j]] == myh);
        msk[j] = mm;
        cnt += mm ? 1 : 0;
        dmin = fminf(dmin, dist);
    }
    float pos = 0.f, neg = 0.f;
    for (int j = 0; j < NS1; ++j) {
        float e = expf(dmin - fdist[j]);  // TEMPERATURE = 1
        neg += e;
        if (msk[j]) pos += e;
    }
    float l = -logf(pos / neg + 1e-6f);
    if (cnt > 0 && cnt < NS1) {
        atomicAdd(&g_bl_sum[stage], (double)l);
        atomicAdd(&g_bl_cnt[stage], 1u);
    }
}

// ---------------- finalize ----------------
__global__ void finalize_kernel(float* out) {
    const int ns[5] = {8192, 2048, 512, 128, 32};
    double ce = g_ce_sum[0] / (double)(BB * NN);
    double o = 0.0;
    for (int j = 0; j < 5; ++j) o += g_ce_sum[1 + j] / (double)(BB * ns[j]);
    double bl = 0.0;
    for (int i = 0; i < 5; ++i) {
        double dn = g_bl_cnt[i] > 0 ? (double)g_bl_cnt[i] : 1.0;
        bl += g_bl_sum[i] / dn;
    }
    out[0] = (float)(ce + 0.1 * bl + 0.1 * o);
}

// ---------------- launch ----------------
extern "C" void kernel_launch(void* const* d_in, const int* in_sizes, int n_in,
                              void* d_out, int out_size) {
    (void)in_sizes; (void)n_in; (void)out_size;
    // metadata order == setup_inputs dict insertion order:
    // 0:labels, 1..4:index2..5, 5:output,
    // then per stage j: 6+3j:pred_{j+1}, 7+3j:xyz_{j+1}, 8+3j:feat_{j+1}, 21:num_classes
    const int* labels = (const int*)d_in[0];
    const int* idx2 = (const int*)d_in[1];
    const int* idx3 = (const int*)d_in[2];
    const int* idx4 = (const int*)d_in[3];
    const int* idx5 = (const int*)d_in[4];
    const float* output = (const float*)d_in[5];
    const float* pred[5], *xyz[5], *feat[5];
    for (int j = 0; j < 5; ++j) {
        pred[j] = (const float*)d_in[6 + 3 * j];
        xyz[j]  = (const float*)d_in[7 + 3 * j];
        feat[j] = (const float*)d_in[8 + 3 * j];
    }
    const int Ns[5]   = {8192, 2048, 512, 128, 32};
    const int Ds[5]   = {64, 128, 256, 512, 512};
    const int hoff[5] = {0, 16384, 20480, 21504, 21760};

    zero_kernel<<<1, 32>>>();

    // Cross entropies
    ce_kernel<<<(BB * NN + 255) / 256, 256>>>(output,  labels, nullptr, NN, 0);
    ce_kernel<<<(BB * NN + 255) / 256, 256>>>(pred[0], labels, nullptr, NN, 1);
    ce_kernel<<<(BB * Ns[1] + 255) / 256, 256>>>(pred[1], labels, idx2, Ns[1], 2);
    ce_kernel<<<(BB * Ns[2] + 255) / 256, 256>>>(pred[2], labels, idx3, Ns[2], 3);
    ce_kernel<<<(BB * Ns[3] + 255) / 256, 256>>>(pred[3], labels, idx4, Ns[3], 4);
    ce_kernel<<<(BB * Ns[4] + 255) / 256, 256>>>(pred[4], labels, idx5, Ns[4], 5);

    // Hard (argmax-of-soft) labels per stage
    hard_copy<<<(BB * NN + 255) / 256, 256>>>(labels);
    hard_knn<4>  <<<dim3((Ns[1] + 127) / 128, BB), 128>>>(xyz[0], xyz[1], labels, Ns[1], hoff[1]);
    hard_knn<16> <<<dim3((Ns[2] + 127) / 128, BB), 128>>>(xyz[0], xyz[2], labels, Ns[2], hoff[2]);
    hard_knn<64> <<<dim3((Ns[3] + 127) / 128, BB), 128>>>(xyz[0], xyz[3], labels, Ns[3], hoff[3]);
    hard_knn<256><<<dim3((Ns[4] + 127) / 128, BB), 128>>>(xyz[0], xyz[4], labels, Ns[4], hoff[4]);

    // Boundary loss per stage
    stage_loss<35><<<dim3((Ns[0] + 127) / 128, BB), 128>>>(xyz[0], feat[0], Ns[0], Ds[0], hoff[0], 0);
    stage_loss<23><<<dim3((Ns[1] + 127) / 128, BB), 128>>>(xyz[1], feat[1], Ns[1], Ds[1], hoff[1], 1);
    stage_loss<23><<<dim3((Ns[2] + 127) / 128, BB), 128>>>(xyz[2], feat[2], Ns[2], Ds[2], hoff[2], 2);
    stage_loss<23><<<dim3((Ns[3] + 127) / 128, BB), 128>>>(xyz[3], feat[3], Ns[3], Ds[3], hoff[3], 3);
    stage_loss<23><<<dim3((Ns[4] + 127) / 128, BB), 128>>>(xyz[4], feat[4], Ns[4], Ds[4], hoff[4], 4);

    finalize_kernel<<<1, 1>>>((float*)d_out);
}

// round 4
// speedup vs baseline: 446.7198x; 446.7198x over previous
#include <cuda_runtime.h>
#include <math.h>

#define BB 2
#define NN 8192
#define CC 13

// Stage sizes: Ns = {8192,2048,512,128,32}, D = {64,128,256,512,512}
// nsample-1 = {35,23,23,23,23}, kneighbors = {1,4,16,64,256}

// ---------------- device scratch ----------------
__device__ double   g_ce_sum[6];
__device__ double   g_bl_sum[5];
__device__ unsigned g_bl_cnt[5];
__device__ int      g_hard[21824];   // offsets 0,16384,20480,21504,21760
__device__ float4   g_pack[21824];   // packed (x,y,z,|p|^2) per stage point, same offsets

__global__ void zero_kernel() {
    int t = threadIdx.x;
    if (t < 6) g_ce_sum[t] = 0.0;
    if (t < 5) { g_bl_sum[t] = 0.0; g_bl_cnt[t] = 0u; }
}

// ---------------- pack coords ----------------
__global__ void pack_kernel(const float* __restrict__ x1, const float* __restrict__ x2,
                            const float* __restrict__ x3, const float* __restrict__ x4,
                            const float* __restrict__ x5) {
    int id = blockIdx.x * blockDim.x + threadIdx.x;
    if (id >= 21824) return;
    const int offs[6] = {0, 16384, 20480, 21504, 21760, 21824};
    const float* xs[5] = {x1, x2, x3, x4, x5};
    int s = 0;
    while (id >= offs[s + 1]) ++s;
    int r = id - offs[s];
    const float* p = xs[s] + (size_t)r * 3;
    float x = p[0], y = p[1], z = p[2];
    g_pack[id] = make_float4(x, y, z, x * x + y * y + z * z);
}

// ---------------- cross entropy ----------------
__global__ void ce_kernel(const float* __restrict__ logits,
                          const int* __restrict__ labels,
                          const int* __restrict__ gidx,
                          int Ni, int slot) {
    int r = blockIdx.x * blockDim.x + threadIdx.x;
    int total = BB * Ni;
    float l = 0.f;
    if (r < total) {
        int b = r / Ni;
        int lab = gidx ? labels[b * NN + gidx[r]] : labels[r];
        const float* row = logits + (size_t)r * CC;
        float v[CC];
#pragma unroll
        for (int c = 0; c < CC; ++c) v[c] = row[c];
        float m = v[0];
#pragma unroll
        for (int c = 1; c < CC; ++c) m = fmaxf(m, v[c]);
        float s = 0.f;
#pragma unroll
        for (int c = 0; c < CC; ++c) s += expf(v[c] - m);
        l = (m + logf(s)) - v[lab];
    }
#pragma unroll
    for (int o = 16; o; o >>= 1) l += __shfl_down_sync(0xFFFFFFFFu, l, o);
    if ((threadIdx.x & 31) == 0 && l != 0.f) atomicAdd(&g_ce_sum[slot], (double)l);
}

__global__ void hard_copy(const int* __restrict__ labels) {
    int r = blockIdx.x * blockDim.x + threadIdx.x;
    if (r < BB * NN) g_hard[r] = labels[r];
}

// ---------------- selection primitives ----------------
__device__ __forceinline__ unsigned ordkey(float f) {
    unsigned u = __float_as_uint(f);
    return (u & 0x80000000u) ? ~u : (u | 0x80000000u);
}

__device__ __forceinline__ unsigned blk_count(int c, unsigned* slot) {
#pragma unroll
    for (int o = 16; o; o >>= 1) c += __shfl_down_sync(0xFFFFFFFFu, c, o);
    if ((threadIdx.x & 31) == 0 && c) atomicAdd(slot, (unsigned)c);
    __syncthreads();
    return *slot;
}

// Returns T = k-th smallest key (1-indexed). c_less = count(key < T) < k <= count(key <= T).
template <int CPT>
__device__ unsigned block_select(const unsigned (&key)[CPT], int k,
                                 unsigned* s_cnt, unsigned* c_less_out) {
    unsigned lo = 0;
#pragma unroll 1
    for (int bit = 31; bit >= 0; --bit) {
        unsigned mid = lo | (1u << bit);
        int c = 0;
#pragma unroll
        for (int i = 0; i < CPT; ++i) c += (key[i] < mid) ? 1 : 0;
        unsigned tot = blk_count(c, &s_cnt[bit]);
        if (tot < (unsigned)k) lo = mid;
    }
    int c = 0;
#pragma unroll
    for (int i = 0; i < CPT; ++i) c += (key[i] < lo) ? 1 : 0;
    *c_less_out = blk_count(c, &s_cnt[32]);
    return lo;
}

// ---------------- hard labels stages 1..4 (block per Q queries) ----------------
template <int K>
__global__ __launch_bounds__(256) void hard_knn_k(
        const int* __restrict__ labels, int cq_off, int Ni, int hard_off, int Q) {
    __shared__ unsigned s_cnt[33];
    __shared__ unsigned s_cls[13];
    __shared__ int s_tie[288];
    __shared__ unsigned s_tien;
    int b = blockIdx.y;
    int tid = threadIdx.x;
    for (int q = 0; q < Q; ++q) {
        int qi = blockIdx.x * Q + q;
        if (qi >= Ni) break;
        if (tid < 33) s_cnt[tid] = 0;
        if (tid < 13) s_cls[tid] = 0;
        if (tid == 0) s_tien = 0;
        __syncthreads();
        float4 qc = g_pack[cq_off + b * Ni + qi];
        unsigned key[32];
#pragma unroll
        for (int i = 0; i < 32; ++i) {
            int c = tid + i * 256;
            float4 p = g_pack[b * NN + c];  // full-res candidates
            float d2 = qc.w - 2.f * (qc.x * p.x + qc.y * p.y + qc.z * p.z) + p.w;
            key[i] = ordkey(d2);
        }
        unsigned cl;
        unsigned T = block_select<32>(key, K, s_cnt, &cl);
#pragma unroll
        for (int i = 0; i < 32; ++i) {
            int c = tid + i * 256;
            if (key[i] < T) atomicAdd(&s_cls[labels[b * NN + c]], 1u);
            else if (key[i] == T) {
                unsigned t = atomicAdd(&s_tien, 1u);
                if (t < 288) s_tie[t] = c;
            }
        }
        __syncthreads();
        if (tid == 0) {
            int need = K - (int)cl;
            int tn = min((int)s_tien, 288);
            for (int s = 0; s < need; ++s) {  // lowest-index ties first (top_k tie-break)
                int mbest = 0x7FFFFFFF, mj = 0;
                for (int j = 0; j < tn; ++j) if (s_tie[j] < mbest) { mbest = s_tie[j]; mj = j; }
                s_cls[labels[b * NN + mbest]]++;
                s_tie[mj] = 0x7FFFFFFF;
            }
            int best = 0; unsigned bc = s_cls[0];
#pragma unroll
            for (int cc = 1; cc < 13; ++cc) if (s_cls[cc] > bc) { bc = s_cls[cc]; best = cc; }
            g_hard[hard_off + b * Ni + qi] = best;
        }
        __syncthreads();
    }
}

// ---------------- boundary loss per stage (block per Q queries) ----------------
template <int CPT, int NS1>
__global__ __launch_bounds__(256) void stage_loss_k(
        const float* __restrict__ feat, int coff, int Ni, int D,
        int hard_off, int stage, int Q) {
    __shared__ unsigned s_cnt[33];
    __shared__ int s_nb[NS1];
    __shared__ unsigned s_nbn, s_tien;
    __shared__ int s_tie[64];
    __shared__ float s_fd[NS1];
    __shared__ int s_msk[NS1];
    int b = blockIdx.y;
    int tid = threadIdx.x;
    int wid = tid >> 5, lane = tid & 31;
    for (int q = 0; q < Q; ++q) {
        int qi = blockIdx.x * Q + q;
        if (qi >= Ni) break;
        if (tid < 33) s_cnt[tid] = 0;
        if (tid == 0) { s_nbn = 0; s_tien = 0; }
        __syncthreads();
        float4 qc = g_pack[coff + b * Ni + qi];
        unsigned key[CPT];
#pragma unroll
        for (int i = 0; i < CPT; ++i) {
            int c = tid + i * 256;
            if (c < Ni && c != qi) {
                float4 p = g_pack[coff + b * Ni + c];
                float d2 = qc.w - 2.f * (qc.x * p.x + qc.y * p.y + qc.z * p.z) + p.w;
                key[i] = ordkey(d2);
            } else key[i] = 0xFFFFFFFFu;
        }
        unsigned cl;
        unsigned T = block_select<CPT>(key, NS1, s_cnt, &cl);
#pragma unroll
        for (int i = 0; i < CPT; ++i) {
            int c = tid + i * 256;
            if (key[i] < T) { unsigned p = atomicAdd(&s_nbn, 1u); s_nb[p] = c; }
            else if (key[i] == T && T != 0xFFFFFFFFu) {
                unsigned t = atomicAdd(&s_tien, 1u);
                if (t < 64) s_tie[t] = c;
            }
        }
        __syncthreads();
        if (tid == 0) {
            int need = NS1 - (int)cl;
            int tn = min((int)s_tien, 64);
            for (int s = 0; s < need; ++s) {
                int mbest = 0x7FFFFFFF, mj = 0;
                for (int j = 0; j < tn; ++j) if (s_tie[j] < mbest) { mbest = s_tie[j]; mj = j; }
                s_nb[(int)cl + s] = mbest;
                s_tie[mj] = 0x7FFFFFFF;
            }
        }
        __syncthreads();
        int myh = g_hard[hard_off + b * Ni + qi];
        const float4* fq = (const float4*)(feat + (size_t)(b * Ni + qi) * D);
        int D4 = D >> 2;
        for (int j = wid; j < NS1; j += 8) {
            int nb = s_nb[j];
            const float4* fn = (const float4*)(feat + (size_t)(b * Ni + nb) * D);
            float ss = 0.f;
            for (int d = lane; d < D4; d += 32) {
                float4 a = fq[d], z = fn[d];
                float dx = a.x - z.x, dy = a.y - z.y, dz = a.z - z.z, dw = a.w - z.w;
                ss += dx * dx + dy * dy + dz * dz + dw * dw;
            }
#pragma unroll
            for (int o = 16; o; o >>= 1) ss += __shfl_down_sync(0xFFFFFFFFu, ss, o);
            if (lane == 0) {
                s_fd[j] = sqrtf(ss + 1e-6f);
                s_msk[j] = (g_hard[hard_off + b * Ni + nb] == myh) ? 1 : 0;
            }
        }
        __syncthreads();
        if (tid == 0) {
            float dmin = 3.0e38f; int cnt = 0;
            for (int j = 0; j < NS1; ++j) { dmin = fminf(dmin, s_fd[j]); cnt += s_msk[j]; }
            if (cnt > 0 && cnt < NS1) {
                float pos = 0.f, neg = 0.f;
                for (int j = 0; j < NS1; ++j) {
                    float e = expf(dmin - s_fd[j]);  // TEMPERATURE = 1
                    neg += e;
                    if (s_msk[j]) pos += e;
                }
                float l = -logf(pos / neg + 1e-6f);
                atomicAdd(&g_bl_sum[stage], (double)l);
                atomicAdd(&g_bl_cnt[stage], 1u);
            }
        }
        __syncthreads();
    }
}

// ---------------- finalize ----------------
__global__ void finalize_kernel(float* out) {
    const int ns[5] = {8192, 2048, 512, 128, 32};
    double ce = g_ce_sum[0] / (double)(BB * NN);
    double o = 0.0;
    for (int j = 0; j < 5; ++j) o += g_ce_sum[1 + j] / (double)(BB * ns[j]);
    double bl = 0.0;
    for (int i = 0; i < 5; ++i) {
        double dn = g_bl_cnt[i] > 0 ? (double)g_bl_cnt[i] : 1.0;
        bl += g_bl_sum[i] / dn;
    }
    out[0] = (float)(ce + 0.1 * bl + 0.1 * o);
}

// ---------------- launch ----------------
extern "C" void kernel_launch(void* const* d_in, const int* in_sizes, int n_in,
                              void* d_out, int out_size) {
    (void)in_sizes; (void)n_in; (void)out_size;
    // 0:labels, 1..4:index2..5, 5:output, then per stage j: 6+3j:pred, 7+3j:xyz, 8+3j:feat
    const int* labels = (const int*)d_in[0];
    const int* idx2 = (const int*)d_in[1];
    const int* idx3 = (const int*)d_in[2];
    const int* idx4 = (const int*)d_in[3];
    const int* idx5 = (const int*)d_in[4];
    const float* output = (const float*)d_in[5];
    const float* pred[5], *xyz[5], *feat[5];
    for (int j = 0; j < 5; ++j) {
        pred[j] = (const float*)d_in[6 + 3 * j];
        xyz[j]  = (const float*)d_in[7 + 3 * j];
        feat[j] = (const float*)d_in[8 + 3 * j];
    }
    const int Ns[5]   = {8192, 2048, 512, 128, 32};
    const int hoff[5] = {0, 16384, 20480, 21504, 21760};

    zero_kernel<<<1, 32>>>();
    pack_kernel<<<(21824 + 255) / 256, 256>>>(xyz[0], xyz[1], xyz[2], xyz[3], xyz[4]);
    hard_copy<<<(BB * NN + 255) / 256, 256>>>(labels);

    // Cross entropies
    ce_kernel<<<(BB * NN + 255) / 256, 256>>>(output,  labels, nullptr, NN, 0);
    ce_kernel<<<(BB * NN + 255) / 256, 256>>>(pred[0], labels, nullptr, NN, 1);
    ce_kernel<<<(BB * Ns[1] + 255) / 256, 256>>>(pred[1], labels, idx2, Ns[1], 2);
    ce_kernel<<<(BB * Ns[2] + 255) / 256, 256>>>(pred[2], labels, idx3, Ns[2], 3);
    ce_kernel<<<(BB * Ns[3] + 255) / 256, 256>>>(pred[3], labels, idx4, Ns[3], 4);
    ce_kernel<<<(BB * Ns[4] + 255) / 256, 256>>>(pred[4], labels, idx5, Ns[4], 5);

    // Hard labels (k nearest full-res points, label count argmax)
    hard_knn_k<4>  <<<dim3(256, BB), 256>>>(labels, hoff[1], Ns[1], hoff[1], 8);
    hard_knn_k<16> <<<dim3(128, BB), 256>>>(labels, hoff[2], Ns[2], hoff[2], 4);
    hard_knn_k<64> <<<dim3(128, BB), 256>>>(labels, hoff[3], Ns[3], hoff[3], 1);
    hard_knn_k<256><<<dim3(32, BB), 256>>>(labels, hoff[4], Ns[4], hoff[4], 1);

    // Boundary losses
    stage_loss_k<32, 35><<<dim3(1024, BB), 256>>>(feat[0], hoff[0], Ns[0], 64,  hoff[0], 0, 8);
    stage_loss_k<8,  23><<<dim3(256, BB), 256>>>(feat[1], hoff[1], Ns[1], 128, hoff[1], 1, 8);
    stage_loss_k<2,  23><<<dim3(128, BB), 256>>>(feat[2], hoff[2], Ns[2], 256, hoff[2], 2, 4);
    stage_loss_k<1,  23><<<dim3(128, BB), 256>>>(feat[3], hoff[3], Ns[3], 512, hoff[3], 3, 1);
    stage_loss_k<1,  23><<<dim3(32, BB), 256>>>(feat[4], hoff[4], Ns[4], 512, hoff[4], 4, 1);

    finalize_kernel<<<1, 1>>>((float*)d_out);
}

// round 5
// speedup vs baseline: 1023.1061x; 2.2903x over previous
#include <cuda_runtime.h>
#include <math.h>

#define BB 2
#define NN 8192

// Stage sizes: Ns = {8192,2048,512,128,32}, D = {64,128,256,512,512}
// nsample-1 = {35,23,23,23,23}, kneighbors = {1,4,16,64,256}
// offsets into g_hard/g_pack: {0,16384,20480,21504,21760}

__device__ double   g_ce_sum[6];
__device__ double   g_bl_sum[5];
__device__ unsigned g_bl_cnt[5];
__device__ int      g_hard[21824];
__device__ float4   g_pack[21824];

__global__ void zero_kernel() {
    int t = threadIdx.x;
    if (t < 6) g_ce_sum[t] = 0.0;
    if (t < 5) { g_bl_sum[t] = 0.0; g_bl_cnt[t] = 0u; }
}

__global__ void pack_kernel(const float* __restrict__ x1, const float* __restrict__ x2,
                            const float* __restrict__ x3, const float* __restrict__ x4,
                            const float* __restrict__ x5) {
    int id = blockIdx.x * blockDim.x + threadIdx.x;
    if (id >= 21824) return;
    const int offs[6] = {0, 16384, 20480, 21504, 21760, 21824};
    const float* xs[5] = {x1, x2, x3, x4, x5};
    int s = 0;
    while (id >= offs[s + 1]) ++s;
    int r = id - offs[s];
    const float* p = xs[s] + (size_t)r * 3;
    float x = p[0], y = p[1], z = p[2];
    g_pack[id] = make_float4(x, y, z, x * x + y * y + z * z);
}

__global__ void hard_copy(const int* __restrict__ labels) {
    int r = blockIdx.x * blockDim.x + threadIdx.x;
    if (r < BB * NN) g_hard[r] = labels[r];
}

// ---------------- fused cross entropy (6 jobs) ----------------
__global__ void ce_fused(const float* __restrict__ lg0, const float* __restrict__ lg1,
                         const float* __restrict__ lg2, const float* __restrict__ lg3,
                         const float* __restrict__ lg4, const float* __restrict__ lg5,
                         const int* __restrict__ labels,
                         const int* __restrict__ i2, const int* __restrict__ i3,
                         const int* __restrict__ i4, const int* __restrict__ i5) {
    const int cum[7] = {0, 16384, 32768, 36864, 37888, 38144, 38208};
    int r = blockIdx.x * blockDim.x + threadIdx.x;
    int job = 0;
#pragma unroll
    for (int j = 1; j < 6; ++j) if (r >= cum[j]) job = j;
    float l = 0.f;
    if (r < 38208) {
        const float* L[6] = {lg0, lg1, lg2, lg3, lg4, lg5};
        const int*   G[6] = {nullptr, nullptr, i2, i3, i4, i5};
        const int   lg[6] = {13, 13, 11, 9, 7, 5};  // log2(Ni)
        int lr = r - cum[job];
        int b = lr >> lg[job];
        const int* g = G[job];
        int lab = g ? labels[b * NN + g[lr]] : labels[lr];
        const float* row = L[job] + (size_t)lr * 13;
        float v[13];
#pragma unroll
        for (int c = 0; c < 13; ++c) v[c] = row[c];
        float m = v[0];
#pragma unroll
        for (int c = 1; c < 13; ++c) m = fmaxf(m, v[c]);
        float s = 0.f;
#pragma unroll
        for (int c = 0; c < 13; ++c) s += expf(v[c] - m);
        l = (m + logf(s)) - v[lab];
    }
#pragma unroll
    for (int o = 16; o; o >>= 1) l += __shfl_down_sync(0xFFFFFFFFu, l, o);
    // job boundaries are multiples of 256 -> slot uniform per block
    if ((threadIdx.x & 31) == 0 && l != 0.f) atomicAdd(&g_ce_sum[job], (double)l);
}

// ---------------- selection primitives ----------------
__device__ __forceinline__ unsigned ordkey(float f) {
    unsigned u = __float_as_uint(f);
    return (u & 0x80000000u) ? ~u : (u | 0x80000000u);
}

// Binary search top 16 bits of the k-th smallest key. Requires blockDim == 256.
// Returns Lo (low 16 bits zero): count(key < Lo) = cl < k <= count(key < Lo + 0x10000).
template <int CPT>
__device__ __forceinline__ void select16(const unsigned (&key)[CPT], int k,
                                         unsigned (*s_w)[8], int wid, int lane,
                                         unsigned& Lo_out, int& cl_out) {
    unsigned Lo = 0x80000000u;  // bit31 always set for ordkey of positive floats
    int cl = 0;
#pragma unroll 1
    for (int bit = 30; bit >= 16; --bit) {
        unsigned mid = Lo | (1u << bit);
        int c = 0;
#pragma unroll
        for (int i = 0; i < CPT; ++i) c += (key[i] < mid) ? 1 : 0;
        c = __reduce_add_sync(0xFFFFFFFFu, c);
        if (lane == 0) s_w[bit - 16][wid] = (unsigned)c;
        __syncthreads();
        int tot = 0;
#pragma unroll
        for (int w = 0; w < 8; ++w) tot += s_w[bit - 16][w];
        if (tot < k) { Lo = mid; cl = tot; }
        // no 2nd barrier: next iteration writes a different s_w row
    }
    Lo_out = Lo; cl_out = cl;
}

// ---------------- fused hard labels (stages 1..4) ----------------
__global__ __launch_bounds__(256) void hard_fused(const int* __restrict__ labels) {
    __shared__ unsigned s_w[15][8];
    __shared__ unsigned s_n, s_cls[13];
    __shared__ unsigned s_skey[128];
    __shared__ int s_sidx[128];
    int bx = blockIdx.x, b = blockIdx.y;
    int s, chunk;
    if (bx < 512)      { s = 0; chunk = bx; }
    else if (bx < 640) { s = 1; chunk = bx - 512; }
    else if (bx < 704) { s = 2; chunk = bx - 640; }
    else               { s = 3; chunk = bx - 704; }
    const int NiA[4] = {2048, 512, 128, 32};
    const int KA[4]  = {4, 16, 64, 256};
    const int QA[4]  = {4, 4, 2, 1};
    const int OffA[4] = {16384, 20480, 21504, 21760};
    int Ni = NiA[s], K = KA[s], Q = QA[s], off = OffA[s];
    int tid = threadIdx.x, wid = tid >> 5, lane = tid & 31;
    for (int q = 0; q < Q; ++q) {
        int qi = chunk * Q + q;
        if (qi >= Ni) break;
        if (tid < 13) s_cls[tid] = 0;
        if (tid == 0) s_n = 0;
        __syncthreads();
        float4 qc = g_pack[off + b * Ni + qi];
        unsigned key[32];
#pragma unroll
        for (int i = 0; i < 32; ++i) {
            float4 p = g_pack[b * NN + tid + i * 256];
            float d2 = qc.w - 2.f * (qc.x * p.x + qc.y * p.y + qc.z * p.z) + p.w;
            key[i] = ordkey(d2);
        }
        unsigned Lo; int cl;
        select16<32>(key, K, s_w, wid, lane, Lo, cl);
#pragma unroll
        for (int i = 0; i < 32; ++i) {
            int c = tid + i * 256;
            if (key[i] < Lo) atomicAdd(&s_cls[labels[b * NN + c]], 1u);
            else if ((key[i] >> 16) == (Lo >> 16)) {
                unsigned p = atomicAdd(&s_n, 1u);
                if (p < 128) { s_skey[p] = key[i]; s_sidx[p] = c; }
            }
        }
        __syncthreads();
        int n = min(s_n, 128u), need = K - cl;
        for (int j = tid; j < n; j += 256) {
            unsigned kj = s_skey[j]; int ij = s_sidx[j], r = 0;
            for (int m = 0; m < n; ++m) {
                unsigned km = s_skey[m];
                r += (km < kj) || (km == kj && s_sidx[m] < ij);
            }
            if (r < need) atomicAdd(&s_cls[labels[b * NN + ij]], 1u);
        }
        __syncthreads();
        if (tid == 0) {
            int best = 0; unsigned bc = s_cls[0];
#pragma unroll
            for (int cc = 1; cc < 13; ++cc) if (s_cls[cc] > bc) { bc = s_cls[cc]; best = cc; }
            g_hard[off + b * Ni + qi] = best;
        }
        __syncthreads();  // protect s_cls/s_skey reuse in next q
    }
}

// ---------------- boundary loss body ----------------
template <int CPT>
__device__ __forceinline__ void loss_body(const float* __restrict__ feat,
                                          int off, int Ni, int D, int stage,
                                          int chunk, int b, int Q, int NS1) {
    __shared__ unsigned s_w[15][8];
    __shared__ unsigned s_n, s_nbn;
    __shared__ unsigned s_skey[128];
    __shared__ int s_sidx[128];
    __shared__ int s_nb[35];
    __shared__ float s_fd[35];
    __shared__ int s_msk[35];
    int tid = threadIdx.x, wid = tid >> 5, lane = tid & 31;
    for (int q = 0; q < Q; ++q) {
        int qi = chunk * Q + q;
        if (qi >= Ni) break;
        if (tid == 0) { s_n = 0; s_nbn = 0; }
        __syncthreads();
        float4 qc = g_pack[off + b * Ni + qi];
        unsigned key[CPT];
#pragma unroll
        for (int i = 0; i < CPT; ++i) {
            int c = tid + i * 256;
            if (c < Ni && c != qi) {
                float4 p = g_pack[off + b * Ni + c];
                float d2 = qc.w - 2.f * (qc.x * p.x + qc.y * p.y + qc.z * p.z) + p.w;
                key[i] = ordkey(d2);
            } else key[i] = 0xFFFFFFFFu;
        }
        unsigned Lo; int cl;
        select16<CPT>(key, NS1, s_w, wid, lane, Lo, cl);
#pragma unroll
        for (int i = 0; i < CPT; ++i) {
            int c = tid + i * 256;
            if (key[i] < Lo) { unsigned p = atomicAdd(&s_nbn, 1u); s_nb[p] = c; }
            else if ((key[i] >> 16) == (Lo >> 16)) {
                unsigned p = atomicAdd(&s_n, 1u);
                if (p < 128) { s_skey[p] = key[i]; s_sidx[p] = c; }
            }
        }
        __syncthreads();
        int n = min(s_n, 128u), need = NS1 - cl;
        for (int j = tid; j < n; j += 256) {
            unsigned kj = s_skey[j]; int ij = s_sidx[j], r = 0;
            for (int m = 0; m < n; ++m) {
                unsigned km = s_skey[m];
                r += (km < kj) || (km == kj && s_sidx[m] < ij);
            }
            if (r < need) { unsigned p = atomicAdd(&s_nbn, 1u); s_nb[p] = ij; }
        }
        __syncthreads();
        // feature-space distances (loss is order-invariant over the neighbor set)
        int myh = g_hard[off + b * Ni + qi];
        const float4* fq = (const float4*)(feat + (size_t)(b * Ni + qi) * D);
        int D4 = D >> 2;
        for (int j = wid; j < NS1; j += 8) {
            int nb = s_nb[j];
            const float4* fn = (const float4*)(feat + (size_t)(b * Ni + nb) * D);
            float ss = 0.f;
            for (int d = lane; d < D4; d += 32) {
                float4 a = fq[d], z = fn[d];
                float dx = a.x - z.x, dy = a.y - z.y, dz = a.z - z.z, dw = a.w - z.w;
                ss += dx * dx + dy * dy + dz * dz + dw * dw;
            }
#pragma unroll
            for (int o = 16; o; o >>= 1) ss += __shfl_down_sync(0xFFFFFFFFu, ss, o);
            if (lane == 0) {
                s_fd[j] = sqrtf(ss + 1e-6f);
                s_msk[j] = (g_hard[off + b * Ni + nb] == myh) ? 1 : 0;
            }
        }
        __syncthreads();
        if (tid == 0) {
            float dmin = 3.0e38f; int cnt = 0;
            for (int j = 0; j < NS1; ++j) { dmin = fminf(dmin, s_fd[j]); cnt += s_msk[j]; }
            if (cnt > 0 && cnt < NS1) {
                float pos = 0.f, neg = 0.f;
                for (int j = 0; j < NS1; ++j) {
                    float e = expf(dmin - s_fd[j]);  // TEMPERATURE = 1
                    neg += e;
                    if (s_msk[j]) pos += e;
                }
                float l = -logf(pos / neg + 1e-6f);
                atomicAdd(&g_bl_sum[stage], (double)l);
                atomicAdd(&g_bl_cnt[stage], 1u);
            }
        }
        __syncthreads();  // protect smem reuse in next q
    }
}

__global__ __launch_bounds__(256) void loss0_kernel(const float* __restrict__ feat) {
    loss_body<32>(feat, 0, NN, 64, 0, blockIdx.x, blockIdx.y, 4, 35);
}

__global__ __launch_bounds__(256) void loss_fused(const float* __restrict__ f2,
                                                  const float* __restrict__ f3,
                                                  const float* __restrict__ f4,
                                                  const float* __restrict__ f5) {
    int bx = blockIdx.x;
    int s, chunk;
    if (bx < 512)      { s = 0; chunk = bx; }
    else if (bx < 768) { s = 1; chunk = bx - 512; }
    else if (bx < 896) { s = 2; chunk = bx - 768; }
    else               { s = 3; chunk = bx - 896; }
    const int NiA[4] = {2048, 512, 128, 32};
    const int DA[4]  = {128, 256, 512, 512};
    const int QA[4]  = {4, 2, 1, 1};
    const int OffA[4] = {16384, 20480, 21504, 21760};
    const float* F[4] = {f2, f3, f4, f5};
    loss_body<8>(F[s], OffA[s], NiA[s], DA[s], s + 1, chunk, blockIdx.y, QA[s], 23);
}

// ---------------- finalize ----------------
__global__ void finalize_kernel(float* out) {
    const int ns[5] = {8192, 2048, 512, 128, 32};
    double ce = g_ce_sum[0] / (double)(BB * NN);
    double o = 0.0;
    for (int j = 0; j < 5; ++j) o += g_ce_sum[1 + j] / (double)(BB * ns[j]);
    double bl = 0.0;
    for (int i = 0; i < 5; ++i) {
        double dn = g_bl_cnt[i] > 0 ? (double)g_bl_cnt[i] : 1.0;
        bl += g_bl_sum[i] / dn;
    }
    out[0] = (float)(ce + 0.1 * bl + 0.1 * o);
}

// ---------------- launch ----------------
extern "C" void kernel_launch(void* const* d_in, const int* in_sizes, int n_in,
                              void* d_out, int out_size) {
    (void)in_sizes; (void)n_in; (void)out_size;
    // 0:labels, 1..4:index2..5, 5:output, per stage j: 6+3j:pred, 7+3j:xyz, 8+3j:feat
    const int* labels = (const int*)d_in[0];
    const int* idx2 = (const int*)d_in[1];
    const int* idx3 = (const int*)d_in[2];
    const int* idx4 = (const int*)d_in[3];
    const int* idx5 = (const int*)d_in[4];
    const float* output = (const float*)d_in[5];
    const float* pred[5], *xyz[5], *feat[5];
    for (int j = 0; j < 5; ++j) {
        pred[j] = (const float*)d_in[6 + 3 * j];
        xyz[j]  = (const float*)d_in[7 + 3 * j];
        feat[j] = (const float*)d_in[8 + 3 * j];
    }

    zero_kernel<<<1, 32>>>();
    pack_kernel<<<(21824 + 255) / 256, 256>>>(xyz[0], xyz[1], xyz[2], xyz[3], xyz[4]);
    hard_copy<<<(BB * NN + 255) / 256, 256>>>(labels);

    hard_fused<<<dim3(736, BB), 256>>>(labels);
    ce_fused<<<150, 256>>>(output, pred[0], pred[1], pred[2], pred[3], pred[4],
                           labels, idx2, idx3, idx4, idx5);
    loss0_kernel<<<dim3(2048, BB), 256>>>(feat[0]);
    loss_fused<<<dim3(928, BB), 256>>>(feat[1], feat[2], feat[3], feat[4]);

    finalize_kernel<<<1, 1>>>((float*)d_out);
}

// round 6
// speedup vs baseline: 1052.0192x; 1.0283x over previous
#include <cuda_runtime.h>
#include <math.h>

#define BB 2
#define NN 8192

// Stage sizes: Ns = {8192,2048,512,128,32}, D = {64,128,256,512,512}
// nsample-1 = {35,23,23,23,23}, kneighbors = {1,4,16,64,256}
// offsets into g_hard/g_pack: {0,16384,20480,21504,21760}

__device__ double   g_ce_sum[6];
__device__ double   g_bl_sum[5];
__device__ unsigned g_bl_cnt[5];
__device__ int      g_hard[21824];
__device__ float4   g_pack[21824];

__global__ void zero_kernel() {
    int t = threadIdx.x;
    if (t < 6) g_ce_sum[t] = 0.0;
    if (t < 5) { g_bl_sum[t] = 0.0; g_bl_cnt[t] = 0u; }
}

__global__ void pack_kernel(const float* __restrict__ x1, const float* __restrict__ x2,
                            const float* __restrict__ x3, const float* __restrict__ x4,
                            const float* __restrict__ x5) {
    int id = blockIdx.x * blockDim.x + threadIdx.x;
    if (id >= 21824) return;
    const int offs[6] = {0, 16384, 20480, 21504, 21760, 21824};
    const float* xs[5] = {x1, x2, x3, x4, x5};
    int s = 0;
    while (id >= offs[s + 1]) ++s;
    int r = id - offs[s];
    const float* p = xs[s] + (size_t)r * 3;
    float x = p[0], y = p[1], z = p[2];
    g_pack[id] = make_float4(x, y, z, x * x + y * y + z * z);
}

__global__ void hard_copy(const int* __restrict__ labels) {
    int r = blockIdx.x * blockDim.x + threadIdx.x;
    if (r < BB * NN) g_hard[r] = labels[r];
}

// ---------------- fused cross entropy (6 jobs) ----------------
__global__ void ce_fused(const float* __restrict__ lg0, const float* __restrict__ lg1,
                         const float* __restrict__ lg2, const float* __restrict__ lg3,
                         const float* __restrict__ lg4, const float* __restrict__ lg5,
                         const int* __restrict__ labels,
                         const int* __restrict__ i2, const int* __restrict__ i3,
                         const int* __restrict__ i4, const int* __restrict__ i5) {
    const int cum[7] = {0, 16384, 32768, 36864, 37888, 38144, 38208};
    int r = blockIdx.x * blockDim.x + threadIdx.x;
    int job = 0;
#pragma unroll
    for (int j = 1; j < 6; ++j) if (r >= cum[j]) job = j;
    float l = 0.f;
    if (r < 38208) {
        const float* L[6] = {lg0, lg1, lg2, lg3, lg4, lg5};
        const int*   G[6] = {nullptr, nullptr, i2, i3, i4, i5};
        const int   lg[6] = {13, 13, 11, 9, 7, 5};  // log2(Ni)
        int lr = r - cum[job];
        int b = lr >> lg[job];
        const int* g = G[job];
        int lab = g ? labels[b * NN + g[lr]] : labels[lr];
        const float* row = L[job] + (size_t)lr * 13;
        float v[13];
#pragma unroll
        for (int c = 0; c < 13; ++c) v[c] = row[c];
        float m = v[0];
#pragma unroll
        for (int c = 1; c < 13; ++c) m = fmaxf(m, v[c]);
        float s = 0.f;
#pragma unroll
        for (int c = 0; c < 13; ++c) s += expf(v[c] - m);
        l = (m + logf(s)) - v[lab];
    }
#pragma unroll
    for (int o = 16; o; o >>= 1) l += __shfl_down_sync(0xFFFFFFFFu, l, o);
    if ((threadIdx.x & 31) == 0 && l != 0.f) atomicAdd(&g_ce_sum[job], (double)l);
}

// ---------------- selection primitives ----------------
__device__ __forceinline__ unsigned ordkey(float f) {
    unsigned u = __float_as_uint(f);
    return (u & 0x80000000u) ? ~u : (u | 0x80000000u);
}

// Find bin containing rank k (1-indexed) in hist[0..NB). res[0]=bin, res[1]=count below bin.
template <int NB>
__device__ __forceinline__ void scan_find(const unsigned* hist, int* wsum, int* res,
                                          int k, int tid, int wid, int lane) {
    const int R = NB / 256;
    int base = tid * R;
    int local = 0;
#pragma unroll
    for (int r = 0; r < R; ++r) local += (int)hist[base + r];
    int incl = local;
#pragma unroll
    for (int o = 1; o < 32; o <<= 1) {
        int t = __shfl_up_sync(0xFFFFFFFFu, incl, o);
        if (lane >= o) incl += t;
    }
    if (lane == 31) wsum[wid] = incl;
    __syncthreads();
    int woff = 0;
#pragma unroll
    for (int w = 0; w < 8; ++w) woff += (w < wid) ? wsum[w] : 0;
    int excl = woff + incl - local;
    if (excl < k && k <= excl + local) {
        int c = excl, bin = base;
#pragma unroll
        for (int r = 0; r < R; ++r) {
            int h = (int)hist[base + r];
            if (c + h >= k) { bin = base + r; break; }
            c += h;
        }
        res[0] = bin; res[1] = c;
    }
    __syncthreads();
}

// Two-level histogram select: prefix22 = top-22-bit prefix of the k-th smallest key,
// cl = count(key < prefix22<<10). Skips invalid keys (0xFFFFFFFF).
template <int CPT>
__device__ __forceinline__ void hist_select(const unsigned (&key)[CPT], int k,
                                            unsigned* hist, int* wsum, int* res,
                                            int tid, int wid, int lane,
                                            unsigned& prefix22, int& cl) {
#pragma unroll
    for (int i = 0; i < 8; ++i) hist[tid + i * 256] = 0;
    __syncthreads();
#pragma unroll
    for (int i = 0; i < CPT; ++i)
        if (key[i] != 0xFFFFFFFFu) atomicAdd(&hist[(key[i] >> 21) & 0x3FFu], 1u);
    __syncthreads();
    scan_find<1024>(hist, wsum, res, k, tid, wid, lane);
    int B1 = res[0], cl1 = res[1];
    __syncthreads();  // everyone has read res before hist rezero
#pragma unroll
    for (int i = 0; i < 8; ++i) hist[tid + i * 256] = 0;
    __syncthreads();
#pragma unroll
    for (int i = 0; i < CPT; ++i)
        if (key[i] != 0xFFFFFFFFu && (int)((key[i] >> 21) & 0x3FFu) == B1)
            atomicAdd(&hist[(key[i] >> 10) & 0x7FFu], 1u);
    __syncthreads();
    scan_find<2048>(hist, wsum, res, k - cl1, tid, wid, lane);
    int B2 = res[0], cl2 = res[1];
    prefix22 = (((unsigned)B1 | 0x400u) << 11) | (unsigned)B2;
    cl = cl1 + cl2;
}

// ---------------- fused hard labels (stages 1..4) ----------------
__global__ __launch_bounds__(256) void hard_fused(const int* __restrict__ labels) {
    __shared__ unsigned s_hist[2048];
    __shared__ int s_wsum[8], s_res[2];
    __shared__ unsigned s_n, s_cls[13];
    __shared__ unsigned s_skey[128];
    __shared__ int s_sidx[128];
    int bx = blockIdx.x, b = blockIdx.y;
    int s, chunk;
    if (bx < 512)      { s = 0; chunk = bx; }
    else if (bx < 640) { s = 1; chunk = bx - 512; }
    else if (bx < 704) { s = 2; chunk = bx - 640; }
    else               { s = 3; chunk = bx - 704; }
    const int NiA[4] = {2048, 512, 128, 32};
    const int KA[4]  = {4, 16, 64, 256};
    const int QA[4]  = {4, 4, 2, 1};
    const int OffA[4] = {16384, 20480, 21504, 21760};
    int Ni = NiA[s], K = KA[s], Q = QA[s], off = OffA[s];
    int tid = threadIdx.x, wid = tid >> 5, lane = tid & 31;
    for (int q = 0; q < Q; ++q) {
        int qi = chunk * Q + q;
        if (qi >= Ni) break;
        if (tid < 13) s_cls[tid] = 0;
        if (tid == 0) s_n = 0;
        float4 qc = g_pack[off + b * Ni + qi];
        unsigned key[32];
#pragma unroll
        for (int i = 0; i < 32; ++i) {
            float4 p = g_pack[b * NN + tid + i * 256];
            float d2 = qc.w - 2.f * (qc.x * p.x + qc.y * p.y + qc.z * p.z) + p.w;
            key[i] = ordkey(d2);
        }
        __syncthreads();  // s_cls/s_n init + previous-iter smem reads done
        unsigned pre; int cl;
        hist_select<32>(key, K, s_hist, s_wsum, s_res, tid, wid, lane, pre, cl);
        unsigned T = pre << 10;
#pragma unroll
        for (int i = 0; i < 32; ++i) {
            int c = tid + i * 256;
            if (key[i] < T) atomicAdd(&s_cls[labels[b * NN + c]], 1u);
            else if ((key[i] >> 10) == pre) {
                unsigned p = atomicAdd(&s_n, 1u);
                if (p < 128) { s_skey[p] = key[i]; s_sidx[p] = c; }
            }
        }
        __syncthreads();
        int n = min(s_n, 128u), need = K - cl;
        for (int j = tid; j < n; j += 256) {
            unsigned kj = s_skey[j]; int ij = s_sidx[j], r = 0;
            for (int m = 0; m < n; ++m) {
                unsigned km = s_skey[m];
                r += (km < kj) || (km == kj && s_sidx[m] < ij);
            }
            if (r < need) atomicAdd(&s_cls[labels[b * NN + ij]], 1u);
        }
        __syncthreads();
        if (tid == 0) {
            int best = 0; unsigned bc = s_cls[0];
#pragma unroll
            for (int cc = 1; cc < 13; ++cc) if (s_cls[cc] > bc) { bc = s_cls[cc]; best = cc; }
            g_hard[off + b * Ni + qi] = best;
        }
    }
}

// ---------------- boundary loss body ----------------
template <int CPT>
__device__ __forceinline__ void loss_body(const float* __restrict__ feat,
                                          int off, int Ni, int D, int stage,
                                          int chunk, int b, int Q, int NS1) {
    __shared__ unsigned s_hist[2048];
    __shared__ int s_wsum[8], s_res[2];
    __shared__ unsigned s_n, s_nbn;
    __shared__ unsigned s_skey[128];
    __shared__ int s_sidx[128];
    __shared__ int s_nb[35];
    __shared__ float s_fd[35];
    __shared__ int s_msk[35];
    int tid = threadIdx.x, wid = tid >> 5, lane = tid & 31;
    for (int q = 0; q < Q; ++q) {
        int qi = chunk * Q + q;
        if (qi >= Ni) break;
        if (tid == 0) { s_n = 0; s_nbn = 0; }
        float4 qc = g_pack[off + b * Ni + qi];
        unsigned key[CPT];
#pragma unroll
        for (int i = 0; i < CPT; ++i) {
            int c = tid + i * 256;
            if (c < Ni && c != qi) {
                float4 p = g_pack[off + b * Ni + c];
                float d2 = qc.w - 2.f * (qc.x * p.x + qc.y * p.y + qc.z * p.z) + p.w;
                key[i] = ordkey(d2);
            } else key[i] = 0xFFFFFFFFu;
        }
        __syncthreads();
        if (Ni <= 256) {
            // direct exact ranking: one candidate per thread, keys staged in smem
            s_hist[tid] = key[0];
            __syncthreads();
            unsigned myk = key[0];
            if (myk != 0xFFFFFFFFu) {
                int r = 0;
                for (int j = 0; j < Ni; ++j) {
                    unsigned kj = s_hist[j];
                    r += (kj < myk) || (kj == myk && j < tid);
                }
                if (r < NS1) s_nb[r] = tid;
            }
            __syncthreads();
        } else {
            unsigned pre; int cl;
            hist_select<CPT>(key, NS1, s_hist, s_wsum, s_res, tid, wid, lane, pre, cl);
            unsigned T = pre << 10;
#pragma unroll
            for (int i = 0; i < CPT; ++i) {
                int c = tid + i * 256;
                if (key[i] < T) { unsigned p = atomicAdd(&s_nbn, 1u); s_nb[p] = c; }
                else if ((key[i] >> 10) == pre) {
                    unsigned p = atomicAdd(&s_n, 1u);
                    if (p < 128) { s_skey[p] = key[i]; s_sidx[p] = c; }
                }
            }
            __syncthreads();
            int n = min(s_n, 128u), need = NS1 - cl;
            for (int j = tid; j < n; j += 256) {
                unsigned kj = s_skey[j]; int ij = s_sidx[j], r = 0;
                for (int m = 0; m < n; ++m) {
                    unsigned km = s_skey[m];
                    r += (km < kj) || (km == kj && s_sidx[m] < ij);
                }
                if (r < need) { unsigned p = atomicAdd(&s_nbn, 1u); s_nb[p] = ij; }
            }
            __syncthreads();
        }
        // feature-space distances (loss is order-invariant over the neighbor set)
        int myh = g_hard[off + b * Ni + qi];
        const float4* fq = (const float4*)(feat + (size_t)(b * Ni + qi) * D);
        int D4 = D >> 2;
        for (int j = wid; j < NS1; j += 8) {
            int nb = s_nb[j];
            const float4* fn = (const float4*)(feat + (size_t)(b * Ni + nb) * D);
            float ss = 0.f;
            for (int d = lane; d < D4; d += 32) {
                float4 a = fq[d], z = fn[d];
                float dx = a.x - z.x, dy = a.y - z.y, dz = a.z - z.z, dw = a.w - z.w;
                ss += dx * dx + dy * dy + dz * dz + dw * dw;
            }
#pragma unroll
            for (int o = 16; o; o >>= 1) ss += __shfl_down_sync(0xFFFFFFFFu, ss, o);
            if (lane == 0) {
                s_fd[j] = sqrtf(ss + 1e-6f);
                s_msk[j] = (g_hard[off + b * Ni + nb] == myh) ? 1 : 0;
            }
        }
        __syncthreads();
        if (tid == 0) {
            float dmin = 3.0e38f; int cnt = 0;
            for (int j = 0; j < NS1; ++j) { dmin = fminf(dmin, s_fd[j]); cnt += s_msk[j]; }
            if (cnt > 0 && cnt < NS1) {
                float pos = 0.f, neg = 0.f;
                for (int j = 0; j < NS1; ++j) {
                    float e = expf(dmin - s_fd[j]);  // TEMPERATURE = 1
                    neg += e;
                    if (s_msk[j]) pos += e;
                }
                float l = -logf(pos / neg + 1e-6f);
                atomicAdd(&g_bl_sum[stage], (double)l);
                atomicAdd(&g_bl_cnt[stage], 1u);
            }
        }
        __syncthreads();  // protect smem reuse in next q
    }
}

__global__ __launch_bounds__(256) void loss0_kernel(const float* __restrict__ feat) {
    loss_body<32>(feat, 0, NN, 64, 0, blockIdx.x, blockIdx.y, 4, 35);
}

__global__ __launch_bounds__(256) void loss_fused(const float* __restrict__ f2,
                                                  const float* __restrict__ f3,
                                                  const float* __restrict__ f4,
                                                  const float* __restrict__ f5) {
    int bx = blockIdx.x;
    int s, chunk;
    if (bx < 512)      { s = 0; chunk = bx; }
    else if (bx < 768) { s = 1; chunk = bx - 512; }
    else if (bx < 896) { s = 2; chunk = bx - 768; }
    else               { s = 3; chunk = bx - 896; }
    const int NiA[4] = {2048, 512, 128, 32};
    const int DA[4]  = {128, 256, 512, 512};
    const int QA[4]  = {4, 2, 1, 1};
    const int OffA[4] = {16384, 20480, 21504, 21760};
    const float* F[4] = {f2, f3, f4, f5};
    loss_body<8>(F[s], OffA[s], NiA[s], DA[s], s + 1, chunk, blockIdx.y, QA[s], 23);
}

// ---------------- finalize ----------------
__global__ void finalize_kernel(float* out) {
    const int ns[5] = {8192, 2048, 512, 128, 32};
    double ce = g_ce_sum[0] / (double)(BB * NN);
    double o = 0.0;
    for (int j = 0; j < 5; ++j) o += g_ce_sum[1 + j] / (double)(BB * ns[j]);
    double bl = 0.0;
    for (int i = 0; i < 5; ++i) {
        double dn = g_bl_cnt[i] > 0 ? (double)g_bl_cnt[i] : 1.0;
        bl += g_bl_sum[i] / dn;
    }
    out[0] = (float)(ce + 0.1 * bl + 0.1 * o);
}

// ---------------- launch ----------------
extern "C" void kernel_launch(void* const* d_in, const int* in_sizes, int n_in,
                              void* d_out, int out_size) {
    (void)in_sizes; (void)n_in; (void)out_size;
    // 0:labels, 1..4:index2..5, 5:output, per stage j: 6+3j:pred, 7+3j:xyz, 8+3j:feat
    const int* labels = (const int*)d_in[0];
    const int* idx2 = (const int*)d_in[1];
    const int* idx3 = (const int*)d_in[2];
    const int* idx4 = (const int*)d_in[3];
    const int* idx5 = (const int*)d_in[4];
    const float* output = (const float*)d_in[5];
    const float* pred[5], *xyz[5], *feat[5];
    for (int j = 0; j < 5; ++j) {
        pred[j] = (const float*)d_in[6 + 3 * j];
        xyz[j]  = (const float*)d_in[7 + 3 * j];
        feat[j] = (const float*)d_in[8 + 3 * j];
    }

    zero_kernel<<<1, 32>>>();
    pack_kernel<<<(21824 + 255) / 256, 256>>>(xyz[0], xyz[1], xyz[2], xyz[3], xyz[4]);
    hard_copy<<<(BB * NN + 255) / 256, 256>>>(labels);

    hard_fused<<<dim3(736, BB), 256>>>(labels);
    ce_fused<<<150, 256>>>(output, pred[0], pred[1], pred[2], pred[3], pred[4],
                           labels, idx2, idx3, idx4, idx5);
    loss0_kernel<<<dim3(2048, BB), 256>>>(feat[0]);
    loss_fused<<<dim3(928, BB), 256>>>(feat[1], feat[2], feat[3], feat[4]);

    finalize_kernel<<<1, 1>>>((float*)d_out);
}

// round 7
// speedup vs baseline: 1327.0878x; 1.2615x over previous
#include <cuda_runtime.h>
#include <math.h>

#define BB 2
#define NN 8192

// Stage sizes: Ns = {8192,2048,512,128,32}, D = {64,128,256,512,512}
// nsample-1 = {35,23,23,23,23}, kneighbors = {1,4,16,64,256}
// offsets into g_hard/g_pack: {0,16384,20480,21504,21760}

__device__ double   g_ce_sum[6];
__device__ double   g_bl_sum[5];
__device__ unsigned g_bl_cnt[5];
__device__ int      g_hard[21824];
__device__ float4   g_pack[21824];

__global__ void zero_kernel() {
    int t = threadIdx.x;
    if (t < 6) g_ce_sum[t] = 0.0;
    if (t < 5) { g_bl_sum[t] = 0.0; g_bl_cnt[t] = 0u; }
}

__global__ void pack_kernel(const float* __restrict__ x1, const float* __restrict__ x2,
                            const float* __restrict__ x3, const float* __restrict__ x4,
                            const float* __restrict__ x5) {
    int id = blockIdx.x * blockDim.x + threadIdx.x;
    if (id >= 21824) return;
    const int offs[6] = {0, 16384, 20480, 21504, 21760, 21824};
    const float* xs[5] = {x1, x2, x3, x4, x5};
    int s = 0;
    while (id >= offs[s + 1]) ++s;
    int r = id - offs[s];
    const float* p = xs[s] + (size_t)r * 3;
    float x = p[0], y = p[1], z = p[2];
    g_pack[id] = make_float4(x, y, z, x * x + y * y + z * z);
}

__global__ void hard_copy(const int* __restrict__ labels) {
    int r = blockIdx.x * blockDim.x + threadIdx.x;
    if (r < BB * NN) g_hard[r] = labels[r];
}

// ---------------- fused cross entropy (6 jobs) ----------------
__global__ void ce_fused(const float* __restrict__ lg0, const float* __restrict__ lg1,
                         const float* __restrict__ lg2, const float* __restrict__ lg3,
                         const float* __restrict__ lg4, const float* __restrict__ lg5,
                         const int* __restrict__ labels,
                         const int* __restrict__ i2, const int* __restrict__ i3,
                         const int* __restrict__ i4, const int* __restrict__ i5) {
    const int cum[7] = {0, 16384, 32768, 36864, 37888, 38144, 38208};
    int r = blockIdx.x * blockDim.x + threadIdx.x;
    int job = 0;
#pragma unroll
    for (int j = 1; j < 6; ++j) if (r >= cum[j]) job = j;
    float l = 0.f;
    if (r < 38208) {
        const float* L[6] = {lg0, lg1, lg2, lg3, lg4, lg5};
        const int*   G[6] = {nullptr, nullptr, i2, i3, i4, i5};
        const int   lg[6] = {13, 13, 11, 9, 7, 5};  // log2(Ni)
        int lr = r - cum[job];
        int b = lr >> lg[job];
        const int* g = G[job];
        int lab = g ? labels[b * NN + g[lr]] : labels[lr];
        const float* row = L[job] + (size_t)lr * 13;
        float v[13];
#pragma unroll
        for (int c = 0; c < 13; ++c) v[c] = row[c];
        float m = v[0];
#pragma unroll
        for (int c = 1; c < 13; ++c) m = fmaxf(m, v[c]);
        float s = 0.f;
#pragma unroll
        for (int c = 0; c < 13; ++c) s += expf(v[c] - m);
        l = (m + logf(s)) - v[lab];
    }
#pragma unroll
    for (int o = 16; o; o >>= 1) l += __shfl_down_sync(0xFFFFFFFFu, l, o);
    if ((threadIdx.x & 31) == 0 && l != 0.f) atomicAdd(&g_ce_sum[job], (double)l);
}

// ---------------- selection primitives ----------------
__device__ __forceinline__ unsigned ordkey(float f) {
    unsigned u = __float_as_uint(f);
    return (u & 0x80000000u) ? ~u : (u | 0x80000000u);
}

// Find bin containing rank k (1-indexed) among hist[0..4096). res[0]=bin, res[1]=count below bin.
__device__ __forceinline__ void scan_find4k(const unsigned* hist, int* wsum, int* res,
                                            int k, int tid, int wid, int lane) {
    int base = tid * 16;
    int local = 0;
#pragma unroll
    for (int r = 0; r < 16; ++r) local += (int)hist[base + r];
    int incl = local;
#pragma unroll
    for (int o = 1; o < 32; o <<= 1) {
        int t = __shfl_up_sync(0xFFFFFFFFu, incl, o);
        if (lane >= o) incl += t;
    }
    if (lane == 31) wsum[wid] = incl;
    __syncthreads();
    int woff = 0;
#pragma unroll
    for (int w = 0; w < 8; ++w) woff += (w < wid) ? wsum[w] : 0;
    int excl = woff + incl - local;
    if (excl < k && k <= excl + local) {
        int c = excl, bin = base;
#pragma unroll
        for (int r = 0; r < 16; ++r) {
            int h = (int)hist[base + r];
            if (c + h >= k) { bin = base + r; break; }
            c += h;
        }
        res[0] = bin; res[1] = c;
    }
    __syncthreads();
}

// Single-pass histogram select on bits 30..19 (bit31 always set for valid keys).
// Returns pre13 = (key>>19) of the k-th smallest, cl = count(key>>19 < pre13).
// Skips invalid keys (0xFFFFFFFF).
template <int CPT>
__device__ __forceinline__ void hist_select1(const unsigned (&key)[CPT], int k,
                                             unsigned* hist, int* wsum, int* res,
                                             int tid, int wid, int lane,
                                             unsigned& pre13, int& cl) {
    uint4* h4 = (uint4*)hist;
    uint4 z4 = make_uint4(0, 0, 0, 0);
#pragma unroll
    for (int i = 0; i < 4; ++i) h4[tid + i * 256] = z4;
    __syncthreads();
#pragma unroll
    for (int i = 0; i < CPT; ++i)
        if (key[i] != 0xFFFFFFFFu) atomicAdd(&hist[(key[i] >> 19) & 0xFFFu], 1u);
    __syncthreads();
    scan_find4k(hist, wsum, res, k, tid, wid, lane);
    pre13 = (unsigned)res[0] | 0x1000u;
    cl = res[1];
    __syncthreads();  // all threads read res before hist reuse
}

// ---------------- fused hard labels (stages 1..4) ----------------
__global__ __launch_bounds__(256) void hard_fused(const int* __restrict__ labels) {
    __shared__ unsigned s_hist[4096];
    __shared__ int s_wsum[8], s_res[2];
    __shared__ unsigned s_n, s_cls[13];
    __shared__ unsigned s_skey[320];
    __shared__ int s_sidx[320];
    int bx = blockIdx.x, b = blockIdx.y;
    int s, chunk;
    if (bx < 512)      { s = 0; chunk = bx; }
    else if (bx < 640) { s = 1; chunk = bx - 512; }
    else if (bx < 704) { s = 2; chunk = bx - 640; }
    else               { s = 3; chunk = bx - 704; }
    const int NiA[4] = {2048, 512, 128, 32};
    const int KA[4]  = {4, 16, 64, 256};
    const int QA[4]  = {4, 4, 2, 1};
    const int OffA[4] = {16384, 20480, 21504, 21760};
    int Ni = NiA[s], K = KA[s], Q = QA[s], off = OffA[s];
    int tid = threadIdx.x, wid = tid >> 5, lane = tid & 31;
    for (int q = 0; q < Q; ++q) {
        int qi = chunk * Q + q;
        if (qi >= Ni) break;
        if (tid < 13) s_cls[tid] = 0;
        if (tid == 0) s_n = 0;
        float4 qc = g_pack[off + b * Ni + qi];
        unsigned key[32];
#pragma unroll
        for (int i = 0; i < 32; ++i) {
            float4 p = g_pack[b * NN + tid + i * 256];
            float d2 = qc.w - 2.f * (qc.x * p.x + qc.y * p.y + qc.z * p.z) + p.w;
            key[i] = ordkey(d2);
        }
        __syncthreads();  // init visible + previous-iteration smem reads done
        unsigned pre; int cl;
        hist_select1<32>(key, K, s_hist, s_wsum, s_res, tid, wid, lane, pre, cl);
        unsigned T = pre << 19;
#pragma unroll
        for (int i = 0; i < 32; ++i) {
            int c = tid + i * 256;
            if (key[i] < T) atomicAdd(&s_cls[labels[b * NN + c]], 1u);
            else if ((key[i] >> 19) == pre) {
                unsigned p = atomicAdd(&s_n, 1u);
                if (p < 320) { s_skey[p] = key[i]; s_sidx[p] = c; }
            }
        }
        __syncthreads();
        int n = min(s_n, 320u), need = K - cl;
        for (int j = tid; j < n; j += 256) {
            unsigned kj = s_skey[j]; int ij = s_sidx[j], r = 0;
            for (int m = 0; m < n; ++m) {
                unsigned km = s_skey[m];
                r += (km < kj) || (km == kj && s_sidx[m] < ij);
            }
            if (r < need) atomicAdd(&s_cls[labels[b * NN + ij]], 1u);
        }
        __syncthreads();
        if (tid == 0) {
            int best = 0; unsigned bc = s_cls[0];
#pragma unroll
            for (int cc = 1; cc < 13; ++cc) if (s_cls[cc] > bc) { bc = s_cls[cc]; best = cc; }
            g_hard[off + b * Ni + qi] = best;
        }
        __syncthreads();  // protect s_cls/s_n reuse in next q
    }
}

// ---------------- boundary loss body ----------------
template <int CPT>
__device__ __forceinline__ void loss_body(const float* __restrict__ feat,
                                          int off, int Ni, int D, int stage,
                                          int chunk, int b, int Q, int NS1) {
    __shared__ unsigned s_hist[4096];
    __shared__ int s_wsum[8], s_res[2];
    __shared__ unsigned s_n, s_nbn;
    __shared__ unsigned s_skey[320];
    __shared__ int s_sidx[320];
    __shared__ int s_nb[35];
    __shared__ float s_fd[35];
    __shared__ int s_msk[35];
    int tid = threadIdx.x, wid = tid >> 5, lane = tid & 31;
    for (int q = 0; q < Q; ++q) {
        int qi = chunk * Q + q;
        if (qi >= Ni) break;
        if (tid == 0) { s_n = 0; s_nbn = 0; }
        float4 qc = g_pack[off + b * Ni + qi];
        unsigned key[CPT];
#pragma unroll
        for (int i = 0; i < CPT; ++i) {
            int c = tid + i * 256;
            if (c < Ni && c != qi) {
                float4 p = g_pack[off + b * Ni + c];
                float d2 = qc.w - 2.f * (qc.x * p.x + qc.y * p.y + qc.z * p.z) + p.w;
                key[i] = ordkey(d2);
            } else key[i] = 0xFFFFFFFFu;
        }
        __syncthreads();
        if (Ni <= 256) {
            // direct exact ranking: one candidate per thread, keys staged in smem
            s_hist[tid] = key[0];
            __syncthreads();
            unsigned myk = key[0];
            if (myk != 0xFFFFFFFFu) {
                int r = 0;
                for (int j = 0; j < Ni; ++j) {
                    unsigned kj = s_hist[j];
                    r += (kj < myk) || (kj == myk && j < tid);
                }
                if (r < NS1) s_nb[r] = tid;
            }
            __syncthreads();
        } else {
            unsigned pre; int cl;
            hist_select1<CPT>(key, NS1, s_hist, s_wsum, s_res, tid, wid, lane, pre, cl);
            unsigned T = pre << 19;
#pragma unroll
            for (int i = 0; i < CPT; ++i) {
                int c = tid + i * 256;
                if (key[i] < T) { unsigned p = atomicAdd(&s_nbn, 1u); s_nb[p] = c; }
                else if ((key[i] >> 19) == pre) {
                    unsigned p = atomicAdd(&s_n, 1u);
                    if (p < 320) { s_skey[p] = key[i]; s_sidx[p] = c; }
                }
            }
            __syncthreads();
            int n = min(s_n, 320u), need = NS1 - cl;
            for (int j = tid; j < n; j += 256) {
                unsigned kj = s_skey[j]; int ij = s_sidx[j], r = 0;
                for (int m = 0; m < n; ++m) {
                    unsigned km = s_skey[m];
                    r += (km < kj) || (km == kj && s_sidx[m] < ij);
                }
                if (r < need) { unsigned p = atomicAdd(&s_nbn, 1u); s_nb[p] = ij; }
            }
            __syncthreads();
        }
        // feature-space distances (loss is order-invariant over the neighbor set)
        int myh = g_hard[off + b * Ni + qi];
        const float4* fq = (const float4*)(feat + (size_t)(b * Ni + qi) * D);
        int D4 = D >> 2;
        for (int j = wid; j < NS1; j += 8) {
            int nb = s_nb[j];
            const float4* fn = (const float4*)(feat + (size_t)(b * Ni + nb) * D);
            float ss = 0.f;
            for (int d = lane; d < D4; d += 32) {
                float4 a = fq[d], z = fn[d];
                float dx = a.x - z.x, dy = a.y - z.y, dz = a.z - z.z, dw = a.w - z.w;
                ss += dx * dx + dy * dy + dz * dz + dw * dw;
            }
#pragma unroll
            for (int o = 16; o; o >>= 1) ss += __shfl_down_sync(0xFFFFFFFFu, ss, o);
            if (lane == 0) {
                s_fd[j] = sqrtf(ss + 1e-6f);
                s_msk[j] = (g_hard[off + b * Ni + nb] == myh) ? 1 : 0;
            }
        }
        __syncthreads();
        if (tid == 0) {
            float dmin = 3.0e38f; int cnt = 0;
            for (int j = 0; j < NS1; ++j) { dmin = fminf(dmin, s_fd[j]); cnt += s_msk[j]; }
            if (cnt > 0 && cnt < NS1) {
                float pos = 0.f, neg = 0.f;
                for (int j = 0; j < NS1; ++j) {
                    float e = expf(dmin - s_fd[j]);  // TEMPERATURE = 1
                    neg += e;
                    if (s_msk[j]) pos += e;
                }
                float l = -logf(pos / neg + 1e-6f);
                atomicAdd(&g_bl_sum[stage], (double)l);
                atomicAdd(&g_bl_cnt[stage], 1u);
            }
        }
        __syncthreads();  // protect smem reuse in next q
    }
}

__global__ __launch_bounds__(256) void loss0_kernel(const float* __restrict__ feat) {
    loss_body<32>(feat, 0, NN, 64, 0, blockIdx.x, blockIdx.y, 4, 35);
}

__global__ __launch_bounds__(256) void loss_fused(const float* __restrict__ f2,
                                                  const float* __restrict__ f3,
                                                  const float* __restrict__ f4,
                                                  const float* __restrict__ f5) {
    int bx = blockIdx.x;
    int s, chunk;
    if (bx < 512)      { s = 0; chunk = bx; }
    else if (bx < 768) { s = 1; chunk = bx - 512; }
    else if (bx < 896) { s = 2; chunk = bx - 768; }
    else               { s = 3; chunk = bx - 896; }
    const int NiA[4] = {2048, 512, 128, 32};
    const int DA[4]  = {128, 256, 512, 512};
    const int QA[4]  = {4, 2, 1, 1};
    const int OffA[4] = {16384, 20480, 21504, 21760};
    const float* F[4] = {f2, f3, f4, f5};
    loss_body<8>(F[s], OffA[s], NiA[s], DA[s], s + 1, chunk, blockIdx.y, QA[s], 23);
}

// ---------------- finalize ----------------
__global__ void finalize_kernel(float* out) {
    const int ns[5] = {8192, 2048, 512, 128, 32};
    double ce = g_ce_sum[0] / (double)(BB * NN);
    double o = 0.0;
    for (int j = 0; j < 5; ++j) o += g_ce_sum[1 + j] / (double)(BB * ns[j]);
    double bl = 0.0;
    for (int i = 0; i < 5; ++i) {
        double dn = g_bl_cnt[i] > 0 ? (double)g_bl_cnt[i] : 1.0;
        bl += g_bl_sum[i] / dn;
    }
    out[0] = (float)(ce + 0.1 * bl + 0.1 * o);
}

// ---------------- launch ----------------
extern "C" void kernel_launch(void* const* d_in, const int* in_sizes, int n_in,
                              void* d_out, int out_size) {
    (void)in_sizes; (void)n_in; (void)out_size;
    // 0:labels, 1..4:index2..5, 5:output, per stage j: 6+3j:pred, 7+3j:xyz, 8+3j:feat
    const int* labels = (const int*)d_in[0];
    const int* idx2 = (const int*)d_in[1];
    const int* idx3 = (const int*)d_in[2];
    const int* idx4 = (const int*)d_in[3];
    const int* idx5 = (const int*)d_in[4];
    const float* output = (const float*)d_in[5];
    const float* pred[5], *xyz[5], *feat[5];
    for (int j = 0; j < 5; ++j) {
        pred[j] = (const float*)d_in[6 + 3 * j];
        xyz[j]  = (const float*)d_in[7 + 3 * j];
        feat[j] = (const float*)d_in[8 + 3 * j];
    }

    zero_kernel<<<1, 32>>>();
    pack_kernel<<<(21824 + 255) / 256, 256>>>(xyz[0], xyz[1], xyz[2], xyz[3], xyz[4]);
    hard_copy<<<(BB * NN + 255) / 256, 256>>>(labels);

    hard_fused<<<dim3(736, BB), 256>>>(labels);
    ce_fused<<<150, 256>>>(output, pred[0], pred[1], pred[2], pred[3], pred[4],
                           labels, idx2, idx3, idx4, idx5);
    loss0_kernel<<<dim3(2048, BB), 256>>>(feat[0]);
    loss_fused<<<dim3(928, BB), 256>>>(feat[1], feat[2], feat[3], feat[4]);

    finalize_kernel<<<1, 1>>>((float*)d_out);
}

// round 8
// speedup vs baseline: 1615.4227x; 1.2173x over previous
#include <cuda_runtime.h>
#include <math.h>

#define BB 2
#define NN 8192

// Stage sizes: Ns = {8192,2048,512,128,32}, D = {64,128,256,512,512}
// nsample-1 = {35,23,23,23,23}, kneighbors = {1,4,16,64,256}
// offsets into g_hard/g_pack: {0,16384,20480,21504,21760}

__device__ double   g_ce_sum[6];
__device__ double   g_bl_sum[5];
__device__ unsigned g_bl_cnt[5];
__device__ int      g_hard[21824];
__device__ float4   g_pack[21824];

struct SelSmem {
    unsigned hist[4096];   // two 2048-bin halves (q0, q1)
    int      wsum[2][8];
    int      resbin[2], resbelow[2];
    unsigned n[2], nbn[2];
    unsigned cls[2][16];
    unsigned skey[2][320];
    int      sidx[2][320];
    int      nb[2][40];
    float    fd[2][40];
    int      msk[2][40];
};

__global__ void zero_kernel() {
    int t = threadIdx.x;
    if (t < 6) g_ce_sum[t] = 0.0;
    if (t < 5) { g_bl_sum[t] = 0.0; g_bl_cnt[t] = 0u; }
}

__global__ void pack_kernel(const float* __restrict__ x1, const float* __restrict__ x2,
                            const float* __restrict__ x3, const float* __restrict__ x4,
                            const float* __restrict__ x5) {
    int id = blockIdx.x * blockDim.x + threadIdx.x;
    if (id >= 21824) return;
    const int offs[6] = {0, 16384, 20480, 21504, 21760, 21824};
    const float* xs[5] = {x1, x2, x3, x4, x5};
    int s = 0;
    while (id >= offs[s + 1]) ++s;
    int r = id - offs[s];
    const float* p = xs[s] + (size_t)r * 3;
    float x = p[0], y = p[1], z = p[2];
    g_pack[id] = make_float4(x, y, z, x * x + y * y + z * z);
}

__global__ void hard_copy(const int* __restrict__ labels) {
    int r = blockIdx.x * blockDim.x + threadIdx.x;
    if (r < BB * NN) g_hard[r] = labels[r];
}

__device__ __forceinline__ unsigned ordkey(float f) {
    unsigned u = __float_as_uint(f);
    return (u & 0x80000000u) ? ~u : (u | 0x80000000u);
}

// ---------------- paired top-k body (512 threads, 2 queries per block) ----------------
template <int CPT, bool IS_LOSS>
__device__ __forceinline__ void pair_body(
        SelSmem& sm, int b, int pairIdx,
        int qoff, int Nq, int coff, int Ncand, int k,
        int stage, const float* __restrict__ feat, int D,
        const int* __restrict__ labels, bool selfex) {
    int tid = threadIdx.x, lane = tid & 31, wid = tid >> 5;
    int qi0 = pairIdx * 2, qi1 = qi0 + 1;
    float4 qc0 = g_pack[qoff + b * Nq + qi0];
    float4 qc1 = g_pack[qoff + b * Nq + qi1];
    const float4* cand = g_pack + coff + b * Ncand;
    unsigned key0[CPT], key1[CPT];
#pragma unroll
    for (int i = 0; i < CPT; ++i) {
        int c = tid + i * 512;
        float4 p = cand[c];
        float d0 = qc0.w - 2.f * (qc0.x * p.x + qc0.y * p.y + qc0.z * p.z) + p.w;
        float d1 = qc1.w - 2.f * (qc1.x * p.x + qc1.y * p.y + qc1.z * p.z) + p.w;
        key0[i] = ordkey(fmaxf(d0, 0.f));
        key1[i] = ordkey(fmaxf(d1, 0.f));
        if (selfex) {
            if (c == qi0) key0[i] = 0xFFFFFFFFu;
            if (c == qi1) key1[i] = 0xFFFFFFFFu;
        }
    }
    // zero hist + counters
    uint4* h4 = (uint4*)sm.hist;
    uint4 z4 = make_uint4(0, 0, 0, 0);
    h4[tid] = z4; h4[tid + 512] = z4;
    if (tid < 2) { sm.n[tid] = 0; sm.nbn[tid] = 0; }
    if (tid < 32) sm.cls[tid >> 4][tid & 15] = 0;
    __syncthreads();
#pragma unroll
    for (int i = 0; i < CPT; ++i) {
        if (key0[i] != 0xFFFFFFFFu) atomicAdd(&sm.hist[(key0[i] >> 20) & 0x7FFu], 1u);
        if (key1[i] != 0xFFFFFFFFu) atomicAdd(&sm.hist[2048u + ((key1[i] >> 20) & 0x7FFu)], 1u);
    }
    __syncthreads();
    // parallel half-scans: warps 0-7 -> q0, warps 8-15 -> q1
    {
        int sub = tid >> 8, t = tid & 255;
        const unsigned* h = sm.hist + sub * 2048;
        int base = t * 8, local = 0;
#pragma unroll
        for (int r = 0; r < 8; ++r) local += (int)h[base + r];
        int incl = local;
#pragma unroll
        for (int o = 1; o < 32; o <<= 1) {
            int tt = __shfl_up_sync(0xFFFFFFFFu, incl, o);
            if (lane >= o) incl += tt;
        }
        if (lane == 31) sm.wsum[sub][wid & 7] = incl;
        __syncthreads();
        int woff = 0;
#pragma unroll
        for (int w = 0; w < 8; ++w) woff += (w < (wid & 7)) ? sm.wsum[sub][w] : 0;
        int excl = woff + incl - local;
        if (excl < k && k <= excl + local) {
            int c2 = excl, bin = base;
#pragma unroll
            for (int r = 0; r < 8; ++r) {
                int hh = (int)h[base + r];
                if (c2 + hh >= k) { bin = base + r; break; }
                c2 += hh;
            }
            sm.resbin[sub] = bin; sm.resbelow[sub] = c2;
        }
        __syncthreads();
    }
    unsigned pre0 = (unsigned)sm.resbin[0] | 0x800u;
    unsigned pre1 = (unsigned)sm.resbin[1] | 0x800u;
    int cl0 = sm.resbelow[0], cl1 = sm.resbelow[1];
    unsigned T0 = pre0 << 20, T1 = pre1 << 20;
    // classify
#pragma unroll
    for (int i = 0; i < CPT; ++i) {
        int c = tid + i * 512;
        unsigned k0 = key0[i];
        if (k0 < T0) {
            if (IS_LOSS) { unsigned p = atomicAdd(&sm.nbn[0], 1u); sm.nb[0][p] = c; }
            else atomicAdd(&sm.cls[0][labels[b * NN + c]], 1u);
        } else if ((k0 >> 20) == pre0) {
            unsigned p = atomicAdd(&sm.n[0], 1u);
            if (p < 320) { sm.skey[0][p] = k0; sm.sidx[0][p] = c; }
        }
        unsigned k1 = key1[i];
        if (k1 < T1) {
            if (IS_LOSS) { unsigned p = atomicAdd(&sm.nbn[1], 1u); sm.nb[1][p] = c; }
            else atomicAdd(&sm.cls[1][labels[b * NN + c]], 1u);
        } else if ((k1 >> 20) == pre1) {
            unsigned p = atomicAdd(&sm.n[1], 1u);
            if (p < 320) { sm.skey[1][p] = k1; sm.sidx[1][p] = c; }
        }
    }
    __syncthreads();
    // exact-rank survivors (key,idx lexicographic == top_k tie-break)
    {
        int sub = tid >> 8, t = tid & 255;
        int n = min(sm.n[sub], 320u);
        int need = k - (sub ? cl1 : cl0);
        for (int j = t; j < n; j += 256) {
            unsigned kj = sm.skey[sub][j]; int ij = sm.sidx[sub][j], r = 0;
            for (int m = 0; m < n; ++m) {
                unsigned km = sm.skey[sub][m];
                r += (km < kj) || (km == kj && sm.sidx[sub][m] < ij);
            }
            if (r < need) {
                if (IS_LOSS) { unsigned p = atomicAdd(&sm.nbn[sub], 1u); sm.nb[sub][p] = ij; }
                else atomicAdd(&sm.cls[sub][labels[b * NN + ij]], 1u);
            }
        }
    }
    __syncthreads();
    if (!IS_LOSS) {
        if ((tid & 255) == 0) {
            int sub = tid >> 8;
            int best = 0; unsigned bc = sm.cls[sub][0];
#pragma unroll
            for (int cc = 1; cc < 13; ++cc)
                if (sm.cls[sub][cc] > bc) { bc = sm.cls[sub][cc]; best = cc; }
            g_hard[qoff + b * Nq + (sub ? qi1 : qi0)] = best;
        }
        return;
    }
    // feature distances: warps 0-7 -> q0, warps 8-15 -> q1
    {
        int sub = wid >> 3, w8 = wid & 7;
        int qi = sub ? qi1 : qi0;
        int hb = qoff + b * Nq;
        int myh = g_hard[hb + qi];
        const float4* fq = (const float4*)(feat + (size_t)(b * Nq + qi) * D);
        int D4 = D >> 2;
        for (int j = w8; j < k; j += 8) {
            int nbi = sm.nb[sub][j];
            const float4* fn = (const float4*)(feat + (size_t)(b * Nq + nbi) * D);
            float ss = 0.f;
            for (int d = lane; d < D4; d += 32) {
                float4 a = fq[d], z = fn[d];
                float dx = a.x - z.x, dy = a.y - z.y, dz = a.z - z.z, dw = a.w - z.w;
                ss += dx * dx + dy * dy + dz * dz + dw * dw;
            }
#pragma unroll
            for (int o = 16; o; o >>= 1) ss += __shfl_down_sync(0xFFFFFFFFu, ss, o);
            if (lane == 0) {
                sm.fd[sub][j] = sqrtf(ss + 1e-6f);
                sm.msk[sub][j] = (g_hard[hb + nbi] == myh) ? 1 : 0;
            }
        }
    }
    __syncthreads();
    if ((tid & 255) == 0) {
        int sub = tid >> 8;
        float dmin = 3.0e38f; int cnt = 0;
        for (int j = 0; j < k; ++j) { dmin = fminf(dmin, sm.fd[sub][j]); cnt += sm.msk[sub][j]; }
        if (cnt > 0 && cnt < k) {
            float pos = 0.f, neg = 0.f;
            for (int j = 0; j < k; ++j) {
                float e = expf(dmin - sm.fd[sub][j]);  // TEMPERATURE = 1
                neg += e;
                if (sm.msk[sub][j]) pos += e;
            }
            atomicAdd(&g_bl_sum[stage], (double)(-logf(pos / neg + 1e-6f)));
            atomicAdd(&g_bl_cnt[stage], 1u);
        }
    }
}

// ---------------- kernel A: loss0 + hard s1..s4 + CE ----------------
__global__ __launch_bounds__(512, 2) void kernelA(
        const float* __restrict__ feat1, const int* __restrict__ labels,
        const float* __restrict__ lg0, const float* __restrict__ lg1,
        const float* __restrict__ lg2, const float* __restrict__ lg3,
        const float* __restrict__ lg4, const float* __restrict__ lg5,
        const int* __restrict__ i2, const int* __restrict__ i3,
        const int* __restrict__ i4, const int* __restrict__ i5) {
    __shared__ SelSmem sm;
    int bx = blockIdx.x, b = blockIdx.y;
    if (bx < 4096) {
        pair_body<16, true>(sm, b, bx, 0, 8192, 0, 8192, 35, 0, feat1, 64, labels, true);
    } else if (bx < 5120) {
        pair_body<16, false>(sm, b, bx - 4096, 16384, 2048, 0, 8192, 4, 0, nullptr, 0, labels, false);
    } else if (bx < 5376) {
        pair_body<16, false>(sm, b, bx - 5120, 20480, 512, 0, 8192, 16, 0, nullptr, 0, labels, false);
    } else if (bx < 5440) {
        pair_body<16, false>(sm, b, bx - 5376, 21504, 128, 0, 8192, 64, 0, nullptr, 0, labels, false);
    } else if (bx < 5456) {
        pair_body<16, false>(sm, b, bx - 5440, 21760, 32, 0, 8192, 256, 0, nullptr, 0, labels, false);
    } else {
        // cross entropy: one row per thread
        const int cum[7] = {0, 16384, 32768, 36864, 37888, 38144, 38208};
        int chunk = bx - 5456;
        int r = (chunk * 2 + b) * 512 + threadIdx.x;
        int job = 0;
        float l = 0.f;
        if (r < 38208) {
#pragma unroll
            for (int j = 1; j < 6; ++j) if (r >= cum[j]) job = j;
            const float* L[6] = {lg0, lg1, lg2, lg3, lg4, lg5};
            const int*   G[6] = {nullptr, nullptr, i2, i3, i4, i5};
            const int   lgn[6] = {13, 13, 11, 9, 7, 5};
            int lr = r - cum[job];
            int bb = lr >> lgn[job];
            const int* g = G[job];
            int lab = g ? labels[bb * NN + g[lr]] : labels[lr];
            const float* row = L[job] + (size_t)lr * 13;
            float v[13];
#pragma unroll
            for (int c = 0; c < 13; ++c) v[c] = row[c];
            float m = v[0];
#pragma unroll
            for (int c = 1; c < 13; ++c) m = fmaxf(m, v[c]);
            float s = 0.f;
#pragma unroll
            for (int c = 0; c < 13; ++c) s += expf(v[c] - m);
            l = (m + logf(s)) - v[lab];
        }
#pragma unroll
        for (int o = 16; o; o >>= 1) l += __shfl_down_sync(0xFFFFFFFFu, l, o);
        // job is warp-uniform (all cum[] are multiples of 256)
        if ((threadIdx.x & 31) == 0 && l != 0.f) atomicAdd(&g_ce_sum[job], (double)l);
    }
}

// ---------------- kernels B/C: losses for stages 1, 2 ----------------
__global__ __launch_bounds__(512, 2) void kernelB(const float* __restrict__ feat2,
                                                  const int* __restrict__ labels) {
    __shared__ SelSmem sm;
    pair_body<4, true>(sm, blockIdx.y, blockIdx.x, 16384, 2048, 16384, 2048, 23, 1,
                       feat2, 128, labels, true);
}

__global__ __launch_bounds__(512, 2) void kernelC(const float* __restrict__ feat3,
                                                  const int* __restrict__ labels) {
    __shared__ SelSmem sm;
    pair_body<1, true>(sm, blockIdx.y, blockIdx.x, 20480, 512, 20480, 512, 23, 2,
                       feat3, 256, labels, true);
}

// ---------------- kernel D: direct-rank losses for stages 3, 4 ----------------
__global__ __launch_bounds__(512) void kernelD(const float* __restrict__ f4,
                                               const float* __restrict__ f5) {
    __shared__ unsigned s_key[512];
    __shared__ int s_nb[23];
    __shared__ float s_fd[23];
    __shared__ int s_msk[23];
    int bx = blockIdx.x, b = blockIdx.y;
    int tid = threadIdx.x, lane = tid & 31, wid = tid >> 5;
    int stage, Ni, off, qi; const float* feat;
    if (bx < 128) { stage = 3; Ni = 128; off = 21504; feat = f4; qi = bx; }
    else          { stage = 4; Ni = 32;  off = 21760; feat = f5; qi = bx - 128; }
    const int D = 512, D4 = 128;
    float4 qc = g_pack[off + b * Ni + qi];
    unsigned myk = 0xFFFFFFFFu;
    if (tid < Ni && tid != qi) {
        float4 p = g_pack[off + b * Ni + tid];
        float d2 = qc.w - 2.f * (qc.x * p.x + qc.y * p.y + qc.z * p.z) + p.w;
        myk = ordkey(fmaxf(d2, 0.f));
    }
    s_key[tid] = myk;
    __syncthreads();
    if (myk != 0xFFFFFFFFu) {
        int r = 0;
        for (int j = 0; j < Ni; ++j) {
            unsigned kj = s_key[j];
            r += (kj < myk) || (kj == myk && j < tid);
        }
        if (r < 23) s_nb[r] = tid;
    }
    __syncthreads();
    int myh = g_hard[off + b * Ni + qi];
    const float4* fq = (const float4*)(feat + (size_t)(b * Ni + qi) * D);
    for (int j = wid; j < 23; j += 16) {
        int nbi = s_nb[j];
        const float4* fn = (const float4*)(feat + (size_t)(b * Ni + nbi) * D);
        float ss = 0.f;
        for (int d = lane; d < D4; d += 32) {
            float4 a = fq[d], z = fn[d];
            float dx = a.x - z.x, dy = a.y - z.y, dz = a.z - z.z, dw = a.w - z.w;
            ss += dx * dx + dy * dy + dz * dz + dw * dw;
        }
#pragma unroll
        for (int o = 16; o; o >>= 1) ss += __shfl_down_sync(0xFFFFFFFFu, ss, o);
        if (lane == 0) {
            s_fd[j] = sqrtf(ss + 1e-6f);
            s_msk[j] = (g_hard[off + b * Ni + nbi] == myh) ? 1 : 0;
        }
    }
    __syncthreads();
    if (tid == 0) {
        float dmin = 3.0e38f; int cnt = 0;
        for (int j = 0; j < 23; ++j) { dmin = fminf(dmin, s_fd[j]); cnt += s_msk[j]; }
        if (cnt > 0 && cnt < 23) {
            float pos = 0.f, neg = 0.f;
            for (int j = 0; j < 23; ++j) {
                float e = expf(dmin - s_fd[j]);
                neg += e;
                if (s_msk[j]) pos += e;
            }
            atomicAdd(&g_bl_sum[stage], (double)(-logf(pos / neg + 1e-6f)));
            atomicAdd(&g_bl_cnt[stage], 1u);
        }
    }
}

// ---------------- finalize ----------------
__global__ void finalize_kernel(float* out) {
    const int ns[5] = {8192, 2048, 512, 128, 32};
    double ce = g_ce_sum[0] / (double)(BB * NN);
    double o = 0.0;
    for (int j = 0; j < 5; ++j) o += g_ce_sum[1 + j] / (double)(BB * ns[j]);
    double bl = 0.0;
    for (int i = 0; i < 5; ++i) {
        double dn = g_bl_cnt[i] > 0 ? (double)g_bl_cnt[i] : 1.0;
        bl += g_bl_sum[i] / dn;
    }
    out[0] = (float)(ce + 0.1 * bl + 0.1 * o);
}

// ---------------- launch ----------------
extern "C" void kernel_launch(void* const* d_in, const int* in_sizes, int n_in,
                              void* d_out, int out_size) {
    (void)in_sizes; (void)n_in; (void)out_size;
    // 0:labels, 1..4:index2..5, 5:output, per stage j: 6+3j:pred, 7+3j:xyz, 8+3j:feat
    const int* labels = (const int*)d_in[0];
    const int* idx2 = (const int*)d_in[1];
    const int* idx3 = (const int*)d_in[2];
    const int* idx4 = (const int*)d_in[3];
    const int* idx5 = (const int*)d_in[4];
    const float* output = (const float*)d_in[5];
    const float* pred[5], *xyz[5], *feat[5];
    for (int j = 0; j < 5; ++j) {
        pred[j] = (const float*)d_in[6 + 3 * j];
        xyz[j]  = (const float*)d_in[7 + 3 * j];
        feat[j] = (const float*)d_in[8 + 3 * j];
    }

    zero_kernel<<<1, 32>>>();
    pack_kernel<<<86, 256>>>(xyz[0], xyz[1], xyz[2], xyz[3], xyz[4]);
    hard_copy<<<64, 256>>>(labels);

    kernelA<<<dim3(5494, BB), 512>>>(feat[0], labels,
                                     output, pred[0], pred[1], pred[2], pred[3], pred[4],
                                     idx2, idx3, idx4, idx5);
    kernelB<<<dim3(1024, BB), 512>>>(feat[1], labels);
    kernelC<<<dim3(256, BB), 512>>>(feat[2], labels);
    kernelD<<<dim3(160, BB), 512>>>(feat[3], feat[4]);

    finalize_kernel<<<1, 1>>>((float*)d_out);
}

// round 10
// speedup vs baseline: 1675.6025x; 1.0373x over previous
#include <cuda_runtime.h>
#include <math.h>

#define BB 2
#define NN 8192

// Ns = {8192,2048,512,128,32}, D = {64,128,256,512,512}
// nsample-1 = {35,23,23,23,23}, kneighbors = {1,4,16,64,256}
// offsets into g_hard/g_pack: {0,16384,20480,21504,21760}

__device__ double   g_ce_sum[6];
__device__ double   g_bl_sum[5];
__device__ unsigned g_bl_cnt[5];
__device__ int      g_hard[21824];
__device__ float4   g_pack[21824];

struct QSmem {
    unsigned hist[4096];     // 4 queries x 1024 bins
    int      wsum[4][4];
    int      resbin[4], resbelow[4];
    unsigned n[4], nbn[4];
    unsigned cls[4][16];
    unsigned skey[4][256];
    int      sidx[4][256];
    int      nb[4][36];
    float    fd[4][36];
    int      msk[4][36];
};

__global__ void zero_kernel() {
    int t = threadIdx.x;
    if (t < 6) g_ce_sum[t] = 0.0;
    if (t < 5) { g_bl_sum[t] = 0.0; g_bl_cnt[t] = 0u; }
}

__global__ void pack_kernel(const float* __restrict__ x1, const float* __restrict__ x2,
                            const float* __restrict__ x3, const float* __restrict__ x4,
                            const float* __restrict__ x5) {
    int id = blockIdx.x * blockDim.x + threadIdx.x;
    if (id >= 21824) return;
    const int offs[6] = {0, 16384, 20480, 21504, 21760, 21824};
    const float* xs[5] = {x1, x2, x3, x4, x5};
    int s = 0;
    while (id >= offs[s + 1]) ++s;
    int r = id - offs[s];
    const float* p = xs[s] + (size_t)r * 3;
    float x = p[0], y = p[1], z = p[2];
    g_pack[id] = make_float4(x, y, z, x * x + y * y + z * z);
}

__global__ void hard_copy(const int* __restrict__ labels) {
    int r = blockIdx.x * blockDim.x + threadIdx.x;
    if (r < BB * NN) g_hard[r] = labels[r];
}

// pinned arithmetic: identical in histogram and classify passes
__device__ __forceinline__ float dist2(float4 q, float4 p) {
    float s = q.z * p.z;
    s = __fmaf_rn(q.y, p.y, s);
    s = __fmaf_rn(q.x, p.x, s);
    return __fmaf_rn(-2.f, s, q.w + p.w);
}

// ---------------- quad top-k body (512 threads, 4 queries per block) ----------------
template <int CPT, bool IS_LOSS>
__device__ __forceinline__ void quad_body(
        QSmem& sm, int b, int quad, int qoff, int Nq, int coff, int Ncand,
        int k, int stage, const float* __restrict__ feat, int D,
        const int* __restrict__ labels, bool selfex) {
    int tid = threadIdx.x, lane = tid & 31, wid = tid >> 5;
    int qbase = quad * 4;
    float4 qc[4];
#pragma unroll
    for (int q = 0; q < 4; ++q) qc[q] = g_pack[qoff + b * Nq + qbase + q];
    const float4* cand = g_pack + coff + b * Ncand;

    uint4* h4 = (uint4*)sm.hist;
    uint4 z4 = make_uint4(0, 0, 0, 0);
    h4[tid] = z4; h4[tid + 512] = z4;
    if (tid < 4) { sm.n[tid] = 0; sm.nbn[tid] = 0; }
    if (tid >= 32 && tid < 96) sm.cls[(tid - 32) >> 4][(tid - 32) & 15] = 0;
    __syncthreads();

    // pass 1: histogram bins (bits 30..21 of clamped d2)
#pragma unroll
    for (int i = 0; i < CPT; ++i) {
        int c = tid + i * 512;
        float4 p = cand[c];
#pragma unroll
        for (int q = 0; q < 4; ++q) {
            if (selfex && c == qbase + q) continue;
            unsigned bin = __float_as_uint(fmaxf(dist2(qc[q], p), 0.f)) >> 21;
            atomicAdd(&sm.hist[(q << 10) + bin], 1u);
        }
    }
    __syncthreads();

    // scan: 4 groups of 128 threads, one per query
    {
        int g = tid >> 7, t = tid & 127, wig = (tid >> 5) & 3;
        const unsigned* h = sm.hist + (g << 10);
        int base = t * 8, local = 0;
#pragma unroll
        for (int r = 0; r < 8; ++r) local += (int)h[base + r];
        int incl = local;
#pragma unroll
        for (int o = 1; o < 32; o <<= 1) {
            int tt = __shfl_up_sync(0xFFFFFFFFu, incl, o);
            if (lane >= o) incl += tt;
        }
        if (lane == 31) sm.wsum[g][wig] = incl;
        __syncthreads();
        int woff = 0;
#pragma unroll
        for (int w = 0; w < 4; ++w) woff += (w < wig) ? sm.wsum[g][w] : 0;
        int excl = woff + incl - local;
        if (excl < k && k <= excl + local) {
            int c2 = excl, bin = base;
#pragma unroll
            for (int r = 0; r < 8; ++r) {
                int hh = (int)h[base + r];
                if (c2 + hh >= k) { bin = base + r; break; }
                c2 += hh;
            }
            sm.resbin[g] = bin; sm.resbelow[g] = c2;
        }
        __syncthreads();
    }
    unsigned rb[4];
#pragma unroll
    for (int q = 0; q < 4; ++q) rb[q] = (unsigned)sm.resbin[q];

    // pass 2: recompute + classify (dist2 is bitwise identical to pass 1)
#pragma unroll
    for (int i = 0; i < CPT; ++i) {
        int c = tid + i * 512;
        float4 p = cand[c];
#pragma unroll
        for (int q = 0; q < 4; ++q) {
            if (selfex && c == qbase + q) continue;
            unsigned key = __float_as_uint(fmaxf(dist2(qc[q], p), 0.f));
            unsigned bin = key >> 21;
            if (bin < rb[q]) {
                if (IS_LOSS) { unsigned pp = atomicAdd(&sm.nbn[q], 1u); sm.nb[q][pp] = c; }
                else atomicAdd(&sm.cls[q][labels[b * NN + c]], 1u);
            } else if (bin == rb[q]) {
                unsigned pp = atomicAdd(&sm.n[q], 1u);
                if (pp < 256) { sm.skey[q][pp] = key; sm.sidx[q][pp] = c; }
            }
        }
    }
    __syncthreads();

    // exact-rank survivors: (key, idx) lexicographic == jax top_k tie-break
    {
        int g = tid >> 7, t = tid & 127;
        int n = min(sm.n[g], 256u);
        int need = k - sm.resbelow[g];
        for (int j = t; j < n; j += 128) {
            unsigned kj = sm.skey[g][j]; int ij = sm.sidx[g][j], r = 0;
            for (int m = 0; m < n; ++m) {
                unsigned km = sm.skey[g][m];
                r += (km < kj) || (km == kj && sm.sidx[g][m] < ij);
            }
            if (r < need) {
                if (IS_LOSS) { unsigned pp = atomicAdd(&sm.nbn[g], 1u); sm.nb[g][pp] = ij; }
                else atomicAdd(&sm.cls[g][labels[b * NN + ij]], 1u);
            }
        }
    }
    __syncthreads();

    if (!IS_LOSS) {
        if ((tid & 127) == 0) {
            int g = tid >> 7;
            int best = 0; unsigned bc = sm.cls[g][0];
#pragma unroll
            for (int cc = 1; cc < 13; ++cc)
                if (sm.cls[g][cc] > bc) { bc = sm.cls[g][cc]; best = cc; }
            g_hard[qoff + b * Nq + qbase + g] = best;
        }
        return;
    }

    // feature distances: 4 warps per query
    {
        int g = wid >> 2, w4 = wid & 3;
        int qi = qbase + g;
        int hb = qoff + b * Nq;
        int myh = g_hard[hb + qi];
        const float4* fq = (const float4*)(feat + (size_t)(b * Nq + qi) * D);
        int D4 = D >> 2;
        for (int j = w4; j < k; j += 4) {
            int nbi = sm.nb[g][j];
            const float4* fn = (const float4*)(feat + (size_t)(b * Nq + nbi) * D);
            float ss = 0.f;
            for (int d = lane; d < D4; d += 32) {
                float4 a = fq[d], z = fn[d];
                float dx = a.x - z.x, dy = a.y - z.y, dz = a.z - z.z, dw = a.w - z.w;
                ss += dx * dx + dy * dy + dz * dz + dw * dw;
            }
#pragma unroll
            for (int o = 16; o; o >>= 1) ss += __shfl_down_sync(0xFFFFFFFFu, ss, o);
            if (lane == 0) {
                sm.fd[g][j] = sqrtf(ss + 1e-6f);
                sm.msk[g][j] = (g_hard[hb + nbi] == myh) ? 1 : 0;
            }
        }
    }
    __syncthreads();
    if ((tid & 127) == 0) {
        int g = tid >> 7;
        float dmin = 3.0e38f; int cnt = 0;
        for (int j = 0; j < k; ++j) { dmin = fminf(dmin, sm.fd[g][j]); cnt += sm.msk[g][j]; }
        if (cnt > 0 && cnt < k) {
            float pos = 0.f, neg = 0.f;
            for (int j = 0; j < k; ++j) {
                float e = expf(dmin - sm.fd[g][j]);  // TEMPERATURE = 1
                neg += e;
                if (sm.msk[g][j]) pos += e;
            }
            atomicAdd(&g_bl_sum[stage], (double)(-logf(pos / neg + 1e-6f)));
            atomicAdd(&g_bl_cnt[stage], 1u);
        }
    }
}

// ---------------- kernel H: hard labels stages 1..4 ----------------
__global__ __launch_bounds__(512, 2) void kernelH(const int* __restrict__ labels) {
    __shared__ QSmem sm;
    int bx = blockIdx.x, b = blockIdx.y;
    if (bx < 512)
        quad_body<16, false>(sm, b, bx, 16384, 2048, 0, 8192, 4, 0, nullptr, 0, labels, false);
    else if (bx < 640)
        quad_body<16, false>(sm, b, bx - 512, 20480, 512, 0, 8192, 16, 0, nullptr, 0, labels, false);
    else if (bx < 672)
        quad_body<16, false>(sm, b, bx - 640, 21504, 128, 0, 8192, 64, 0, nullptr, 0, labels, false);
    else
        quad_body<16, false>(sm, b, bx - 672, 21760, 32, 0, 8192, 256, 0, nullptr, 0, labels, false);
}

// ---------------- kernel L: all boundary losses + CE (single shared QSmem) ----------------
__global__ __launch_bounds__(512, 2) void kernelL(
        const float* __restrict__ f1, const float* __restrict__ f2,
        const float* __restrict__ f3, const float* __restrict__ f4,
        const float* __restrict__ f5, const int* __restrict__ labels,
        const float* __restrict__ lg0, const float* __restrict__ lg1,
        const float* __restrict__ lg2, const float* __restrict__ lg3,
        const float* __restrict__ lg4, const float* __restrict__ lg5,
        const int* __restrict__ i2, const int* __restrict__ i3,
        const int* __restrict__ i4, const int* __restrict__ i5) {
    __shared__ QSmem sm;
    int bx = blockIdx.x, b = blockIdx.y;
    if (bx < 2048) {
        quad_body<16, true>(sm, b, bx, 0, 8192, 0, 8192, 35, 0, f1, 64, nullptr, true);
    } else if (bx < 2560) {
        quad_body<4, true>(sm, b, bx - 2048, 16384, 2048, 16384, 2048, 23, 1, f2, 128, nullptr, true);
    } else if (bx < 2688) {
        quad_body<1, true>(sm, b, bx - 2560, 20480, 512, 20480, 512, 23, 2, f3, 256, nullptr, true);
    } else if (bx < 2848) {
        // direct-rank losses for stages 3, 4 (one query per block); reuse sm storage
        unsigned* s_key = sm.hist;          // 512 words
        int*      s_nb  = sm.nb[0];         // 23 ints
        float*    s_fd  = sm.fd[0];
        int*      s_msk = sm.msk[0];
        int bi = bx - 2688;
        int tid = threadIdx.x, lane = tid & 31, wid = tid >> 5;
        int stage, Ni, off, qi; const float* feat;
        if (bi < 128) { stage = 3; Ni = 128; off = 21504; feat = f4; qi = bi; }
        else          { stage = 4; Ni = 32;  off = 21760; feat = f5; qi = bi - 128; }
        const int D = 512, D4 = 128;
        float4 qc = g_pack[off + b * Ni + qi];
        unsigned myk = 0xFFFFFFFFu;
        if (tid < Ni && tid != qi) {
            float4 p = g_pack[off + b * Ni + tid];
            myk = __float_as_uint(fmaxf(dist2(qc, p), 0.f));
        }
        s_key[tid] = myk;
        __syncthreads();
        if (myk != 0xFFFFFFFFu) {
            int r = 0;
            for (int j = 0; j < Ni; ++j) {
                unsigned kj = s_key[j];
                r += (kj < myk) || (kj == myk && j < tid);
            }
            if (r < 23) s_nb[r] = tid;
        }
        __syncthreads();
        int myh = g_hard[off + b * Ni + qi];
        const float4* fq = (const float4*)(feat + (size_t)(b * Ni + qi) * D);
        for (int j = wid; j < 23; j += 16) {
            int nbi = s_nb[j];
            const float4* fn = (const float4*)(feat + (size_t)(b * Ni + nbi) * D);
            float ss = 0.f;
            for (int d = lane; d < D4; d += 32) {
                float4 a = fq[d], z = fn[d];
                float dx = a.x - z.x, dy = a.y - z.y, dz = a.z - z.z, dw = a.w - z.w;
                ss += dx * dx + dy * dy + dz * dz + dw * dw;
            }
#pragma unroll
            for (int o = 16; o; o >>= 1) ss += __shfl_down_sync(0xFFFFFFFFu, ss, o);
            if (lane == 0) {
                s_fd[j] = sqrtf(ss + 1e-6f);
                s_msk[j] = (g_hard[off + b * Ni + nbi] == myh) ? 1 : 0;
            }
        }
        __syncthreads();
        if (tid == 0) {
            float dmin = 3.0e38f; int cnt = 0;
            for (int j = 0; j < 23; ++j) { dmin = fminf(dmin, s_fd[j]); cnt += s_msk[j]; }
            if (cnt > 0 && cnt < 23) {
                float pos = 0.f, neg = 0.f;
                for (int j = 0; j < 23; ++j) {
                    float e = expf(dmin - s_fd[j]);
                    neg += e;
                    if (s_msk[j]) pos += e;
                }
                atomicAdd(&g_bl_sum[stage], (double)(-logf(pos / neg + 1e-6f)));
                atomicAdd(&g_bl_cnt[stage], 1u);
            }
        }
    } else {
        // cross entropy: one row per thread
        const int cum[7] = {0, 16384, 32768, 36864, 37888, 38144, 38208};
        int chunk = bx - 2848;
        int r = (chunk * 2 + b) * 512 + threadIdx.x;
        int job = 0;
        float l = 0.f;
        if (r < 38208) {
#pragma unroll
            for (int j = 1; j < 6; ++j) if (r >= cum[j]) job = j;
            const float* L[6] = {lg0, lg1, lg2, lg3, lg4, lg5};
            const int*   G[6] = {nullptr, nullptr, i2, i3, i4, i5};
            const int   lgn[6] = {13, 13, 11, 9, 7, 5};
            int lr = r - cum[job];
            int bb = lr >> lgn[job];
            const int* g = G[job];
            int lab = g ? labels[bb * NN + g[lr]] : labels[lr];
            const float* row = L[job] + (size_t)lr * 13;
            float v[13];
#pragma unroll
            for (int c = 0; c < 13; ++c) v[c] = row[c];
            float m = v[0];
#pragma unroll
            for (int c = 1; c < 13; ++c) m = fmaxf(m, v[c]);
            float s = 0.f;
#pragma unroll
            for (int c = 0; c < 13; ++c) s += expf(v[c] - m);
            l = (m + logf(s)) - v[lab];
        }
#pragma unroll
        for (int o = 16; o; o >>= 1) l += __shfl_down_sync(0xFFFFFFFFu, l, o);
        if ((threadIdx.x & 31) == 0 && l != 0.f) atomicAdd(&g_ce_sum[job], (double)l);
    }
}

// ---------------- finalize ----------------
__global__ void finalize_kernel(float* out) {
    const int ns[5] = {8192, 2048, 512, 128, 32};
    double ce = g_ce_sum[0] / (double)(BB * NN);
    double o = 0.0;
    for (int j = 0; j < 5; ++j) o += g_ce_sum[1 + j] / (double)(BB * ns[j]);
    double bl = 0.0;
    for (int i = 0; i < 5; ++i) {
        double dn = g_bl_cnt[i] > 0 ? (double)g_bl_cnt[i] : 1.0;
        bl += g_bl_sum[i] / dn;
    }
    out[0] = (float)(ce + 0.1 * bl + 0.1 * o);
}

// ---------------- launch ----------------
extern "C" void kernel_launch(void* const* d_in, const int* in_sizes, int n_in,
                              void* d_out, int out_size) {
    (void)in_sizes; (void)n_in; (void)out_size;
    // 0:labels, 1..4:index2..5, 5:output, per stage j: 6+3j:pred, 7+3j:xyz, 8+3j:feat
    const int* labels = (const int*)d_in[0];
    const int* idx2 = (const int*)d_in[1];
    const int* idx3 = (const int*)d_in[2];
    const int* idx4 = (const int*)d_in[3];
    const int* idx5 = (const int*)d_in[4];
    const float* output = (const float*)d_in[5];
    const float* pred[5], *xyz[5], *feat[5];
    for (int j = 0; j < 5; ++j) {
        pred[j] = (const float*)d_in[6 + 3 * j];
        xyz[j]  = (const float*)d_in[7 + 3 * j];
        feat[j] = (const float*)d_in[8 + 3 * j];
    }

    zero_kernel<<<1, 32>>>();
    pack_kernel<<<86, 256>>>(xyz[0], xyz[1], xyz[2], xyz[3], xyz[4]);
    hard_copy<<<64, 256>>>(labels);

    kernelH<<<dim3(680, BB), 512>>>(labels);
    kernelL<<<dim3(2886, BB), 512>>>(feat[0], feat[1], feat[2], feat[3], feat[4], labels,
                                     output, pred[0], pred[1], pred[2], pred[3], pred[4],
                                     idx2, idx3, idx4, idx5);

    finalize_kernel<<<1, 1>>>((float*)d_out);
}

// round 11
// speedup vs baseline: 1771.5339x; 1.0573x over previous
#include <cuda_runtime.h>
#include <math.h>

#define BB 2
#define NN 8192

// Ns = {8192,2048,512,128,32}, D = {64,128,256,512,512}
// nsample-1 = {35,23,23,23,23}, kneighbors = {1,4,16,64,256}
// offsets into g_hard/g_pack: {0,16384,20480,21504,21760}

__device__ double   g_ce_sum[6];
__device__ double   g_bl_sum[5];
__device__ unsigned g_bl_cnt[5];
__device__ int      g_hard[21824];
__device__ float4   g_pack[21824];

struct QSmem {                // quad: 4 queries x 1024 bins
    unsigned hist[4096];
    int      wsum[4][4];
    int      resbin[4], resbelow[4];
    unsigned n[4], nbn[4];
    unsigned cls[4][16];
    unsigned skey[4][256];
    int      sidx[4][256];
    int      nb[4][36];
    float    fd[4][36];
    int      msk[4][36];
};
struct OSmem {                // octo: 8 queries x 512 bins
    unsigned hist[4096];
    int      wsum[8][2];
    int      resbin[8], resbelow[8];
    unsigned n[8], nbn[8];
    unsigned cls[8][16];
    unsigned skey[8][128];
    int      sidx[8][128];
    int      nb[8][36];
    float    fd[8][36];
    int      msk[8][36];
};
union USmem { QSmem q; OSmem o; };

// ---------------- prep: zero accumulators, copy labels, pack coords ----------------
__global__ void prep_kernel(const float* __restrict__ x1, const float* __restrict__ x2,
                            const float* __restrict__ x3, const float* __restrict__ x4,
                            const float* __restrict__ x5, const int* __restrict__ labels) {
    int id = blockIdx.x * blockDim.x + threadIdx.x;
    if (id < 6) g_ce_sum[id] = 0.0;
    if (id >= 8 && id < 13) { g_bl_sum[id - 8] = 0.0; g_bl_cnt[id - 8] = 0u; }
    if (id < BB * NN) g_hard[id] = labels[id];
    if (id < 21824) {
        const int offs[6] = {0, 16384, 20480, 21504, 21760, 21824};
        const float* xs[5] = {x1, x2, x3, x4, x5};
        int s = 0;
        while (id >= offs[s + 1]) ++s;
        int r = id - offs[s];
        const float* p = xs[s] + (size_t)r * 3;
        float x = p[0], y = p[1], z = p[2];
        g_pack[id] = make_float4(x, y, z, x * x + y * y + z * z);
    }
}

// pinned arithmetic: identical across passes
__device__ __forceinline__ float dist2(float4 q, float4 p) {
    float s = q.z * p.z;
    s = __fmaf_rn(q.y, p.y, s);
    s = __fmaf_rn(q.x, p.x, s);
    return __fmaf_rn(-2.f, s, q.w + p.w);
}

// ---------------- quad body: 4 queries, 1024 bins (k=256 path) ----------------
template <int CPT, bool IS_LOSS>
__device__ __forceinline__ void quad_body(
        QSmem& sm, int b, int quad, int qoff, int Nq, int coff, int Ncand,
        int k, int stage, const float* __restrict__ feat, int D,
        const int* __restrict__ labels, bool selfex) {
    int tid = threadIdx.x, lane = tid & 31, wid = tid >> 5;
    int qbase = quad * 4;
    float4 qc[4];
#pragma unroll
    for (int q = 0; q < 4; ++q) qc[q] = g_pack[qoff + b * Nq + qbase + q];
    const float4* cand = g_pack + coff + b * Ncand;

    uint4* h4 = (uint4*)sm.hist;
    uint4 z4 = make_uint4(0, 0, 0, 0);
    h4[tid] = z4; h4[tid + 512] = z4;
    if (tid < 4) { sm.n[tid] = 0; sm.nbn[tid] = 0; }
    if (tid >= 32 && tid < 96) sm.cls[(tid - 32) >> 4][(tid - 32) & 15] = 0;
    __syncthreads();
#pragma unroll
    for (int i = 0; i < CPT; ++i) {
        int c = tid + i * 512;
        float4 p = cand[c];
#pragma unroll
        for (int q = 0; q < 4; ++q) {
            if (selfex && c == qbase + q) continue;
            unsigned bin = __float_as_uint(fmaxf(dist2(qc[q], p), 0.f)) >> 21;
            atomicAdd(&sm.hist[(q << 10) + bin], 1u);
        }
    }
    __syncthreads();
    {
        int g = tid >> 7, t = tid & 127, wig = (tid >> 5) & 3;
        const unsigned* h = sm.hist + (g << 10);
        int base = t * 8, local = 0;
#pragma unroll
        for (int r = 0; r < 8; ++r) local += (int)h[base + r];
        int incl = local;
#pragma unroll
        for (int o = 1; o < 32; o <<= 1) {
            int tt = __shfl_up_sync(0xFFFFFFFFu, incl, o);
            if (lane >= o) incl += tt;
        }
        if (lane == 31) sm.wsum[g][wig] = incl;
        __syncthreads();
        int woff = 0;
#pragma unroll
        for (int w = 0; w < 4; ++w) woff += (w < wig) ? sm.wsum[g][w] : 0;
        int excl = woff + incl - local;
        if (excl < k && k <= excl + local) {
            int c2 = excl, bin = base;
#pragma unroll
            for (int r = 0; r < 8; ++r) {
                int hh = (int)h[base + r];
                if (c2 + hh >= k) { bin = base + r; break; }
                c2 += hh;
            }
            sm.resbin[g] = bin; sm.resbelow[g] = c2;
        }
        __syncthreads();
    }
    unsigned rb[4];
#pragma unroll
    for (int q = 0; q < 4; ++q) rb[q] = (unsigned)sm.resbin[q];
#pragma unroll
    for (int i = 0; i < CPT; ++i) {
        int c = tid + i * 512;
        float4 p = cand[c];
#pragma unroll
        for (int q = 0; q < 4; ++q) {
            if (selfex && c == qbase + q) continue;
            unsigned key = __float_as_uint(fmaxf(dist2(qc[q], p), 0.f));
            unsigned bin = key >> 21;
            if (bin < rb[q]) {
                if (IS_LOSS) { unsigned pp = atomicAdd(&sm.nbn[q], 1u); sm.nb[q][pp] = c; }
                else atomicAdd(&sm.cls[q][labels[b * NN + c]], 1u);
            } else if (bin == rb[q]) {
                unsigned pp = atomicAdd(&sm.n[q], 1u);
                if (pp < 256) { sm.skey[q][pp] = key; sm.sidx[q][pp] = c; }
            }
        }
    }
    __syncthreads();
    {
        int g = tid >> 7, t = tid & 127;
        int n = min(sm.n[g], 256u);
        int need = k - sm.resbelow[g];
        for (int j = t; j < n; j += 128) {
            unsigned kj = sm.skey[g][j]; int ij = sm.sidx[g][j], r = 0;
            for (int m = 0; m < n; ++m) {
                unsigned km = sm.skey[g][m];
                r += (km < kj) || (km == kj && sm.sidx[g][m] < ij);
            }
            if (r < need) {
                if (IS_LOSS) { unsigned pp = atomicAdd(&sm.nbn[g], 1u); sm.nb[g][pp] = ij; }
                else atomicAdd(&sm.cls[g][labels[b * NN + ij]], 1u);
            }
        }
    }
    __syncthreads();
    if (!IS_LOSS) {
        if ((tid & 127) == 0) {
            int g = tid >> 7;
            int best = 0; unsigned bc = sm.cls[g][0];
#pragma unroll
            for (int cc = 1; cc < 13; ++cc)
                if (sm.cls[g][cc] > bc) { bc = sm.cls[g][cc]; best = cc; }
            g_hard[qoff + b * Nq + qbase + g] = best;
        }
        return;
    }
    {
        int g = wid >> 2, w4 = wid & 3;
        int qi = qbase + g;
        int hb = qoff + b * Nq;
        int myh = g_hard[hb + qi];
        const float4* fq = (const float4*)(feat + (size_t)(b * Nq + qi) * D);
        int D4 = D >> 2;
        for (int j = w4; j < k; j += 4) {
            int nbi = sm.nb[g][j];
            const float4* fn = (const float4*)(feat + (size_t)(b * Nq + nbi) * D);
            float ss = 0.f;
            for (int d = lane; d < D4; d += 32) {
                float4 a = fq[d], z = fn[d];
                float dx = a.x - z.x, dy = a.y - z.y, dz = a.z - z.z, dw = a.w - z.w;
                ss += dx * dx + dy * dy + dz * dz + dw * dw;
            }
#pragma unroll
            for (int o = 16; o; o >>= 1) ss += __shfl_down_sync(0xFFFFFFFFu, ss, o);
            if (lane == 0) {
                sm.fd[g][j] = sqrtf(ss + 1e-6f);
                sm.msk[g][j] = (g_hard[hb + nbi] == myh) ? 1 : 0;
            }
        }
    }
    __syncthreads();
    if ((tid & 127) == 0) {
        int g = tid >> 7;
        float dmin = 3.0e38f; int cnt = 0;
        for (int j = 0; j < k; ++j) { dmin = fminf(dmin, sm.fd[g][j]); cnt += sm.msk[g][j]; }
        if (cnt > 0 && cnt < k) {
            float pos = 0.f, neg = 0.f;
            for (int j = 0; j < k; ++j) {
                float e = expf(dmin - sm.fd[g][j]);  // TEMPERATURE = 1
                neg += e;
                if (sm.msk[g][j]) pos += e;
            }
            atomicAdd(&g_bl_sum[stage], (double)(-logf(pos / neg + 1e-6f)));
            atomicAdd(&g_bl_cnt[stage], 1u);
        }
    }
}

// ---------------- octo body: 8 queries, 512 bins (k<=64) ----------------
template <int CPT, bool IS_LOSS>
__device__ __forceinline__ void octo_body(
        OSmem& sm, int b, int oct, int qoff, int Nq, int coff, int Ncand,
        int k, int stage, const float* __restrict__ feat, int D,
        const int* __restrict__ labels, bool selfex) {
    int tid = threadIdx.x, lane = tid & 31, wid = tid >> 5;
    int qbase = oct * 8;
    float4 qc[8];
#pragma unroll
    for (int q = 0; q < 8; ++q) qc[q] = g_pack[qoff + b * Nq + qbase + q];
    const float4* cand = g_pack + coff + b * Ncand;

    uint4* h4 = (uint4*)sm.hist;
    uint4 z4 = make_uint4(0, 0, 0, 0);
    h4[tid] = z4; h4[tid + 512] = z4;
    if (tid < 8) { sm.n[tid] = 0; sm.nbn[tid] = 0; }
    if (tid >= 32 && tid < 160) sm.cls[(tid - 32) >> 4][(tid - 32) & 15] = 0;
    __syncthreads();
    // pass 1: histogram (bits 30..22 -> 512 half-octave bins)
#pragma unroll
    for (int i = 0; i < CPT; ++i) {
        int c = tid + i * 512;
        float4 p = cand[c];
#pragma unroll
        for (int q = 0; q < 8; ++q) {
            if (selfex && c == qbase + q) continue;
            unsigned bin = __float_as_uint(fmaxf(dist2(qc[q], p), 0.f)) >> 22;
            atomicAdd(&sm.hist[(q << 9) + bin], 1u);
        }
    }
    __syncthreads();
    // scan: 8 groups of 64 threads (2 warps each)
    {
        int g = tid >> 6, t = tid & 63, wig = (tid >> 5) & 1;
        const unsigned* h = sm.hist + (g << 9);
        int base = t * 8, local = 0;
#pragma unroll
        for (int r = 0; r < 8; ++r) local += (int)h[base + r];
        int incl = local;
#pragma unroll
        for (int o = 1; o < 32; o <<= 1) {
            int tt = __shfl_up_sync(0xFFFFFFFFu, incl, o);
            if (lane >= o) incl += tt;
        }
        if (lane == 31) sm.wsum[g][wig] = incl;
        __syncthreads();
        int woff = wig ? sm.wsum[g][0] : 0;
        int excl = woff + incl - local;
        if (excl < k && k <= excl + local) {
            int c2 = excl, bin = base;
#pragma unroll
            for (int r = 0; r < 8; ++r) {
                int hh = (int)h[base + r];
                if (c2 + hh >= k) { bin = base + r; break; }
                c2 += hh;
            }
            sm.resbin[g] = bin; sm.resbelow[g] = c2;
        }
        __syncthreads();
    }
    unsigned rb[8];
#pragma unroll
    for (int q = 0; q < 8; ++q) rb[q] = (unsigned)sm.resbin[q];
    // pass 2: recompute + classify
#pragma unroll
    for (int i = 0; i < CPT; ++i) {
        int c = tid + i * 512;
        float4 p = cand[c];
#pragma unroll
        for (int q = 0; q < 8; ++q) {
            if (selfex && c == qbase + q) continue;
            unsigned key = __float_as_uint(fmaxf(dist2(qc[q], p), 0.f));
            unsigned bin = key >> 22;
            if (bin < rb[q]) {
                if (IS_LOSS) { unsigned pp = atomicAdd(&sm.nbn[q], 1u); sm.nb[q][pp] = c; }
                else atomicAdd(&sm.cls[q][labels[b * NN + c]], 1u);
            } else if (bin == rb[q]) {
                unsigned pp = atomicAdd(&sm.n[q], 1u);
                if (pp < 128) { sm.skey[q][pp] = key; sm.sidx[q][pp] = c; }
            }
        }
    }
    __syncthreads();
    // exact-rank survivors
    {
        int g = tid >> 6, t = tid & 63;
        int n = min(sm.n[g], 128u);
        int need = k - sm.resbelow[g];
        for (int j = t; j < n; j += 64) {
            unsigned kj = sm.skey[g][j]; int ij = sm.sidx[g][j], r = 0;
            for (int m = 0; m < n; ++m) {
                unsigned km = sm.skey[g][m];
                r += (km < kj) || (km == kj && sm.sidx[g][m] < ij);
            }
            if (r < need) {
                if (IS_LOSS) { unsigned pp = atomicAdd(&sm.nbn[g], 1u); sm.nb[g][pp] = ij; }
                else atomicAdd(&sm.cls[g][labels[b * NN + ij]], 1u);
            }
        }
    }
    __syncthreads();
    if (!IS_LOSS) {
        if ((tid & 63) == 0) {
            int g = tid >> 6;
            int best = 0; unsigned bc = sm.cls[g][0];
#pragma unroll
            for (int cc = 1; cc < 13; ++cc)
                if (sm.cls[g][cc] > bc) { bc = sm.cls[g][cc]; best = cc; }
            g_hard[qoff + b * Nq + qbase + g] = best;
        }
        return;
    }
    // feature distances: 2 warps per query
    {
        int g = wid >> 1, w2 = wid & 1;
        int qi = qbase + g;
        int hb = qoff + b * Nq;
        int myh = g_hard[hb + qi];
        const float4* fq = (const float4*)(feat + (size_t)(b * Nq + qi) * D);
        int D4 = D >> 2;
        for (int j = w2; j < k; j += 2) {
            int nbi = sm.nb[g][j];
            const float4* fn = (const float4*)(feat + (size_t)(b * Nq + nbi) * D);
            float ss = 0.f;
            for (int d = lane; d < D4; d += 32) {
                float4 a = fq[d], z = fn[d];
                float dx = a.x - z.x, dy = a.y - z.y, dz = a.z - z.z, dw = a.w - z.w;
                ss += dx * dx + dy * dy + dz * dz + dw * dw;
            }
#pragma unroll
            for (int o = 16; o; o >>= 1) ss += __shfl_down_sync(0xFFFFFFFFu, ss, o);
            if (lane == 0) {
                sm.fd[g][j] = sqrtf(ss + 1e-6f);
                sm.msk[g][j] = (g_hard[hb + nbi] == myh) ? 1 : 0;
            }
        }
    }
    __syncthreads();
    if ((tid & 63) == 0) {
        int g = tid >> 6;
        float dmin = 3.0e38f; int cnt = 0;
        for (int j = 0; j < k; ++j) { dmin = fminf(dmin, sm.fd[g][j]); cnt += sm.msk[g][j]; }
        if (cnt > 0 && cnt < k) {
            float pos = 0.f, neg = 0.f;
            for (int j = 0; j < k; ++j) {
                float e = expf(dmin - sm.fd[g][j]);  // TEMPERATURE = 1
                neg += e;
                if (sm.msk[g][j]) pos += e;
            }
            atomicAdd(&g_bl_sum[stage], (double)(-logf(pos / neg + 1e-6f)));
            atomicAdd(&g_bl_cnt[stage], 1u);
        }
    }
}

// ---------------- kernel H: hard labels stages 1..4 ----------------
__global__ __launch_bounds__(512, 2) void kernelH(const int* __restrict__ labels) {
    __shared__ USmem u;
    int bx = blockIdx.x, b = blockIdx.y;
    if (bx < 256)
        octo_body<16, false>(u.o, b, bx, 16384, 2048, 0, 8192, 4, 0, nullptr, 0, labels, false);
    else if (bx < 320)
        octo_body<16, false>(u.o, b, bx - 256, 20480, 512, 0, 8192, 16, 0, nullptr, 0, labels, false);
    else if (bx < 336)
        octo_body<16, false>(u.o, b, bx - 320, 21504, 128, 0, 8192, 64, 0, nullptr, 0, labels, false);
    else
        quad_body<16, false>(u.q, b, bx - 336, 21760, 32, 0, 8192, 256, 0, nullptr, 0, labels, false);
}

// ---------------- kernel L: all boundary losses + CE ----------------
__global__ __launch_bounds__(512, 2) void kernelL(
        const float* __restrict__ f1, const float* __restrict__ f2,
        const float* __restrict__ f3, const float* __restrict__ f4,
        const float* __restrict__ f5, const int* __restrict__ labels,
        const float* __restrict__ lg0, const float* __restrict__ lg1,
        const float* __restrict__ lg2, const float* __restrict__ lg3,
        const float* __restrict__ lg4, const float* __restrict__ lg5,
        const int* __restrict__ i2, const int* __restrict__ i3,
        const int* __restrict__ i4, const int* __restrict__ i5) {
    __shared__ USmem u;
    int bx = blockIdx.x, b = blockIdx.y;
    if (bx < 1024) {
        octo_body<16, true>(u.o, b, bx, 0, 8192, 0, 8192, 35, 0, f1, 64, nullptr, true);
    } else if (bx < 1280) {
        octo_body<4, true>(u.o, b, bx - 1024, 16384, 2048, 16384, 2048, 23, 1, f2, 128, nullptr, true);
    } else if (bx < 1344) {
        octo_body<1, true>(u.o, b, bx - 1280, 20480, 512, 20480, 512, 23, 2, f3, 256, nullptr, true);
    } else if (bx < 1504) {
        // direct-rank losses for stages 3, 4 (one query per block); reuse union storage
        unsigned* s_key = u.o.hist;
        int*      s_nb  = u.o.nb[0];
        float*    s_fd  = u.o.fd[0];
        int*      s_msk = u.o.msk[0];
        int bi = bx - 1344;
        int tid = threadIdx.x, lane = tid & 31, wid = tid >> 5;
        int stage, Ni, off, qi; const float* feat;
        if (bi < 128) { stage = 3; Ni = 128; off = 21504; feat = f4; qi = bi; }
        else          { stage = 4; Ni = 32;  off = 21760; feat = f5; qi = bi - 128; }
        const int D = 512, D4 = 128;
        float4 qc = g_pack[off + b * Ni + qi];
        unsigned myk = 0xFFFFFFFFu;
        if (tid < Ni && tid != qi) {
            float4 p = g_pack[off + b * Ni + tid];
            myk = __float_as_uint(fmaxf(dist2(qc, p), 0.f));
        }
        s_key[tid] = myk;
        __syncthreads();
        if (myk != 0xFFFFFFFFu) {
            int r = 0;
            for (int j = 0; j < Ni; ++j) {
                unsigned kj = s_key[j];
                r += (kj < myk) || (kj == myk && j < tid);
            }
            if (r < 23) s_nb[r] = tid;
        }
        __syncthreads();
        int myh = g_hard[off + b * Ni + qi];
        const float4* fq = (const float4*)(feat + (size_t)(b * Ni + qi) * D);
        for (int j = wid; j < 23; j += 16) {
            int nbi = s_nb[j];
            const float4* fn = (const float4*)(feat + (size_t)(b * Ni + nbi) * D);
            float ss = 0.f;
            for (int d = lane; d < D4; d += 32) {
                float4 a = fq[d], z = fn[d];
                float dx = a.x - z.x, dy = a.y - z.y, dz = a.z - z.z, dw = a.w - z.w;
                ss += dx * dx + dy * dy + dz * dz + dw * dw;
            }
#pragma unroll
            for (int o = 16; o; o >>= 1) ss += __shfl_down_sync(0xFFFFFFFFu, ss, o);
            if (lane == 0) {
                s_fd[j] = sqrtf(ss + 1e-6f);
                s_msk[j] = (g_hard[off + b * Ni + nbi] == myh) ? 1 : 0;
            }
        }
        __syncthreads();
        if (tid == 0) {
            float dmin = 3.0e38f; int cnt = 0;
            for (int j = 0; j < 23; ++j) { dmin = fminf(dmin, s_fd[j]); cnt += s_msk[j]; }
            if (cnt > 0 && cnt < 23) {
                float pos = 0.f, neg = 0.f;
                for (int j = 0; j < 23; ++j) {
                    float e = expf(dmin - s_fd[j]);
                    neg += e;
                    if (s_msk[j]) pos += e;
                }
                atomicAdd(&g_bl_sum[stage], (double)(-logf(pos / neg + 1e-6f)));
                atomicAdd(&g_bl_cnt[stage], 1u);
            }
        }
    } else {
        // cross entropy: one row per thread
        const int cum[7] = {0, 16384, 32768, 36864, 37888, 38144, 38208};
        int chunk = bx - 1504;
        int r = (chunk * 2 + b) * 512 + threadIdx.x;
        int job = 0;
        float l = 0.f;
        if (r < 38208) {
#pragma unroll
            for (int j = 1; j < 6; ++j) if (r >= cum[j]) job = j;
            const float* L[6] = {lg0, lg1, lg2, lg3, lg4, lg5};
            const int*   G[6] = {nullptr, nullptr, i2, i3, i4, i5};
            const int   lgn[6] = {13, 13, 11, 9, 7, 5};
            int lr = r - cum[job];
            int bb = lr >> lgn[job];
            const int* g = G[job];
            int lab = g ? labels[bb * NN + g[lr]] : labels[lr];
            const float* row = L[job] + (size_t)lr * 13;
            float v[13];
#pragma unroll
            for (int c = 0; c < 13; ++c) v[c] = row[c];
            float m = v[0];
#pragma unroll
            for (int c = 1; c < 13; ++c) m = fmaxf(m, v[c]);
            float s = 0.f;
#pragma unroll
            for (int c = 0; c < 13; ++c) s += expf(v[c] - m);
            l = (m + logf(s)) - v[lab];
        }
#pragma unroll
        for (int o = 16; o; o >>= 1) l += __shfl_down_sync(0xFFFFFFFFu, l, o);
        if ((threadIdx.x & 31) == 0 && l != 0.f) atomicAdd(&g_ce_sum[job], (double)l);
    }
}

// ---------------- finalize ----------------
__global__ void finalize_kernel(float* out) {
    const int ns[5] = {8192, 2048, 512, 128, 32};
    double ce = g_ce_sum[0] / (double)(BB * NN);
    double o = 0.0;
    for (int j = 0; j < 5; ++j) o += g_ce_sum[1 + j] / (double)(BB * ns[j]);
    double bl = 0.0;
    for (int i = 0; i < 5; ++i) {
        double dn = g_bl_cnt[i] > 0 ? (double)g_bl_cnt[i] : 1.0;
        bl += g_bl_sum[i] / dn;
    }
    out[0] = (float)(ce + 0.1 * bl + 0.1 * o);
}

// ---------------- launch ----------------
extern "C" void kernel_launch(void* const* d_in, const int* in_sizes, int n_in,
                              void* d_out, int out_size) {
    (void)in_sizes; (void)n_in; (void)out_size;
    // 0:labels, 1..4:index2..5, 5:output, per stage j: 6+3j:pred, 7+3j:xyz, 8+3j:feat
    const int* labels = (const int*)d_in[0];
    const int* idx2 = (const int*)d_in[1];
    const int* idx3 = (const int*)d_in[2];
    const int* idx4 = (const int*)d_in[3];
    const int* idx5 = (const int*)d_in[4];
    const float* output = (const float*)d_in[5];
    const float* pred[5], *xyz[5], *feat[5];
    for (int j = 0; j < 5; ++j) {
        pred[j] = (const float*)d_in[6 + 3 * j];
        xyz[j]  = (const float*)d_in[7 + 3 * j];
        feat[j] = (const float*)d_in[8 + 3 * j];
    }

    prep_kernel<<<86, 256>>>(xyz[0], xyz[1], xyz[2], xyz[3], xyz[4], labels);
    kernelH<<<dim3(344, BB), 512>>>(labels);
    kernelL<<<dim3(1542, BB), 512>>>(feat[0], feat[1], feat[2], feat[3], feat[4], labels,
                                     output, pred[0], pred[1], pred[2], pred[3], pred[4],
                                     idx2, idx3, idx4, idx5);

    finalize_kernel<<<1, 1>>>((float*)d_out);
}

// round 12
// speedup vs baseline: 1862.5913x; 1.0514x over previous
#include <cuda_runtime.h>
#include <math.h>

#define BB 2
#define NN 8192

// Ns = {8192,2048,512,128,32}, D = {64,128,256,512,512}
// nsample-1 = {35,23,23,23,23}, kneighbors = {1,4,16,64,256}
// offsets into g_hard/g_pack: {0,16384,20480,21504,21760}

__device__ double   g_ce_sum[6];
__device__ double   g_bl_sum[5];
__device__ unsigned g_bl_cnt[5];
__device__ int      g_hard[21824];
__device__ float4   g_pack[21824];

struct QSmem {                // quad: 4 queries x 1024 bins (k=256 path only)
    unsigned hist[4096];
    int      wsum[4][4];
    int      resbin[4], resbelow[4];
    unsigned n[4], nbn[4];
    unsigned cls[4][16];
    unsigned skey[4][256];
    int      sidx[4][256];
    int      nb[4][36];
    float    fd[4][36];
    int      msk[4][36];
};
struct OSmem {                // octo: 8 queries x 512 bins, with min-bin sieve
    unsigned hist[4096];
    unsigned char  cbin[8192];     // coarse min-bin per candidate (bin>>1)
    unsigned short list[3072];     // compacted survivor candidate indices
    unsigned ln;
    int      wsum[8][2];
    int      resbin[8], resbelow[8];
    unsigned n[8], nbn[8];
    unsigned cls[8][16];
    unsigned skey[8][128];
    int      sidx[8][128];
    int      nb[8][36];
    float    fd[8][36];
    int      msk[8][36];
};
union USmem { QSmem q; OSmem o; };

// ---------------- prep: zero accumulators, copy labels, pack coords ----------------
__global__ void prep_kernel(const float* __restrict__ x1, const float* __restrict__ x2,
                            const float* __restrict__ x3, const float* __restrict__ x4,
                            const float* __restrict__ x5, const int* __restrict__ labels) {
    int id = blockIdx.x * blockDim.x + threadIdx.x;
    if (id < 6) g_ce_sum[id] = 0.0;
    if (id >= 8 && id < 13) { g_bl_sum[id - 8] = 0.0; g_bl_cnt[id - 8] = 0u; }
    if (id < BB * NN) g_hard[id] = labels[id];
    if (id < 21824) {
        const int offs[6] = {0, 16384, 20480, 21504, 21760, 21824};
        const float* xs[5] = {x1, x2, x3, x4, x5};
        int s = 0;
        while (id >= offs[s + 1]) ++s;
        int r = id - offs[s];
        const float* p = xs[s] + (size_t)r * 3;
        float x = p[0], y = p[1], z = p[2];
        g_pack[id] = make_float4(x, y, z, x * x + y * y + z * z);
    }
}

// pinned arithmetic: identical across passes
__device__ __forceinline__ float dist2(float4 q, float4 p) {
    float s = q.z * p.z;
    s = __fmaf_rn(q.y, p.y, s);
    s = __fmaf_rn(q.x, p.x, s);
    return __fmaf_rn(-2.f, s, q.w + p.w);
}

// ---------------- quad body: 4 queries, 1024 bins (k=256 path, 8 blocks total) ----------------
template <int CPT, bool IS_LOSS>
__device__ __forceinline__ void quad_body(
        QSmem& sm, int b, int quad, int qoff, int Nq, int coff, int Ncand,
        int k, int stage, const float* __restrict__ feat, int D,
        const int* __restrict__ labels, bool selfex) {
    int tid = threadIdx.x, lane = tid & 31, wid = tid >> 5;
    int qbase = quad * 4;
    float4 qc[4];
#pragma unroll
    for (int q = 0; q < 4; ++q) qc[q] = g_pack[qoff + b * Nq + qbase + q];
    const float4* cand = g_pack + coff + b * Ncand;

    uint4* h4 = (uint4*)sm.hist;
    uint4 z4 = make_uint4(0, 0, 0, 0);
    h4[tid] = z4; h4[tid + 512] = z4;
    if (tid < 4) { sm.n[tid] = 0; sm.nbn[tid] = 0; }
    if (tid >= 32 && tid < 96) sm.cls[(tid - 32) >> 4][(tid - 32) & 15] = 0;
    __syncthreads();
#pragma unroll
    for (int i = 0; i < CPT; ++i) {
        int c = tid + i * 512;
        float4 p = cand[c];
#pragma unroll
        for (int q = 0; q < 4; ++q) {
            if (selfex && c == qbase + q) continue;
            unsigned bin = __float_as_uint(fmaxf(dist2(qc[q], p), 0.f)) >> 21;
            atomicAdd(&sm.hist[(q << 10) + bin], 1u);
        }
    }
    __syncthreads();
    {
        int g = tid >> 7, t = tid & 127, wig = (tid >> 5) & 3;
        const unsigned* h = sm.hist + (g << 10);
        int base = t * 8, local = 0;
#pragma unroll
        for (int r = 0; r < 8; ++r) local += (int)h[base + r];
        int incl = local;
#pragma unroll
        for (int o = 1; o < 32; o <<= 1) {
            int tt = __shfl_up_sync(0xFFFFFFFFu, incl, o);
            if (lane >= o) incl += tt;
        }
        if (lane == 31) sm.wsum[g][wig] = incl;
        __syncthreads();
        int woff = 0;
#pragma unroll
        for (int w = 0; w < 4; ++w) woff += (w < wig) ? sm.wsum[g][w] : 0;
        int excl = woff + incl - local;
        if (excl < k && k <= excl + local) {
            int c2 = excl, bin = base;
#pragma unroll
            for (int r = 0; r < 8; ++r) {
                int hh = (int)h[base + r];
                if (c2 + hh >= k) { bin = base + r; break; }
                c2 += hh;
            }
            sm.resbin[g] = bin; sm.resbelow[g] = c2;
        }
        __syncthreads();
    }
    unsigned rb[4];
#pragma unroll
    for (int q = 0; q < 4; ++q) rb[q] = (unsigned)sm.resbin[q];
#pragma unroll
    for (int i = 0; i < CPT; ++i) {
        int c = tid + i * 512;
        float4 p = cand[c];
#pragma unroll
        for (int q = 0; q < 4; ++q) {
            if (selfex && c == qbase + q) continue;
            unsigned key = __float_as_uint(fmaxf(dist2(qc[q], p), 0.f));
            unsigned bin = key >> 21;
            if (bin < rb[q]) {
                if (IS_LOSS) { unsigned pp = atomicAdd(&sm.nbn[q], 1u); sm.nb[q][pp] = c; }
                else atomicAdd(&sm.cls[q][labels[b * NN + c]], 1u);
            } else if (bin == rb[q]) {
                unsigned pp = atomicAdd(&sm.n[q], 1u);
                if (pp < 256) { sm.skey[q][pp] = key; sm.sidx[q][pp] = c; }
            }
        }
    }
    __syncthreads();
    {
        int g = tid >> 7, t = tid & 127;
        int n = min(sm.n[g], 256u);
        int need = k - sm.resbelow[g];
        for (int j = t; j < n; j += 128) {
            unsigned kj = sm.skey[g][j]; int ij = sm.sidx[g][j], r = 0;
            for (int m = 0; m < n; ++m) {
                unsigned km = sm.skey[g][m];
                r += (km < kj) || (km == kj && sm.sidx[g][m] < ij);
            }
            if (r < need) {
                if (IS_LOSS) { unsigned pp = atomicAdd(&sm.nbn[g], 1u); sm.nb[g][pp] = ij; }
                else atomicAdd(&sm.cls[g][labels[b * NN + ij]], 1u);
            }
        }
    }
    __syncthreads();
    if (!IS_LOSS) {
        if ((tid & 127) == 0) {
            int g = tid >> 7;
            int best = 0; unsigned bc = sm.cls[g][0];
#pragma unroll
            for (int cc = 1; cc < 13; ++cc)
                if (sm.cls[g][cc] > bc) { bc = sm.cls[g][cc]; best = cc; }
            g_hard[qoff + b * Nq + qbase + g] = best;
        }
        return;
    }
}

// ---------------- octo body: 8 queries, 512 bins, min-bin sieve + compaction ----------------
template <int CPT, bool IS_LOSS>
__device__ __forceinline__ void octo_body(
        OSmem& sm, int b, int oct, int qoff, int Nq, int coff, int Ncand,
        int k, int stage, const float* __restrict__ feat, int D,
        const int* __restrict__ labels, bool selfex) {
    int tid = threadIdx.x, lane = tid & 31, wid = tid >> 5;
    int qbase = oct * 8;
    float4 qc[8];
#pragma unroll
    for (int q = 0; q < 8; ++q) qc[q] = g_pack[qoff + b * Nq + qbase + q];
    const float4* cand = g_pack + coff + b * Ncand;

    uint4* h4 = (uint4*)sm.hist;
    uint4 z4 = make_uint4(0, 0, 0, 0);
    h4[tid] = z4; h4[tid + 512] = z4;
    if (tid < 8) { sm.n[tid] = 0; sm.nbn[tid] = 0; }
    if (tid == 16) sm.ln = 0;
    if (tid >= 32 && tid < 160) sm.cls[(tid - 32) >> 4][(tid - 32) & 15] = 0;
    __syncthreads();

    // pass 1: histogram (bits 30..22 -> 512 half-octave bins) + min-bin record
#pragma unroll
    for (int i = 0; i < CPT; ++i) {
        int c = tid + i * 512;
        float4 p = cand[c];
        unsigned mb = 511u;
#pragma unroll
        for (int q = 0; q < 8; ++q) {
            if (selfex && c == qbase + q) continue;
            unsigned bin = __float_as_uint(fmaxf(dist2(qc[q], p), 0.f)) >> 22;
            atomicAdd(&sm.hist[(q << 9) + bin], 1u);
            mb = min(mb, bin);
        }
        sm.cbin[c] = (unsigned char)(mb >> 1);
    }
    __syncthreads();

    // scan: 8 groups of 64 threads (2 warps each)
    {
        int g = tid >> 6, t = tid & 63, wig = (tid >> 5) & 1;
        const unsigned* h = sm.hist + (g << 9);
        int base = t * 8, local = 0;
#pragma unroll
        for (int r = 0; r < 8; ++r) local += (int)h[base + r];
        int incl = local;
#pragma unroll
        for (int o = 1; o < 32; o <<= 1) {
            int tt = __shfl_up_sync(0xFFFFFFFFu, incl, o);
            if (lane >= o) incl += tt;
        }
        if (lane == 31) sm.wsum[g][wig] = incl;
        __syncthreads();
        int woff = wig ? sm.wsum[g][0] : 0;
        int excl = woff + incl - local;
        if (excl < k && k <= excl + local) {
            int c2 = excl, bin = base;
#pragma unroll
            for (int r = 0; r < 8; ++r) {
                int hh = (int)h[base + r];
                if (c2 + hh >= k) { bin = base + r; break; }
                c2 += hh;
            }
            sm.resbin[g] = bin; sm.resbelow[g] = c2;
        }
        __syncthreads();
    }
    unsigned rb[8];
    unsigned rbmax = 0;
#pragma unroll
    for (int q = 0; q < 8; ++q) { rb[q] = (unsigned)sm.resbin[q]; rbmax = max(rbmax, rb[q]); }

    // compact: candidates with coarse min-bin <= rbmax>>1 (conservative, exact)
    {
        unsigned char rbc = (unsigned char)(rbmax >> 1);
#pragma unroll
        for (int i = 0; i < CPT; ++i) {
            int c = tid + i * 512;
            if (sm.cbin[c] <= rbc) {
                unsigned p = atomicAdd(&sm.ln, 1u);
                if (p < 3072) sm.list[p] = (unsigned short)c;
            }
        }
    }
    __syncthreads();
    int Ln = (int)sm.ln;

    // pass 2: classify compacted survivors (fallback: full divergent loop on overflow)
    if (Ln <= 3072) {
        for (int j = tid; j < Ln; j += 512) {
            int c = (int)sm.list[j];
            float4 p = cand[c];
#pragma unroll
            for (int q = 0; q < 8; ++q) {
                if (selfex && c == qbase + q) continue;
                unsigned key = __float_as_uint(fmaxf(dist2(qc[q], p), 0.f));
                unsigned bin = key >> 22;
                if (bin < rb[q]) {
                    if (IS_LOSS) { unsigned pp = atomicAdd(&sm.nbn[q], 1u); sm.nb[q][pp] = c; }
                    else atomicAdd(&sm.cls[q][labels[b * NN + c]], 1u);
                } else if (bin == rb[q]) {
                    unsigned pp = atomicAdd(&sm.n[q], 1u);
                    if (pp < 128) { sm.skey[q][pp] = key; sm.sidx[q][pp] = c; }
                }
            }
        }
    } else {
        unsigned char rbc = (unsigned char)(rbmax >> 1);
#pragma unroll
        for (int i = 0; i < CPT; ++i) {
            int c = tid + i * 512;
            if (sm.cbin[c] > rbc) continue;
            float4 p = cand[c];
#pragma unroll
            for (int q = 0; q < 8; ++q) {
                if (selfex && c == qbase + q) continue;
                unsigned key = __float_as_uint(fmaxf(dist2(qc[q], p), 0.f));
                unsigned bin = key >> 22;
                if (bin < rb[q]) {
                    if (IS_LOSS) { unsigned pp = atomicAdd(&sm.nbn[q], 1u); sm.nb[q][pp] = c; }
                    else atomicAdd(&sm.cls[q][labels[b * NN + c]], 1u);
                } else if (bin == rb[q]) {
                    unsigned pp = atomicAdd(&sm.n[q], 1u);
                    if (pp < 128) { sm.skey[q][pp] = key; sm.sidx[q][pp] = c; }
                }
            }
        }
    }
    __syncthreads();

    // exact-rank survivors: (key, idx) lexicographic == jax top_k tie-break
    {
        int g = tid >> 6, t = tid & 63;
        int n = min(sm.n[g], 128u);
        int need = k - sm.resbelow[g];
        for (int j = t; j < n; j += 64) {
            unsigned kj = sm.skey[g][j]; int ij = sm.sidx[g][j], r = 0;
            for (int m = 0; m < n; ++m) {
                unsigned km = sm.skey[g][m];
                r += (km < kj) || (km == kj && sm.sidx[g][m] < ij);
            }
            if (r < need) {
                if (IS_LOSS) { unsigned pp = atomicAdd(&sm.nbn[g], 1u); sm.nb[g][pp] = ij; }
                else atomicAdd(&sm.cls[g][labels[b * NN + ij]], 1u);
            }
        }
    }
    __syncthreads();
    if (!IS_LOSS) {
        if ((tid & 63) == 0) {
            int g = tid >> 6;
            int best = 0; unsigned bc = sm.cls[g][0];
#pragma unroll
            for (int cc = 1; cc < 13; ++cc)
                if (sm.cls[g][cc] > bc) { bc = sm.cls[g][cc]; best = cc; }
            g_hard[qoff + b * Nq + qbase + g] = best;
        }
        return;
    }
    // feature distances: 2 warps per query
    {
        int g = wid >> 1, w2 = wid & 1;
        int qi = qbase + g;
        int hb = qoff + b * Nq;
        int myh = g_hard[hb + qi];
        const float4* fq = (const float4*)(feat + (size_t)(b * Nq + qi) * D);
        int D4 = D >> 2;
        for (int j = w2; j < k; j += 2) {
            int nbi = sm.nb[g][j];
            const float4* fn = (const float4*)(feat + (size_t)(b * Nq + nbi) * D);
            float ss = 0.f;
            for (int d = lane; d < D4; d += 32) {
                float4 a = fq[d], z = fn[d];
                float dx = a.x - z.x, dy = a.y - z.y, dz = a.z - z.z, dw = a.w - z.w;
                ss += dx * dx + dy * dy + dz * dz + dw * dw;
            }
#pragma unroll
            for (int o = 16; o; o >>= 1) ss += __shfl_down_sync(0xFFFFFFFFu, ss, o);
            if (lane == 0) {
                sm.fd[g][j] = sqrtf(ss + 1e-6f);
                sm.msk[g][j] = (g_hard[hb + nbi] == myh) ? 1 : 0;
            }
        }
    }
    __syncthreads();
    if ((tid & 63) == 0) {
        int g = tid >> 6;
        float dmin = 3.0e38f; int cnt = 0;
        for (int j = 0; j < k; ++j) { dmin = fminf(dmin, sm.fd[g][j]); cnt += sm.msk[g][j]; }
        if (cnt > 0 && cnt < k) {
            float pos = 0.f, neg = 0.f;
            for (int j = 0; j < k; ++j) {
                float e = expf(dmin - sm.fd[g][j]);  // TEMPERATURE = 1
                neg += e;
                if (sm.msk[g][j]) pos += e;
            }
            atomicAdd(&g_bl_sum[stage], (double)(-logf(pos / neg + 1e-6f)));
            atomicAdd(&g_bl_cnt[stage], 1u);
        }
    }
}

// ---------------- kernel A: loss0 + hard labels + CE (mutually independent) ----------------
__global__ __launch_bounds__(512, 2) void kernelA(
        const float* __restrict__ f1, const int* __restrict__ labels,
        const float* __restrict__ lg0, const float* __restrict__ lg1,
        const float* __restrict__ lg2, const float* __restrict__ lg3,
        const float* __restrict__ lg4, const float* __restrict__ lg5,
        const int* __restrict__ i2, const int* __restrict__ i3,
        const int* __restrict__ i4, const int* __restrict__ i5) {
    __shared__ USmem u;
    int bx = blockIdx.x, b = blockIdx.y;
    if (bx < 1024) {
        octo_body<16, true>(u.o, b, bx, 0, 8192, 0, 8192, 35, 0, f1, 64, nullptr, true);
    } else if (bx < 1280) {
        octo_body<16, false>(u.o, b, bx - 1024, 16384, 2048, 0, 8192, 4, 0, nullptr, 0, labels, false);
    } else if (bx < 1344) {
        octo_body<16, false>(u.o, b, bx - 1280, 20480, 512, 0, 8192, 16, 0, nullptr, 0, labels, false);
    } else if (bx < 1360) {
        octo_body<16, false>(u.o, b, bx - 1344, 21504, 128, 0, 8192, 64, 0, nullptr, 0, labels, false);
    } else if (bx < 1368) {
        quad_body<16, false>(u.q, b, bx - 1360, 21760, 32, 0, 8192, 256, 0, nullptr, 0, labels, false);
    } else {
        // cross entropy: one row per thread
        const int cum[7] = {0, 16384, 32768, 36864, 37888, 38144, 38208};
        int chunk = bx - 1368;
        int r = (chunk * 2 + b) * 512 + threadIdx.x;
        int job = 0;
        float l = 0.f;
        if (r < 38208) {
#pragma unroll
            for (int j = 1; j < 6; ++j) if (r >= cum[j]) job = j;
            const float* L[6] = {lg0, lg1, lg2, lg3, lg4, lg5};
            const int*   G[6] = {nullptr, nullptr, i2, i3, i4, i5};
            const int   lgn[6] = {13, 13, 11, 9, 7, 5};
            int lr = r - cum[job];
            int bb = lr >> lgn[job];
            const int* g = G[job];
            int lab = g ? labels[bb * NN + g[lr]] : labels[lr];
            const float* row = L[job] + (size_t)lr * 13;
            float v[13];
#pragma unroll
            for (int c = 0; c < 13; ++c) v[c] = row[c];
            float m = v[0];
#pragma unroll
            for (int c = 1; c < 13; ++c) m = fmaxf(m, v[c]);
            float s = 0.f;
#pragma unroll
            for (int c = 0; c < 13; ++c) s += expf(v[c] - m);
            l = (m + logf(s)) - v[lab];
        }
#pragma unroll
        for (int o = 16; o; o >>= 1) l += __shfl_down_sync(0xFFFFFFFFu, l, o);
        if ((threadIdx.x & 31) == 0 && l != 0.f) atomicAdd(&g_ce_sum[job], (double)l);
    }
}

// ---------------- kernel B: losses for stages 1..4 (need g_hard from kernelA) ----------------
__global__ __launch_bounds__(512, 2) void kernelB(
        const float* __restrict__ f2, const float* __restrict__ f3,
        const float* __restrict__ f4, const float* __restrict__ f5) {
    __shared__ USmem u;
    int bx = blockIdx.x, b = blockIdx.y;
    if (bx < 256) {
        octo_body<4, true>(u.o, b, bx, 16384, 2048, 16384, 2048, 23, 1, f2, 128, nullptr, true);
    } else if (bx < 320) {
        octo_body<1, true>(u.o, b, bx - 256, 20480, 512, 20480, 512, 23, 2, f3, 256, nullptr, true);
    } else {
        // direct-rank losses for stages 3, 4 (one query per block); reuse union storage
        unsigned* s_key = u.o.hist;
        int*      s_nb  = u.o.nb[0];
        float*    s_fd  = u.o.fd[0];
        int*      s_msk = u.o.msk[0];
        int bi = bx - 320;
        int tid = threadIdx.x, lane = tid & 31, wid = tid >> 5;
        int stage, Ni, off, qi; const float* feat;
        if (bi < 128) { stage = 3; Ni = 128; off = 21504; feat = f4; qi = bi; }
        else          { stage = 4; Ni = 32;  off = 21760; feat = f5; qi = bi - 128; }
        const int D = 512, D4 = 128;
        float4 qc = g_pack[off + b * Ni + qi];
        unsigned myk = 0xFFFFFFFFu;
        if (tid < Ni && tid != qi) {
            float4 p = g_pack[off + b * Ni + tid];
            myk = __float_as_uint(fmaxf(dist2(qc, p), 0.f));
        }
        s_key[tid] = myk;
        __syncthreads();
        if (myk != 0xFFFFFFFFu) {
            int r = 0;
            for (int j = 0; j < Ni; ++j) {
                unsigned kj = s_key[j];
                r += (kj < myk) || (kj == myk && j < tid);
            }
            if (r < 23) s_nb[r] = tid;
        }
        __syncthreads();
        int myh = g_hard[off + b * Ni + qi];
        const float4* fq = (const float4*)(feat + (size_t)(b * Ni + qi) * D);
        for (int j = wid; j < 23; j += 16) {
            int nbi = s_nb[j];
            const float4* fn = (const float4*)(feat + (size_t)(b * Ni + nbi) * D);
            float ss = 0.f;
            for (int d = lane; d < D4; d += 32) {
                float4 a = fq[d], z = fn[d];
                float dx = a.x - z.x, dy = a.y - z.y, dz = a.z - z.z, dw = a.w - z.w;
                ss += dx * dx + dy * dy + dz * dz + dw * dw;
            }
#pragma unroll
            for (int o = 16; o; o >>= 1) ss += __shfl_down_sync(0xFFFFFFFFu, ss, o);
            if (lane == 0) {
                s_fd[j] = sqrtf(ss + 1e-6f);
                s_msk[j] = (g_hard[off + b * Ni + nbi] == myh) ? 1 : 0;
            }
        }
        __syncthreads();
        if (tid == 0) {
            float dmin = 3.0e38f; int cnt = 0;
            for (int j = 0; j < 23; ++j) { dmin = fminf(dmin, s_fd[j]); cnt += s_msk[j]; }
            if (cnt > 0 && cnt < 23) {
                float pos = 0.f, neg = 0.f;
                for (int j = 0; j < 23; ++j) {
                    float e = expf(dmin - s_fd[j]);
                    neg += e;
                    if (s_msk[j]) pos += e;
                }
                atomicAdd(&g_bl_sum[stage], (double)(-logf(pos / neg + 1e-6f)));
                atomicAdd(&g_bl_cnt[stage], 1u);
            }
        }
    }
}

// ---------------- finalize ----------------
__global__ void finalize_kernel(float* out) {
    const int ns[5] = {8192, 2048, 512, 128, 32};
    double ce = g_ce_sum[0] / (double)(BB * NN);
    double o = 0.0;
    for (int j = 0; j < 5; ++j) o += g_ce_sum[1 + j] / (double)(BB * ns[j]);
    double bl = 0.0;
    for (int i = 0; i < 5; ++i) {
        double dn = g_bl_cnt[i] > 0 ? (double)g_bl_cnt[i] : 1.0;
        bl += g_bl_sum[i] / dn;
    }
    out[0] = (float)(ce + 0.1 * bl + 0.1 * o);
}

// ---------------- launch ----------------
extern "C" void kernel_launch(void* const* d_in, const int* in_sizes, int n_in,
                              void* d_out, int out_size) {
    (void)in_sizes; (void)n_in; (void)out_size;
    // 0:labels, 1..4:index2..5, 5:output, per stage j: 6+3j:pred, 7+3j:xyz, 8+3j:feat
    const int* labels = (const int*)d_in[0];
    const int* idx2 = (const int*)d_in[1];
    const int* idx3 = (const int*)d_in[2];
    const int* idx4 = (const int*)d_in[3];
    const int* idx5 = (const int*)d_in[4];
    const float* output = (const float*)d_in[5];
    const float* pred[5], *xyz[5], *feat[5];
    for (int j = 0; j < 5; ++j) {
        pred[j] = (const float*)d_in[6 + 3 * j];
        xyz[j]  = (const float*)d_in[7 + 3 * j];
        feat[j] = (const float*)d_in[8 + 3 * j];
    }

    prep_kernel<<<86, 256>>>(xyz[0], xyz[1], xyz[2], xyz[3], xyz[4], labels);
    kernelA<<<dim3(1406, BB), 512>>>(feat[0], labels,
                                     output, pred[0], pred[1], pred[2], pred[3], pred[4],
                                     idx2, idx3, idx4, idx5);
    kernelB<<<dim3(480, BB), 512>>>(feat[1], feat[2], feat[3], feat[4]);

    finalize_kernel<<<1, 1>>>((float*)d_out);
}

// round 13
// speedup vs baseline: 2016.8887x; 1.0828x over previous
#include <cuda_runtime.h>
#include <math.h>

#define BB 2
#define NN 8192

// Ns = {8192,2048,512,128,32}, D = {64,128,256,512,512}
// nsample-1 = {35,23,23,23,23}, kneighbors = {1,4,16,64,256}
// offsets into g_hard/g_pack: {0,16384,20480,21504,21760}

__device__ double   g_ce_sum[6];
__device__ double   g_bl_sum[5];
__device__ unsigned g_bl_cnt[5];
__device__ int      g_hard[21824];
__device__ float4   g_pack[21824];
__device__ float4   g_packQ[BB * NN];   // Morton-sorted stage-0 queries
__device__ int      g_qperm[BB * NN];

struct QSmem {                // quad: 4 queries x 1024 bins (k=256 path only)
    unsigned hist[4096];
    int      wsum[4][4];
    int      resbin[4], resbelow[4];
    unsigned n[4], nbn[4];
    unsigned cls[4][16];
    unsigned skey[4][256];
    int      sidx[4][256];
    int      nb[4][36];
    float    fd[4][36];
    int      msk[4][36];
};
struct OSmem {                // octo: 8 queries x 512 bins, with min-bin sieve
    unsigned hist[4096];
    unsigned char  cbin[8192];
    unsigned short list[3072];
    unsigned ln;
    int      wsum[8][2];
    int      resbin[8], resbelow[8];
    unsigned n[8], nbn[8];
    unsigned cls[8][16];
    unsigned skey[8][128];
    int      sidx[8][128];
    int      nb[8][36];
    float    fd[8][36];
    int      msk[8][36];
};
struct LSmem {                // loss0: center-ball pruned, 8 sorted queries
    unsigned chist[512];
    union { unsigned char cbin[8192]; unsigned qhist[2048]; } u8;  // aliased
    unsigned short list[6144];
    unsigned ln;
    int      wsum[16];
    int      resbin[8], resbelow[8];
    unsigned n[8], nbn[8];
    int      qio[8];
    unsigned skey[8][128];
    int      sidx[8][128];
    int      nb[8][36];
    float    fd[8][36];
    int      msk[8][36];
};
union USmem { QSmem q; OSmem o; LSmem l; };

// ---------------- prep ----------------
__global__ void prep_kernel(const float* __restrict__ x1, const float* __restrict__ x2,
                            const float* __restrict__ x3, const float* __restrict__ x4,
                            const float* __restrict__ x5, const int* __restrict__ labels) {
    int id = blockIdx.x * blockDim.x + threadIdx.x;
    if (id < 6) g_ce_sum[id] = 0.0;
    if (id >= 8 && id < 13) { g_bl_sum[id - 8] = 0.0; g_bl_cnt[id - 8] = 0u; }
    if (id < BB * NN) g_hard[id] = labels[id];
    if (id < 21824) {
        const int offs[6] = {0, 16384, 20480, 21504, 21760, 21824};
        const float* xs[5] = {x1, x2, x3, x4, x5};
        int s = 0;
        while (id >= offs[s + 1]) ++s;
        int r = id - offs[s];
        const float* p = xs[s] + (size_t)r * 3;
        float x = p[0], y = p[1], z = p[2];
        g_pack[id] = make_float4(x, y, z, x * x + y * y + z * z);
    }
}

__device__ __forceinline__ unsigned part3(unsigned x) {
    x &= 1023u;
    x = (x | (x << 16)) & 0x030000FFu;
    x = (x | (x << 8))  & 0x0300F00Fu;
    x = (x | (x << 4))  & 0x030C30C3u;
    x = (x | (x << 2))  & 0x09249249u;
    return x;
}

// ---------------- Morton counting sort of stage-0 queries (one block per b) ----------------
__global__ __launch_bounds__(512) void msort_kernel() {
    __shared__ unsigned hist[4096];
    __shared__ unsigned short scode[8192];
    __shared__ int wsum[16];
    int b = blockIdx.x, tid = threadIdx.x, lane = tid & 31, wid = tid >> 5;
    for (int i = tid; i < 4096; i += 512) hist[i] = 0;
    __syncthreads();
#pragma unroll
    for (int j = 0; j < 16; ++j) {
        int id = tid + j * 512;
        float4 p = g_pack[b * NN + id];
        int cx = min(max((int)((p.x + 4.f) * 2.f), 0), 15);
        int cy = min(max((int)((p.y + 4.f) * 2.f), 0), 15);
        int cz = min(max((int)((p.z + 4.f) * 2.f), 0), 15);
        unsigned code = part3((unsigned)cx) | (part3((unsigned)cy) << 1) | (part3((unsigned)cz) << 2);
        scode[id] = (unsigned short)code;
        atomicAdd(&hist[code], 1u);
    }
    __syncthreads();
    // exclusive scan over 4096 bins (8 per thread)
    int base = tid * 8, local = 0;
    int pre[8];
#pragma unroll
    for (int r = 0; r < 8; ++r) { pre[r] = local; local += (int)hist[base + r]; }
    int incl = local;
#pragma unroll
    for (int o = 1; o < 32; o <<= 1) {
        int t = __shfl_up_sync(0xFFFFFFFFu, incl, o);
        if (lane >= o) incl += t;
    }
    if (lane == 31) wsum[wid] = incl;
    __syncthreads();
    int woff = 0;
#pragma unroll
    for (int w = 0; w < 16; ++w) woff += (w < wid) ? wsum[w] : 0;
    int excl = woff + incl - local;
    __syncthreads();
#pragma unroll
    for (int r = 0; r < 8; ++r) hist[base + r] = (unsigned)(excl + pre[r]);
    __syncthreads();
#pragma unroll
    for (int j = 0; j < 16; ++j) {
        int id = tid + j * 512;
        unsigned code = scode[id];
        unsigned slot = atomicAdd(&hist[code], 1u);
        g_packQ[b * NN + slot] = g_pack[b * NN + id];
        g_qperm[b * NN + slot] = id;
    }
}

// pinned arithmetic: identical across passes
__device__ __forceinline__ float dist2(float4 q, float4 p) {
    float s = q.z * p.z;
    s = __fmaf_rn(q.y, p.y, s);
    s = __fmaf_rn(q.x, p.x, s);
    return __fmaf_rn(-2.f, s, q.w + p.w);
}

// ---------------- loss0: center-ball pruned body (8 sorted queries) ----------------
__device__ __forceinline__ void loss0n_body(LSmem& sm, int b, int blk,
                                            const float* __restrict__ feat) {
    int tid = threadIdx.x, lane = tid & 31, wid = tid >> 5;
    float4 qc[8];
    if (tid < 8) sm.qio[tid] = g_qperm[b * NN + blk * 8 + tid];
#pragma unroll
    for (int q = 0; q < 8; ++q) qc[q] = g_packQ[b * NN + blk * 8 + q];
    float cx = 0.f, cy = 0.f, cz = 0.f;
#pragma unroll
    for (int q = 0; q < 8; ++q) { cx += qc[q].x; cy += qc[q].y; cz += qc[q].z; }
    cx *= 0.125f; cy *= 0.125f; cz *= 0.125f;
    float4 cen = make_float4(cx, cy, cz, cx * cx + cy * cy + cz * cz);
    float R2 = 0.f;
#pragma unroll
    for (int q = 0; q < 8; ++q) R2 = fmaxf(R2, fmaxf(dist2(cen, qc[q]), 0.f));
    float R = sqrtf(R2);

    sm.chist[tid] = 0;
    if (tid == 0) sm.ln = 0;
    if (tid < 8) { sm.n[tid] = 0; sm.nbn[tid] = 0; }
    __syncthreads();
    const float4* cand = g_pack + b * NN;

    // phase 1: ONE center distance + ONE atomic per candidate
#pragma unroll
    for (int i = 0; i < 16; ++i) {
        int c = tid + i * 512;
        float4 p = cand[c];
        unsigned key = __float_as_uint(fmaxf(dist2(cen, p), 0.f));
        atomicAdd(&sm.chist[(key >> 22) & 511u], 1u);
        int cb = (int)(key >> 20) - 960;
        sm.u8.cbin[c] = (unsigned char)min(max(cb, 0), 255);
    }
    __syncthreads();

    // scan center hist for rank 44 = 36 (k incl self) + 8 (block queries in candidate set)
    {
        int cnt = (int)sm.chist[tid];
        int incl = cnt;
#pragma unroll
        for (int o = 1; o < 32; o <<= 1) {
            int t = __shfl_up_sync(0xFFFFFFFFu, incl, o);
            if (lane >= o) incl += t;
        }
        if (lane == 31) sm.wsum[wid] = incl;
        __syncthreads();
        int woff = 0;
#pragma unroll
        for (int w = 0; w < 16; ++w) woff += (w < wid) ? sm.wsum[w] : 0;
        int excl = woff + incl - cnt;
        if (excl < 44 && 44 <= excl + cnt) sm.resbin[0] = tid;
        __syncthreads();
    }
    float t = __uint_as_float(((unsigned)sm.resbin[0] + 1u) << 22);  // bin upper edge
    float rr = sqrtf(t) + R + R;
    float cutd2 = rr * rr;
    int cut8 = min((int)(__float_as_uint(cutd2) >> 20) - 960 + 1, 255);

    // compact survivors
#pragma unroll
    for (int i = 0; i < 16; ++i) {
        int c = tid + i * 512;
        if ((int)sm.u8.cbin[c] <= cut8) {
            unsigned p = atomicAdd(&sm.ln, 1u);
            if (p < 6144) sm.list[p] = (unsigned short)c;
        }
    }
    __syncthreads();
    int Ln = (int)min(sm.ln, 6144u);
    bool ovf = sm.ln > 6144u;
    // zero qhist (aliases cbin; safe post-compaction)
    ((uint4*)sm.u8.qhist)[tid] = make_uint4(0, 0, 0, 0);
    __syncthreads();

    // phase 2: per-query octave histograms over survivors (self included; k'=36)
    if (!ovf) {
        for (int j = tid; j < Ln; j += 512) {
            int c = (int)sm.list[j];
            float4 p = cand[c];
#pragma unroll
            for (int q = 0; q < 8; ++q) {
                unsigned key = __float_as_uint(fmaxf(dist2(qc[q], p), 0.f));
                atomicAdd(&sm.u8.qhist[(q << 8) + ((key >> 23) & 255u)], 1u);
            }
        }
    } else {
#pragma unroll
        for (int i = 0; i < 16; ++i) {
            int c = tid + i * 512;
            float4 p = cand[c];
            unsigned ck = __float_as_uint(fmaxf(dist2(cen, p), 0.f));
            if ((int)(ck >> 20) - 960 > cut8) continue;
#pragma unroll
            for (int q = 0; q < 8; ++q) {
                unsigned key = __float_as_uint(fmaxf(dist2(qc[q], p), 0.f));
                atomicAdd(&sm.u8.qhist[(q << 8) + ((key >> 23) & 255u)], 1u);
            }
        }
    }
    __syncthreads();

    // scan per-query hist for rank 36 (256 bins; 8 groups x 64 threads)
    {
        int g = tid >> 6, t2 = tid & 63, wig = (tid >> 5) & 1;
        int base = (g << 8) + t2 * 4, local = 0;
#pragma unroll
        for (int r = 0; r < 4; ++r) local += (int)sm.u8.qhist[base + r];
        int incl = local;
#pragma unroll
        for (int o = 1; o < 32; o <<= 1) {
            int tt = __shfl_up_sync(0xFFFFFFFFu, incl, o);
            if (lane >= o) incl += tt;
        }
        if (lane == 31) sm.wsum[g * 2 + wig] = incl;
        __syncthreads();
        int woff = wig ? sm.wsum[g * 2] : 0;
        int excl = woff + incl - local;
        if (excl < 36 && 36 <= excl + local) {
            int c2 = excl, bin = t2 * 4;
#pragma unroll
            for (int r = 0; r < 4; ++r) {
                int hh = (int)sm.u8.qhist[base + r];
                if (c2 + hh >= 36) { bin = t2 * 4 + r; break; }
                c2 += hh;
            }
            sm.resbin[g] = bin; sm.resbelow[g] = c2;
        }
        __syncthreads();
    }
    unsigned rb[8];
#pragma unroll
    for (int q = 0; q < 8; ++q) rb[q] = (unsigned)sm.resbin[q];

    // phase 3: classify survivors (drop self only at insert points)
    if (!ovf) {
        for (int j = tid; j < Ln; j += 512) {
            int c = (int)sm.list[j];
            float4 p = cand[c];
#pragma unroll
            for (int q = 0; q < 8; ++q) {
                unsigned key = __float_as_uint(fmaxf(dist2(qc[q], p), 0.f));
                unsigned bin = (key >> 23) & 255u;
                if (bin < rb[q]) {
                    if (c != sm.qio[q]) {
                        unsigned pp = atomicAdd(&sm.nbn[q], 1u);
                        if (pp < 35) sm.nb[q][pp] = c;
                    }
                } else if (bin == rb[q]) {
                    unsigned pp = atomicAdd(&sm.n[q], 1u);
                    if (pp < 128) { sm.skey[q][pp] = key; sm.sidx[q][pp] = c; }
                }
            }
        }
    } else {
#pragma unroll
        for (int i = 0; i < 16; ++i) {
            int c = tid + i * 512;
            float4 p = cand[c];
            unsigned ck = __float_as_uint(fmaxf(dist2(cen, p), 0.f));
            if ((int)(ck >> 20) - 960 > cut8) continue;
#pragma unroll
            for (int q = 0; q < 8; ++q) {
                unsigned key = __float_as_uint(fmaxf(dist2(qc[q], p), 0.f));
                unsigned bin = (key >> 23) & 255u;
                if (bin < rb[q]) {
                    if (c != sm.qio[q]) {
                        unsigned pp = atomicAdd(&sm.nbn[q], 1u);
                        if (pp < 35) sm.nb[q][pp] = c;
                    }
                } else if (bin == rb[q]) {
                    unsigned pp = atomicAdd(&sm.n[q], 1u);
                    if (pp < 128) { sm.skey[q][pp] = key; sm.sidx[q][pp] = c; }
                }
            }
        }
    }
    __syncthreads();

    // exact-rank the rank-bin survivors ((key,idx) lexicographic == top_k tie-break)
    {
        int g = tid >> 6, t2 = tid & 63;
        int n = (int)min(sm.n[g], 128u);
        int need = 36 - sm.resbelow[g];
        for (int j = t2; j < n; j += 64) {
            unsigned kj = sm.skey[g][j]; int ij = sm.sidx[g][j], r = 0;
            for (int m = 0; m < n; ++m) {
                unsigned km = sm.skey[g][m];
                r += (km < kj) || (km == kj && sm.sidx[g][m] < ij);
            }
            if (r < need && ij != sm.qio[g]) {
                unsigned pp = atomicAdd(&sm.nbn[g], 1u);
                if (pp < 35) sm.nb[g][pp] = ij;
            }
        }
    }
    __syncthreads();

    // feature distances (D=64): 2 warps per query
    {
        int g = wid >> 1, w2 = wid & 1;
        int qi = sm.qio[g];
        int myh = g_hard[b * NN + qi];
        const float4* fq = (const float4*)(feat + (size_t)(b * NN + qi) * 64);
        for (int j = w2; j < 35; j += 2) {
            int nbi = sm.nb[g][j];
            const float4* fn = (const float4*)(feat + (size_t)(b * NN + nbi) * 64);
            float ss = 0.f;
            if (lane < 16) {
                float4 a = fq[lane], z = fn[lane];
                float dx = a.x - z.x, dy = a.y - z.y, dz = a.z - z.z, dw = a.w - z.w;
                ss = dx * dx + dy * dy + dz * dz + dw * dw;
            }
#pragma unroll
            for (int o = 16; o; o >>= 1) ss += __shfl_down_sync(0xFFFFFFFFu, ss, o);
            if (lane == 0) {
                sm.fd[g][j] = sqrtf(ss + 1e-6f);
                sm.msk[g][j] = (g_hard[b * NN + nbi] == myh) ? 1 : 0;
            }
        }
    }
    __syncthreads();
    if ((tid & 63) == 0) {
        int g = tid >> 6;
        float dmin = 3.0e38f; int cnt = 0;
        for (int j = 0; j < 35; ++j) { dmin = fminf(dmin, sm.fd[g][j]); cnt += sm.msk[g][j]; }
        if (cnt > 0 && cnt < 35) {
            float pos = 0.f, neg = 0.f;
            for (int j = 0; j < 35; ++j) {
                float e = expf(dmin - sm.fd[g][j]);  // TEMPERATURE = 1
                neg += e;
                if (sm.msk[g][j]) pos += e;
            }
            atomicAdd(&g_bl_sum[0], (double)(-logf(pos / neg + 1e-6f)));
            atomicAdd(&g_bl_cnt[0], 1u);
        }
    }
}

// ---------------- quad body: 4 queries, 1024 bins (k=256 hard path) ----------------
template <int CPT>
__device__ __forceinline__ void quad_body(
        QSmem& sm, int b, int quad, int qoff, int Nq, int coff, int Ncand,
        int k, const int* __restrict__ labels) {
    int tid = threadIdx.x, lane = tid & 31;
    int qbase = quad * 4;
    float4 qc[4];
#pragma unroll
    for (int q = 0; q < 4; ++q) qc[q] = g_pack[qoff + b * Nq + qbase + q];
    const float4* cand = g_pack + coff + b * Ncand;

    uint4* h4 = (uint4*)sm.hist;
    uint4 z4 = make_uint4(0, 0, 0, 0);
    h4[tid] = z4; h4[tid + 512] = z4;
    if (tid < 4) sm.n[tid] = 0;
    if (tid >= 32 && tid < 96) sm.cls[(tid - 32) >> 4][(tid - 32) & 15] = 0;
    __syncthreads();
#pragma unroll
    for (int i = 0; i < CPT; ++i) {
        int c = tid + i * 512;
        float4 p = cand[c];
#pragma unroll
        for (int q = 0; q < 4; ++q) {
            unsigned bin = __float_as_uint(fmaxf(dist2(qc[q], p), 0.f)) >> 21;
            atomicAdd(&sm.hist[(q << 10) + bin], 1u);
        }
    }
    __syncthreads();
    {
        int g = tid >> 7, t = tid & 127, wig = (tid >> 5) & 3;
        const unsigned* h = sm.hist + (g << 10);
        int base = t * 8, local = 0;
#pragma unroll
        for (int r = 0; r < 8; ++r) local += (int)h[base + r];
        int incl = local;
#pragma unroll
        for (int o = 1; o < 32; o <<= 1) {
            int tt = __shfl_up_sync(0xFFFFFFFFu, incl, o);
            if (lane >= o) incl += tt;
        }
        if (lane == 31) sm.wsum[g][wig] = incl;
        __syncthreads();
        int woff = 0;
#pragma unroll
        for (int w = 0; w < 4; ++w) woff += (w < wig) ? sm.wsum[g][w] : 0;
        int excl = woff + incl - local;
        if (excl < k && k <= excl + local) {
            int c2 = excl, bin = base;
#pragma unroll
            for (int r = 0; r < 8; ++r) {
                int hh = (int)h[base + r];
                if (c2 + hh >= k) { bin = base + r; break; }
                c2 += hh;
            }
            sm.resbin[g] = bin; sm.resbelow[g] = c2;
        }
        __syncthreads();
    }
    unsigned rb[4];
#pragma unroll
    for (int q = 0; q < 4; ++q) rb[q] = (unsigned)sm.resbin[q];
#pragma unroll
    for (int i = 0; i < CPT; ++i) {
        int c = tid + i * 512;
        float4 p = cand[c];
#pragma unroll
        for (int q = 0; q < 4; ++q) {
            unsigned key = __float_as_uint(fmaxf(dist2(qc[q], p), 0.f));
            unsigned bin = key >> 21;
            if (bin < rb[q]) {
                atomicAdd(&sm.cls[q][labels[b * NN + c]], 1u);
            } else if (bin == rb[q]) {
                unsigned pp = atomicAdd(&sm.n[q], 1u);
                if (pp < 256) { sm.skey[q][pp] = key; sm.sidx[q][pp] = c; }
            }
        }
    }
    __syncthreads();
    {
        int g = tid >> 7, t = tid & 127;
        int n = (int)min(sm.n[g], 256u);
        int need = k - sm.resbelow[g];
        for (int j = t; j < n; j += 128) {
            unsigned kj = sm.skey[g][j]; int ij = sm.sidx[g][j], r = 0;
            for (int m = 0; m < n; ++m) {
                unsigned km = sm.skey[g][m];
                r += (km < kj) || (km == kj && sm.sidx[g][m] < ij);
            }
            if (r < need) atomicAdd(&sm.cls[g][labels[b * NN + ij]], 1u);
        }
    }
    __syncthreads();
    if ((tid & 127) == 0) {
        int g = tid >> 7;
        int best = 0; unsigned bc = sm.cls[g][0];
#pragma unroll
        for (int cc = 1; cc < 13; ++cc)
            if (sm.cls[g][cc] > bc) { bc = sm.cls[g][cc]; best = cc; }
        g_hard[qoff + b * Nq + qbase + g] = best;
    }
}

// ---------------- octo body: 8 queries, 512 bins, min-bin sieve (R12 path) ----------------
template <int CPT, bool IS_LOSS>
__device__ __forceinline__ void octo_body(
        OSmem& sm, int b, int oct, int qoff, int Nq, int coff, int Ncand,
        int k, int stage, const float* __restrict__ feat, int D,
        const int* __restrict__ labels, bool selfex) {
    int tid = threadIdx.x, lane = tid & 31, wid = tid >> 5;
    int qbase = oct * 8;
    float4 qc[8];
#pragma unroll
    for (int q = 0; q < 8; ++q) qc[q] = g_pack[qoff + b * Nq + qbase + q];
    const float4* cand = g_pack + coff + b * Ncand;

    uint4* h4 = (uint4*)sm.hist;
    uint4 z4 = make_uint4(0, 0, 0, 0);
    h4[tid] = z4; h4[tid + 512] = z4;
    if (tid < 8) { sm.n[tid] = 0; sm.nbn[tid] = 0; }
    if (tid == 16) sm.ln = 0;
    if (tid >= 32 && tid < 160) sm.cls[(tid - 32) >> 4][(tid - 32) & 15] = 0;
    __syncthreads();
#pragma unroll
    for (int i = 0; i < CPT; ++i) {
        int c = tid + i * 512;
        float4 p = cand[c];
        unsigned mb = 511u;
#pragma unroll
        for (int q = 0; q < 8; ++q) {
            if (selfex && c == qbase + q) continue;
            unsigned bin = __float_as_uint(fmaxf(dist2(qc[q], p), 0.f)) >> 22;
            atomicAdd(&sm.hist[(q << 9) + bin], 1u);
            mb = min(mb, bin);
        }
        sm.cbin[c] = (unsigned char)(mb >> 1);
    }
    __syncthreads();
    {
        int g = tid >> 6, t = tid & 63, wig = (tid >> 5) & 1;
        const unsigned* h = sm.hist + (g << 9);
        int base = t * 8, local = 0;
#pragma unroll
        for (int r = 0; r < 8; ++r) local += (int)h[base + r];
        int incl = local;
#pragma unroll
        for (int o = 1; o < 32; o <<= 1) {
            int tt = __shfl_up_sync(0xFFFFFFFFu, incl, o);
            if (lane >= o) incl += tt;
        }
        if (lane == 31) sm.wsum[g][wig] = incl;
        __syncthreads();
        int woff = wig ? sm.wsum[g][0] : 0;
        int excl = woff + incl - local;
        if (excl < k && k <= excl + local) {
            int c2 = excl, bin = base;
#pragma unroll
            for (int r = 0; r < 8; ++r) {
                int hh = (int)h[base + r];
                if (c2 + hh >= k) { bin = base + r; break; }
                c2 += hh;
            }
            sm.resbin[g] = bin; sm.resbelow[g] = c2;
        }
        __syncthreads();
    }
    unsigned rb[8];
    unsigned rbmax = 0;
#pragma unroll
    for (int q = 0; q < 8; ++q) { rb[q] = (unsigned)sm.resbin[q]; rbmax = max(rbmax, rb[q]); }
    {
        unsigned char rbc = (unsigned char)(rbmax >> 1);
#pragma unroll
        for (int i = 0; i < CPT; ++i) {
            int c = tid + i * 512;
            if (sm.cbin[c] <= rbc) {
                unsigned p = atomicAdd(&sm.ln, 1u);
                if (p < 3072) sm.list[p] = (unsigned short)c;
            }
        }
    }
    __syncthreads();
    int Ln = (int)sm.ln;
    if (Ln <= 3072) {
        for (int j = tid; j < Ln; j += 512) {
            int c = (int)sm.list[j];
            float4 p = cand[c];
#pragma unroll
            for (int q = 0; q < 8; ++q) {
                if (selfex && c == qbase + q) continue;
                unsigned key = __float_as_uint(fmaxf(dist2(qc[q], p), 0.f));
                unsigned bin = key >> 22;
                if (bin < rb[q]) {
                    if (IS_LOSS) { unsigned pp = atomicAdd(&sm.nbn[q], 1u); sm.nb[q][pp] = c; }
                    else atomicAdd(&sm.cls[q][labels[b * NN + c]], 1u);
                } else if (bin == rb[q]) {
                    unsigned pp = atomicAdd(&sm.n[q], 1u);
                    if (pp < 128) { sm.skey[q][pp] = key; sm.sidx[q][pp] = c; }
                }
            }
        }
    } else {
        unsigned char rbc = (unsigned char)(rbmax >> 1);
#pragma unroll
        for (int i = 0; i < CPT; ++i) {
            int c = tid + i * 512;
            if (sm.cbin[c] > rbc) continue;
            float4 p = cand[c];
#pragma unroll
            for (int q = 0; q < 8; ++q) {
                if (selfex && c == qbase + q) continue;
                unsigned key = __float_as_uint(fmaxf(dist2(qc[q], p), 0.f));
                unsigned bin = key >> 22;
                if (bin < rb[q]) {
                    if (IS_LOSS) { unsigned pp = atomicAdd(&sm.nbn[q], 1u); sm.nb[q][pp] = c; }
                    else atomicAdd(&sm.cls[q][labels[b * NN + c]], 1u);
                } else if (bin == rb[q]) {
                    unsigned pp = atomicAdd(&sm.n[q], 1u);
                    if (pp < 128) { sm.skey[q][pp] = key; sm.sidx[q][pp] = c; }
                }
            }
        }
    }
    __syncthreads();
    {
        int g = tid >> 6, t = tid & 63;
        int n = (int)min(sm.n[g], 128u);
        int need = k - sm.resbelow[g];
        for (int j = t; j < n; j += 64) {
            unsigned kj = sm.skey[g][j]; int ij = sm.sidx[g][j], r = 0;
            for (int m = 0; m < n; ++m) {
                unsigned km = sm.skey[g][m];
                r += (km < kj) || (km == kj && sm.sidx[g][m] < ij);
            }
            if (r < need) {
                if (IS_LOSS) { unsigned pp = atomicAdd(&sm.nbn[g], 1u); sm.nb[g][pp] = ij; }
                else atomicAdd(&sm.cls[g][labels[b * NN + ij]], 1u);
            }
        }
    }
    __syncthreads();
    if (!IS_LOSS) {
        if ((tid & 63) == 0) {
            int g = tid >> 6;
            int best = 0; unsigned bc = sm.cls[g][0];
#pragma unroll
            for (int cc = 1; cc < 13; ++cc)
                if (sm.cls[g][cc] > bc) { bc = sm.cls[g][cc]; best = cc; }
            g_hard[qoff + b * Nq + qbase + g] = best;
        }
        return;
    }
    {
        int g = wid >> 1, w2 = wid & 1;
        int qi = qbase + g;
        int hb = qoff + b * Nq;
        int myh = g_hard[hb + qi];
        const float4* fq = (const float4*)(feat + (size_t)(b * Nq + qi) * D);
        int D4 = D >> 2;
        for (int j = w2; j < k; j += 2) {
            int nbi = sm.nb[g][j];
            const float4* fn = (const float4*)(feat + (size_t)(b * Nq + nbi) * D);
            float ss = 0.f;
            for (int d = lane; d < D4; d += 32) {
                float4 a = fq[d], z = fn[d];
                float dx = a.x - z.x, dy = a.y - z.y, dz = a.z - z.z, dw = a.w - z.w;
                ss += dx * dx + dy * dy + dz * dz + dw * dw;
            }
#pragma unroll
            for (int o = 16; o; o >>= 1) ss += __shfl_down_sync(0xFFFFFFFFu, ss, o);
            if (lane == 0) {
                sm.fd[g][j] = sqrtf(ss + 1e-6f);
                sm.msk[g][j] = (g_hard[hb + nbi] == myh) ? 1 : 0;
            }
        }
    }
    __syncthreads();
    if ((tid & 63) == 0) {
        int g = tid >> 6;
        float dmin = 3.0e38f; int cnt = 0;
        for (int j = 0; j < k; ++j) { dmin = fminf(dmin, sm.fd[g][j]); cnt += sm.msk[g][j]; }
        if (cnt > 0 && cnt < k) {
            float pos = 0.f, neg = 0.f;
            for (int j = 0; j < k; ++j) {
                float e = expf(dmin - sm.fd[g][j]);  // TEMPERATURE = 1
                neg += e;
                if (sm.msk[g][j]) pos += e;
            }
            atomicAdd(&g_bl_sum[stage], (double)(-logf(pos / neg + 1e-6f)));
            atomicAdd(&g_bl_cnt[stage], 1u);
        }
    }
}

// ---------------- kernel A: loss0 (pruned) + hard labels + CE ----------------
__global__ __launch_bounds__(512, 2) void kernelA(
        const float* __restrict__ f1, const int* __restrict__ labels,
        const float* __restrict__ lg0, const float* __restrict__ lg1,
        const float* __restrict__ lg2, const float* __restrict__ lg3,
        const float* __restrict__ lg4, const float* __restrict__ lg5,
        const int* __restrict__ i2, const int* __restrict__ i3,
        const int* __restrict__ i4, const int* __restrict__ i5) {
    __shared__ USmem u;
    int bx = blockIdx.x, b = blockIdx.y;
    if (bx < 1024) {
        loss0n_body(u.l, b, bx, f1);
    } else if (bx < 1280) {
        octo_body<16, false>(u.o, b, bx - 1024, 16384, 2048, 0, 8192, 4, 0, nullptr, 0, labels, false);
    } else if (bx < 1344) {
        octo_body<16, false>(u.o, b, bx - 1280, 20480, 512, 0, 8192, 16, 0, nullptr, 0, labels, false);
    } else if (bx < 1360) {
        octo_body<16, false>(u.o, b, bx - 1344, 21504, 128, 0, 8192, 64, 0, nullptr, 0, labels, false);
    } else if (bx < 1368) {
        quad_body<16>(u.q, b, bx - 1360, 21760, 32, 0, 8192, 256, labels);
    } else {
        const int cum[7] = {0, 16384, 32768, 36864, 37888, 38144, 38208};
        int chunk = bx - 1368;
        int r = (chunk * 2 + b) * 512 + threadIdx.x;
        int job = 0;
        float l = 0.f;
        if (r < 38208) {
#pragma unroll
            for (int j = 1; j < 6; ++j) if (r >= cum[j]) job = j;
            const float* L[6] = {lg0, lg1, lg2, lg3, lg4, lg5};
            const int*   G[6] = {nullptr, nullptr, i2, i3, i4, i5};
            const int   lgn[6] = {13, 13, 11, 9, 7, 5};
            int lr = r - cum[job];
            int bb = lr >> lgn[job];
            const int* g = G[job];
            int lab = g ? labels[bb * NN + g[lr]] : labels[lr];
            const float* row = L[job] + (size_t)lr * 13;
            float v[13];
#pragma unroll
            for (int c = 0; c < 13; ++c) v[c] = row[c];
            float m = v[0];
#pragma unroll
            for (int c = 1; c < 13; ++c) m = fmaxf(m, v[c]);
            float s = 0.f;
#pragma unroll
            for (int c = 0; c < 13; ++c) s += expf(v[c] - m);
            l = (m + logf(s)) - v[lab];
        }
#pragma unroll
        for (int o = 16; o; o >>= 1) l += __shfl_down_sync(0xFFFFFFFFu, l, o);
        if ((threadIdx.x & 31) == 0 && l != 0.f) atomicAdd(&g_ce_sum[job], (double)l);
    }
}

// ---------------- kernel B: losses stages 1..4 (need g_hard) ----------------
__global__ __launch_bounds__(512, 2) void kernelB(
        const float* __restrict__ f2, const float* __restrict__ f3,
        const float* __restrict__ f4, const float* __restrict__ f5) {
    __shared__ USmem u;
    int bx = blockIdx.x, b = blockIdx.y;
    if (bx < 256) {
        octo_body<4, true>(u.o, b, bx, 16384, 2048, 16384, 2048, 23, 1, f2, 128, nullptr, true);
    } else if (bx < 320) {
        octo_body<1, true>(u.o, b, bx - 256, 20480, 512, 20480, 512, 23, 2, f3, 256, nullptr, true);
    } else {
        unsigned* s_key = u.o.hist;
        int*      s_nb  = u.o.nb[0];
        float*    s_fd  = u.o.fd[0];
        int*      s_msk = u.o.msk[0];
        int bi = bx - 320;
        int tid = threadIdx.x, lane = tid & 31, wid = tid >> 5;
        int stage, Ni, off, qi; const float* feat;
        if (bi < 128) { stage = 3; Ni = 128; off = 21504; feat = f4; qi = bi; }
        else          { stage = 4; Ni = 32;  off = 21760; feat = f5; qi = bi - 128; }
        const int D = 512, D4 = 128;
        float4 qc = g_pack[off + b * Ni + qi];
        unsigned myk = 0xFFFFFFFFu;
        if (tid < Ni && tid != qi) {
            float4 p = g_pack[off + b * Ni + tid];
            myk = __float_as_uint(fmaxf(dist2(qc, p), 0.f));
        }
        s_key[tid] = myk;
        __syncthreads();
        if (myk != 0xFFFFFFFFu) {
            int r = 0;
            for (int j = 0; j < Ni; ++j) {
                unsigned kj = s_key[j];
                r += (kj < myk) || (kj == myk && j < tid);
            }
            if (r < 23) s_nb[r] = tid;
        }
        __syncthreads();
        int myh = g_hard[off + b * Ni + qi];
        const float4* fq = (const float4*)(feat + (size_t)(b * Ni + qi) * D);
        for (int j = wid; j < 23; j += 16) {
            int nbi = s_nb[j];
            const float4* fn = (const float4*)(feat + (size_t)(b * Ni + nbi) * D);
            float ss = 0.f;
            for (int d = lane; d < D4; d += 32) {
                float4 a = fq[d], z = fn[d];
                float dx = a.x - z.x, dy = a.y - z.y, dz = a.z - z.z, dw = a.w - z.w;
                ss += dx * dx + dy * dy + dz * dz + dw * dw;
            }
#pragma unroll
            for (int o = 16; o; o >>= 1) ss += __shfl_down_sync(0xFFFFFFFFu, ss, o);
            if (lane == 0) {
                s_fd[j] = sqrtf(ss + 1e-6f);
                s_msk[j] = (g_hard[off + b * Ni + nbi] == myh) ? 1 : 0;
            }
        }
        __syncthreads();
        if (tid == 0) {
            float dmin = 3.0e38f; int cnt = 0;
            for (int j = 0; j < 23; ++j) { dmin = fminf(dmin, s_fd[j]); cnt += s_msk[j]; }
            if (cnt > 0 && cnt < 23) {
                float pos = 0.f, neg = 0.f;
                for (int j = 0; j < 23; ++j) {
                    float e = expf(dmin - s_fd[j]);
                    neg += e;
                    if (s_msk[j]) pos += e;
                }
                atomicAdd(&g_bl_sum[stage], (double)(-logf(pos / neg + 1e-6f)));
                atomicAdd(&g_bl_cnt[stage], 1u);
            }
        }
    }
}

// ---------------- finalize ----------------
__global__ void finalize_kernel(float* out) {
    const int ns[5] = {8192, 2048, 512, 128, 32};
    double ce = g_ce_sum[0] / (double)(BB * NN);
    double o = 0.0;
    for (int j = 0; j < 5; ++j) o += g_ce_sum[1 + j] / (double)(BB * ns[j]);
    double bl = 0.0;
    for (int i = 0; i < 5; ++i) {
        double dn = g_bl_cnt[i] > 0 ? (double)g_bl_cnt[i] : 1.0;
        bl += g_bl_sum[i] / dn;
    }
    out[0] = (float)(ce + 0.1 * bl + 0.1 * o);
}

// ---------------- launch ----------------
extern "C" void kernel_launch(void* const* d_in, const int* in_sizes, int n_in,
                              void* d_out, int out_size) {
    (void)in_sizes; (void)n_in; (void)out_size;
    // 0:labels, 1..4:index2..5, 5:output, per stage j: 6+3j:pred, 7+3j:xyz, 8+3j:feat
    const int* labels = (const int*)d_in[0];
    const int* idx2 = (const int*)d_in[1];
    const int* idx3 = (const int*)d_in[2];
    const int* idx4 = (const int*)d_in[3];
    const int* idx5 = (const int*)d_in[4];
    const float* output = (const float*)d_in[5];
    const float* pred[5], *xyz[5], *feat[5];
    for (int j = 0; j < 5; ++j) {
        pred[j] = (const float*)d_in[6 + 3 * j];
        xyz[j]  = (const float*)d_in[7 + 3 * j];
        feat[j] = (const float*)d_in[8 + 3 * j];
    }

    prep_kernel<<<86, 256>>>(xyz[0], xyz[1], xyz[2], xyz[3], xyz[4], labels);
    msort_kernel<<<BB, 512>>>();
    kernelA<<<dim3(1406, BB), 512>>>(feat[0], labels,
                                     output, pred[0], pred[1], pred[2], pred[3], pred[4],
                                     idx2, idx3, idx4, idx5);
    kernelB<<<dim3(480, BB), 512>>>(feat[1], feat[2], feat[3], feat[4]);

    finalize_kernel<<<1, 1>>>((float*)d_out);
}